// round 5
// baseline (speedup 1.0000x reference)
#include <cuda_runtime.h>
#include <math.h>

#define Bt 8
#define Nn 1024
#define Hh 64
#define Tt 128
#define C1 66              // channels in xh = 2 + H
#define KC 330             // 5 * C1
#define M_DIFF (Bt*C1)     // 528
#define BS (Bt*C1*Nn)      // one zc block: 540672 floats
#define PRED_SZ (Bt*Nn*Tt) // 1048576

#define BKk 32
#define PAD 68

// ---------------- device globals (scratch; allocation-free) ----------------
__device__ float g_Sf  [Nn*Nn];
__device__ float g_Sb  [Nn*Nn];
__device__ float g_SfT [Nn*Nn];   // sup_f^T  : [v][w]
__device__ float g_SbT [Nn*Nn];   // sup_b^T
__device__ float g_Sf2T[Nn*Nn];   // (sup_f^2)^T
__device__ float g_Sb2T[Nn*Nn];   // (sup_b^2)^T
__device__ float g_zc  [5*BS];    // [k][b][c][n]; k=0 is z, k=1..4 diffused
__device__ float g_zc2 [BS];      // c-path input [b][c][n] = [x_in, mask, r*h]
__device__ float g_h   [Bt*Hh*Nn];
__device__ float g_u   [Bt*Hh*Nn];
__device__ int   g_masktype;      // 0 = 1-byte elements, 1 = 4-byte elements

// ---------------- mask dtype sniffer ----------------
// int32 / float32 masks only yield words in {0, 1, 0x3F800000}.
// Packed uint8/bool yields words with all bytes <=1 but value >1 (e.g. 0x00010100).
__global__ void detect_mask_kernel(const unsigned int* __restrict__ m) {
    if (threadIdx.x != 0 || blockIdx.x != 0) return;
    int byte_like = 0;
    for (int i = 0; i < 1024; i++) {
        unsigned int w = m[i];
        if (w == 0u || w == 1u || w == 0x3F800000u) continue;
        unsigned int b0 = w & 255u, b1 = (w >> 8) & 255u,
                     b2 = (w >> 16) & 255u, b3 = w >> 24;
        if (b0 <= 1u && b1 <= 1u && b2 <= 1u && b3 <= 1u) { byte_like = 1; break; }
    }
    g_masktype = byte_like ? 0 : 1;
}

// ---------------- support normalization ----------------
// sup_f[w][v] = adj[w][v]/(rowsum_w+1e-8);  sup_b[w][v] = adj[v][w]/(colsum_w+1e-8)
__global__ void norm_kernel(const float* __restrict__ adj) {
    int w = blockIdx.x;
    int tid = threadIdx.x;
    __shared__ float sred[256];
    float rs = 0.f, cs = 0.f;
    for (int v = tid; v < Nn; v += 256) {
        rs += adj[w*Nn + v];
        cs += adj[v*Nn + w];
    }
    sred[tid] = rs; __syncthreads();
    for (int s = 128; s > 0; s >>= 1) { if (tid < s) sred[tid] += sred[tid+s]; __syncthreads(); }
    float rsum = sred[0] + 1e-8f; __syncthreads();
    sred[tid] = cs; __syncthreads();
    for (int s = 128; s > 0; s >>= 1) { if (tid < s) sred[tid] += sred[tid+s]; __syncthreads(); }
    float csum = sred[0] + 1e-8f; __syncthreads();
    for (int v = tid; v < Nn; v += 256) {
        g_Sf[w*Nn + v] = adj[w*Nn + v] / rsum;
        g_Sb[w*Nn + v] = adj[v*Nn + w] / csum;
    }
}

__global__ void transpose_kernel() {
    const float* src = blockIdx.z ? g_Sb : g_Sf;
    float*       dst = blockIdx.z ? g_SbT : g_SfT;
    __shared__ float tile[32][33];
    int x0 = blockIdx.x*32, y0 = blockIdx.y*32;
    int tx = threadIdx.x, ty = threadIdx.y;   // (32,8)
    #pragma unroll
    for (int j = 0; j < 32; j += 8) tile[ty+j][tx] = src[(size_t)(y0+ty+j)*Nn + x0 + tx];
    __syncthreads();
    #pragma unroll
    for (int j = 0; j < 32; j += 8) dst[(size_t)(x0+ty+j)*Nn + y0 + tx] = tile[tx][ty+j];
}

// ---------------- shared GEMM-NN tile body ----------------
// C[m][w] = sum_k A[m][k] * B[k][w];  A:[M][1024], B:[1024][1024], 64x64 tile, BK=32
__device__ __forceinline__ void gemm_nn_body(const float* __restrict__ A,
                                             const float* __restrict__ B,
                                             float* __restrict__ C, int M)
{
    __shared__ float As[BKk*PAD];
    __shared__ float Bs[BKk*PAD];
    int tid  = threadIdx.x;
    int row0 = blockIdx.y*64, col0 = blockIdx.x*64;
    int alr = tid >> 3, alc = (tid & 7) << 2;
    int blr = tid >> 4, blc = (tid & 15) << 2;
    int tx = tid & 15, ty = tid >> 4;
    float acc[4][4];
    #pragma unroll
    for (int i = 0; i < 4; i++)
        #pragma unroll
        for (int j = 0; j < 4; j++) acc[i][j] = 0.f;

    for (int k0 = 0; k0 < Nn; k0 += BKk) {
        #pragma unroll
        for (int p = 0; p < 2; p++) {
            int m = row0 + alr + p*32;
            float4 av = make_float4(0.f,0.f,0.f,0.f);
            if (m < M) av = *reinterpret_cast<const float4*>(A + (size_t)m*Nn + k0 + alc);
            As[(alc+0)*PAD + alr + p*32] = av.x;
            As[(alc+1)*PAD + alr + p*32] = av.y;
            As[(alc+2)*PAD + alr + p*32] = av.z;
            As[(alc+3)*PAD + alr + p*32] = av.w;
            int kk = k0 + blr + p*16;
            float4 bv = *reinterpret_cast<const float4*>(B + (size_t)kk*Nn + col0 + blc);
            *reinterpret_cast<float4*>(&Bs[(blr + p*16)*PAD + blc]) = bv;
        }
        __syncthreads();
        #pragma unroll
        for (int kk = 0; kk < BKk; kk++) {
            float4 a = *reinterpret_cast<const float4*>(&As[kk*PAD + (ty<<2)]);
            float4 b = *reinterpret_cast<const float4*>(&Bs[kk*PAD + (tx<<2)]);
            float av[4] = {a.x, a.y, a.z, a.w};
            float bv[4] = {b.x, b.y, b.z, b.w};
            #pragma unroll
            for (int i = 0; i < 4; i++)
                #pragma unroll
                for (int j = 0; j < 4; j++) acc[i][j] += av[i]*bv[j];
        }
        __syncthreads();
    }
    #pragma unroll
    for (int i = 0; i < 4; i++) {
        int m = row0 + (ty<<2) + i;
        if (m < M) {
            float4 o = make_float4(acc[i][0], acc[i][1], acc[i][2], acc[i][3]);
            *reinterpret_cast<float4*>(C + (size_t)m*Nn + col0 + (tx<<2)) = o;
        }
    }
}

// one-time: Sf2T = SfT @ SfT = (Sf^2)^T ; same for Sb
__global__ __launch_bounds__(256) void square_kernel() {
    const float* S = blockIdx.z ? g_SbT : g_SfT;
    float*       D = blockIdx.z ? g_Sb2T : g_Sf2T;
    gemm_nn_body(S, S, D, Nn);
}

// per-step diffusion: 4 independent GEMMs (Sf, Sf^2, Sb, Sb^2) from z (or zc2)
__global__ __launch_bounds__(256) void diff_kernel(int use2) {
    const float* A = use2 ? g_zc2 : g_zc;
    const float* B; float* C;
    switch (blockIdx.z) {
        case 0:  B = g_SfT;  C = g_zc + 1*(size_t)BS; break;
        case 1:  B = g_Sf2T; C = g_zc + 2*(size_t)BS; break;
        case 2:  B = g_SbT;  C = g_zc + 3*(size_t)BS; break;
        default: B = g_Sb2T; C = g_zc + 4*(size_t)BS; break;
    }
    gemm_nn_body(A, B, C, M_DIFF);
}

__global__ void zero_h_kernel() {
    int i = blockIdx.x*256 + threadIdx.x;
    if (i < Bt*Hh*Nn) g_h[i] = 0.f;
}

// ---------------- per-step: x_hat, outputs, build z ----------------
__global__ __launch_bounds__(128) void pre_kernel(
    const float* __restrict__ x, const void* __restrict__ mask,
    const float* __restrict__ Wout, const float* __restrict__ bout,
    float* __restrict__ out, int t)
{
    int n = blockIdx.x*128 + threadIdx.x;
    int b = blockIdx.y;
    __shared__ float ws[Hh];
    if (threadIdx.x < Hh) ws[threadIdx.x] = Wout[threadIdx.x];
    __syncthreads();
    float acc = 0.f;
    #pragma unroll 4
    for (int hh = 0; hh < Hh; hh++) {
        float hv = g_h[((size_t)(b*Hh + hh))*Nn + n];
        acc += hv * ws[hh];
        g_zc[((size_t)(b*C1 + 2 + hh))*Nn + n] = hv;                       // z channels 2..65
        out[PRED_SZ + (((size_t)(b*Hh + hh))*Nn + n)*Tt + t] = hv;         // states (pre-update h)
    }
    float xhat = acc + bout[0];
    out[((size_t)(b*Nn) + n)*Tt + t] = xhat;                               // predictions
    size_t xi = ((size_t)b*Nn + n)*Tt + t;
    float xv = x[xi];
    bool m;
    if (g_masktype == 0)
        m = ((const unsigned char*)mask)[xi] != 0;
    else
        m = ((const unsigned int*)mask)[xi] != 0u;   // correct for both int32 and float32
    float xin = m ? xv : xhat;
    g_zc[((size_t)(b*C1) + 0)*Nn + n] = xin;
    g_zc[((size_t)(b*C1) + 1)*Nn + n] = m ? 1.f : 0.f;
}

// ---------------- gates r,u: sigmoid(W . zc + b); fold r*h into zc2 ----------------
__global__ __launch_bounds__(256) void gates_kernel(
    const float* __restrict__ Wr, const float* __restrict__ br,
    const float* __restrict__ Wu, const float* __restrict__ bu)
{
    int b = blockIdx.y, gate = blockIdx.z;
    int col0 = blockIdx.x*64;
    const float* W    = gate ? Wu : Wr;
    const float* bias = gate ? bu : br;
    __shared__ float As[BKk*PAD];
    __shared__ float Bs[BKk*PAD];
    int tid = threadIdx.x;
    int alr = tid >> 3, alc = (tid & 7) << 2;
    int blr = tid >> 4, blc = (tid & 15) << 2;
    int tx = tid & 15, ty = tid >> 4;
    float acc[4][4];
    #pragma unroll
    for (int i = 0; i < 4; i++)
        #pragma unroll
        for (int j = 0; j < 4; j++) acc[i][j] = 0.f;

    for (int k0 = 0; k0 < KC; k0 += BKk) {
        #pragma unroll
        for (int p = 0; p < 2; p++) {
            int o = alr + p*32;
            #pragma unroll
            for (int i = 0; i < 4; i++) {
                int kf = k0 + alc + i;
                As[(alc+i)*PAD + o] = (kf < KC) ? W[o*KC + kf] : 0.f;
            }
            int kf = k0 + blr + p*16;
            float4 bv = make_float4(0.f,0.f,0.f,0.f);
            if (kf < KC) {
                int kb = kf / C1, c = kf - kb*C1;
                const float* src = g_zc + ((size_t)((kb*Bt + b)*C1 + c))*Nn;
                bv = *reinterpret_cast<const float4*>(src + col0 + blc);
            }
            *reinterpret_cast<float4*>(&Bs[(blr + p*16)*PAD + blc]) = bv;
        }
        __syncthreads();
        #pragma unroll
        for (int kk = 0; kk < BKk; kk++) {
            float4 a = *reinterpret_cast<const float4*>(&As[kk*PAD + (ty<<2)]);
            float4 b4 = *reinterpret_cast<const float4*>(&Bs[kk*PAD + (tx<<2)]);
            float av[4] = {a.x, a.y, a.z, a.w};
            float bv[4] = {b4.x, b4.y, b4.z, b4.w};
            #pragma unroll
            for (int i = 0; i < 4; i++)
                #pragma unroll
                for (int j = 0; j < 4; j++) acc[i][j] += av[i]*bv[j];
        }
        __syncthreads();
    }
    #pragma unroll
    for (int i = 0; i < 4; i++) {
        int o = (ty<<2) + i;
        int n = col0 + (tx<<2);
        float bb = bias[o];
        float4 s;
        s.x = 1.f/(1.f + expf(-(acc[i][0] + bb)));
        s.y = 1.f/(1.f + expf(-(acc[i][1] + bb)));
        s.z = 1.f/(1.f + expf(-(acc[i][2] + bb)));
        s.w = 1.f/(1.f + expf(-(acc[i][3] + bb)));
        size_t idx = ((size_t)(b*Hh + o))*Nn + n;
        if (gate == 0) {
            float4 hv = *reinterpret_cast<const float4*>(g_h + idx);
            float4 rh = make_float4(s.x*hv.x, s.y*hv.y, s.z*hv.z, s.w*hv.w);
            *reinterpret_cast<float4*>(g_zc2 + ((size_t)(b*C1 + 2 + o))*Nn + n) = rh;
        } else {
            *reinterpret_cast<float4*>(g_u + idx) = s;
        }
    }
    if (gate == 0 && tid < 128) {   // copy inp channels (0,1) into zc2
        int ch = tid >> 6, n = col0 + (tid & 63);
        g_zc2[((size_t)(b*C1 + ch))*Nn + n] = g_zc[((size_t)(b*C1 + ch))*Nn + n];
    }
}

// ---------------- update: c = tanh(Wc . zc2-set + bc); h = u*h + (1-u)*c ----------------
__global__ __launch_bounds__(256) void update_kernel(
    const float* __restrict__ Wc, const float* __restrict__ bc)
{
    int b = blockIdx.y;
    int col0 = blockIdx.x*64;
    __shared__ float As[BKk*PAD];
    __shared__ float Bs[BKk*PAD];
    int tid = threadIdx.x;
    int alr = tid >> 3, alc = (tid & 7) << 2;
    int blr = tid >> 4, blc = (tid & 15) << 2;
    int tx = tid & 15, ty = tid >> 4;
    float acc[4][4];
    #pragma unroll
    for (int i = 0; i < 4; i++)
        #pragma unroll
        for (int j = 0; j < 4; j++) acc[i][j] = 0.f;

    for (int k0 = 0; k0 < KC; k0 += BKk) {
        #pragma unroll
        for (int p = 0; p < 2; p++) {
            int o = alr + p*32;
            #pragma unroll
            for (int i = 0; i < 4; i++) {
                int kf = k0 + alc + i;
                As[(alc+i)*PAD + o] = (kf < KC) ? Wc[o*KC + kf] : 0.f;
            }
            int kf = k0 + blr + p*16;
            float4 bv = make_float4(0.f,0.f,0.f,0.f);
            if (kf < KC) {
                int kb = kf / C1, c = kf - kb*C1;
                const float* src = (kb == 0)
                    ? (g_zc2 + ((size_t)(b*C1 + c))*Nn)
                    : (g_zc  + ((size_t)((kb*Bt + b)*C1 + c))*Nn);
                bv = *reinterpret_cast<const float4*>(src + col0 + blc);
            }
            *reinterpret_cast<float4*>(&Bs[(blr + p*16)*PAD + blc]) = bv;
        }
        __syncthreads();
        #pragma unroll
        for (int kk = 0; kk < BKk; kk++) {
            float4 a = *reinterpret_cast<const float4*>(&As[kk*PAD + (ty<<2)]);
            float4 b4 = *reinterpret_cast<const float4*>(&Bs[kk*PAD + (tx<<2)]);
            float av[4] = {a.x, a.y, a.z, a.w};
            float bv[4] = {b4.x, b4.y, b4.z, b4.w};
            #pragma unroll
            for (int i = 0; i < 4; i++)
                #pragma unroll
                for (int j = 0; j < 4; j++) acc[i][j] += av[i]*bv[j];
        }
        __syncthreads();
    }
    #pragma unroll
    for (int i = 0; i < 4; i++) {
        int o = (ty<<2) + i;
        int n = col0 + (tx<<2);
        float bb = bc[o];
        size_t idx = ((size_t)(b*Hh + o))*Nn + n;
        float4 uu = *reinterpret_cast<const float4*>(g_u + idx);
        float4 hh = *reinterpret_cast<const float4*>(g_h + idx);
        float4 hn;
        hn.x = uu.x*hh.x + (1.f-uu.x)*tanhf(acc[i][0] + bb);
        hn.y = uu.y*hh.y + (1.f-uu.y)*tanhf(acc[i][1] + bb);
        hn.z = uu.z*hh.z + (1.f-uu.z)*tanhf(acc[i][2] + bb);
        hn.w = uu.w*hh.w + (1.f-uu.w)*tanhf(acc[i][3] + bb);
        *reinterpret_cast<float4*>(g_h + idx) = hn;
    }
}

// ---------------- launch ----------------
extern "C" void kernel_launch(void* const* d_in, const int* in_sizes, int n_in,
                              void* d_out, int out_size) {
    // Input-order dispatch: dict order (x first, 1048576 elems) vs
    // alphabetical order (Wc first, 21120 elems).
    int ix, imask, iadj, iWr, ibr, iWu, ibu, iWc, ibc, iWout, ibout;
    if (in_sizes[0] == 21120) {
        // alphabetical: Wc, Wout, Wr, Wu, adj, bc, bout, br, bu, mask, x
        iWc = 0; iWout = 1; iWr = 2; iWu = 3; iadj = 4; ibc = 5;
        ibout = 6; ibr = 7; ibu = 8; imask = 9; ix = 10;
    } else {
        // dict order: x, mask, adj, Wr, br, Wu, bu, Wc, bc, Wout, bout
        ix = 0; imask = 1; iadj = 2; iWr = 3; ibr = 4; iWu = 5;
        ibu = 6; iWc = 7; ibc = 8; iWout = 9; ibout = 10;
    }
    const float* x    = (const float*)d_in[ix];
    const void*  mask = d_in[imask];
    const float* adj  = (const float*)d_in[iadj];
    const float* Wr   = (const float*)d_in[iWr];
    const float* br   = (const float*)d_in[ibr];
    const float* Wu   = (const float*)d_in[iWu];
    const float* bu   = (const float*)d_in[ibu];
    const float* Wc   = (const float*)d_in[iWc];
    const float* bc   = (const float*)d_in[ibc];
    const float* Wout = (const float*)d_in[iWout];
    const float* bout = (const float*)d_in[ibout];
    float* out = (float*)d_out;

    detect_mask_kernel<<<1, 32>>>((const unsigned int*)mask);
    norm_kernel<<<Nn, 256>>>(adj);
    transpose_kernel<<<dim3(32,32,2), dim3(32,8)>>>();
    square_kernel<<<dim3(16,16,2), 256>>>();
    zero_h_kernel<<<(Bt*Hh*Nn + 255)/256, 256>>>();

    for (int t = 0; t < Tt; t++) {
        pre_kernel<<<dim3(Nn/128, Bt), 128>>>(x, mask, Wout, bout, out, t);
        diff_kernel<<<dim3(16, 9, 4), 256>>>(0);                 // zc[1..4] from z
        gates_kernel<<<dim3(16, Bt, 2), 256>>>(Wr, br, Wu, bu);  // r,u; zc2 = [inp, r*h]
        diff_kernel<<<dim3(16, 9, 4), 256>>>(1);                 // zc[1..4] from zc2
        update_kernel<<<dim3(16, Bt), 256>>>(Wc, bc);            // c; h update
    }
}

// round 7
// speedup vs baseline: 1.2198x; 1.2198x over previous
#include <cuda_runtime.h>
#include <math.h>

#define Bt 8
#define Nn 1024
#define Hh 64
#define Tt 128
#define C1 66              // channels in xh = 2 + H
#define KC 330             // 5 * C1
#define M_DIFF (Bt*C1)     // 528
#define BS (Bt*C1*Nn)      // one zc block: 540672 floats
#define PRED_SZ (Bt*Nn*Tt) // 1048576

#define BKk 32
#define PAD 68

// diffusion GEMM tile
#define DBM 64
#define DBN 128
#define DBK 16
#define APAD 68            // As rows padded (bytes multiple of 16: 272)
#define BPAD 132           // Bs rows padded (bytes multiple of 16: 528)

// ---------------- f32x2 packed-FMA helpers ----------------
__device__ __forceinline__ unsigned long long pack2(float v) {
    unsigned long long r;
    asm("mov.b64 %0, {%1, %1};" : "=l"(r) : "f"(v));
    return r;
}
__device__ __forceinline__ void ffma2(unsigned long long& d,
                                      unsigned long long a, unsigned long long b) {
    asm("fma.rn.f32x2 %0, %1, %2, %0;" : "+l"(d) : "l"(a), "l"(b));
}
__device__ __forceinline__ float2 unpack2(unsigned long long v) {
    float2 f;
    asm("mov.b64 {%0, %1}, %2;" : "=f"(f.x), "=f"(f.y) : "l"(v));
    return f;
}

// ---------------- device globals (scratch; allocation-free) ----------------
__device__ float g_Sf  [Nn*Nn];
__device__ float g_Sb  [Nn*Nn];
__device__ float g_SfT [Nn*Nn];   // sup_f^T  : [v][w]
__device__ float g_SbT [Nn*Nn];   // sup_b^T
__device__ float g_Sf2T[Nn*Nn];   // (sup_f^2)^T
__device__ float g_Sb2T[Nn*Nn];   // (sup_b^2)^T
__device__ float g_zc  [5*BS];    // [k][b][c][n]; k=0 is z, k=1..4 diffused
__device__ float g_zc2 [BS];      // c-path input [b][c][n] = [x_in, mask, r*h]
__device__ float g_h   [Bt*Hh*Nn];
__device__ float g_u   [Bt*Hh*Nn];
__device__ int   g_masktype;      // 0 = 1-byte elements, 1 = 4-byte elements

// ---------------- mask dtype sniffer ----------------
__global__ void detect_mask_kernel(const unsigned int* __restrict__ m) {
    if (threadIdx.x != 0 || blockIdx.x != 0) return;
    int byte_like = 0;
    for (int i = 0; i < 1024; i++) {
        unsigned int w = m[i];
        if (w == 0u || w == 1u || w == 0x3F800000u) continue;
        unsigned int b0 = w & 255u, b1 = (w >> 8) & 255u,
                     b2 = (w >> 16) & 255u, b3 = w >> 24;
        if (b0 <= 1u && b1 <= 1u && b2 <= 1u && b3 <= 1u) { byte_like = 1; break; }
    }
    g_masktype = byte_like ? 0 : 1;
}

// ---------------- support normalization ----------------
__global__ void norm_kernel(const float* __restrict__ adj) {
    int w = blockIdx.x;
    int tid = threadIdx.x;
    __shared__ float sred[256];
    float rs = 0.f, cs = 0.f;
    for (int v = tid; v < Nn; v += 256) {
        rs += adj[w*Nn + v];
        cs += adj[v*Nn + w];
    }
    sred[tid] = rs; __syncthreads();
    for (int s = 128; s > 0; s >>= 1) { if (tid < s) sred[tid] += sred[tid+s]; __syncthreads(); }
    float rsum = sred[0] + 1e-8f; __syncthreads();
    sred[tid] = cs; __syncthreads();
    for (int s = 128; s > 0; s >>= 1) { if (tid < s) sred[tid] += sred[tid+s]; __syncthreads(); }
    float csum = sred[0] + 1e-8f; __syncthreads();
    for (int v = tid; v < Nn; v += 256) {
        g_Sf[w*Nn + v] = adj[w*Nn + v] / rsum;
        g_Sb[w*Nn + v] = adj[v*Nn + w] / csum;
    }
}

__global__ void transpose_kernel() {
    const float* src = blockIdx.z ? g_Sb : g_Sf;
    float*       dst = blockIdx.z ? g_SbT : g_SfT;
    __shared__ float tile[32][33];
    int x0 = blockIdx.x*32, y0 = blockIdx.y*32;
    int tx = threadIdx.x, ty = threadIdx.y;   // (32,8)
    #pragma unroll
    for (int j = 0; j < 32; j += 8) tile[ty+j][tx] = src[(size_t)(y0+ty+j)*Nn + x0 + tx];
    __syncthreads();
    #pragma unroll
    for (int j = 0; j < 32; j += 8) dst[(size_t)(x0+ty+j)*Nn + y0 + tx] = tile[tx][ty+j];
}

// ---------------- f32x2 GEMM-NN body: 64x128 tile, BK=16, reg prefetch ----------------
// C[m][w] = sum_k A[m][k]*B[k][w]; A:[M][1024] (M<=DBM*gridDim.y), B:[1024][1024]
__device__ __forceinline__ void gemm_nn_f32x2(const float* __restrict__ A,
                                              const float* __restrict__ B,
                                              float* __restrict__ C, int M)
{
    __shared__ float As[DBK][APAD];
    __shared__ float Bs[DBK][BPAD];
    const int tid  = threadIdx.x;
    const int row0 = blockIdx.y*DBM, col0 = blockIdx.x*DBN;
    const int am = tid >> 2, ak = (tid & 3) << 2;    // A: 64 rows x 16 k
    const int bk = tid >> 5, bn = (tid & 31) << 2;   // B: rows bk, bk+8; 128 cols
    const int tx = tid & 15, ty = tid >> 4;

    unsigned long long acc[4][4];
    #pragma unroll
    for (int i = 0; i < 4; i++)
        #pragma unroll
        for (int p = 0; p < 4; p++) acc[i][p] = 0ULL;

    const bool arow_ok = (row0 + am) < M;
    const float* Aptr  = A + (size_t)(row0 + am)*Nn + ak;
    const float* Bptr0 = B + (size_t)bk*Nn + col0 + bn;
    const float* Bptr1 = B + (size_t)(bk + 8)*Nn + col0 + bn;

    float4 areg  = arow_ok ? *(const float4*)Aptr : make_float4(0.f,0.f,0.f,0.f);
    float4 breg0 = *(const float4*)Bptr0;
    float4 breg1 = *(const float4*)Bptr1;

    for (int k0 = 0; k0 < Nn; k0 += DBK) {
        As[ak+0][am] = areg.x; As[ak+1][am] = areg.y;
        As[ak+2][am] = areg.z; As[ak+3][am] = areg.w;
        *(float4*)&Bs[bk][bn]     = breg0;
        *(float4*)&Bs[bk+8][bn]   = breg1;
        __syncthreads();
        if (k0 + DBK < Nn) {
            areg  = arow_ok ? *(const float4*)(Aptr + k0 + DBK) : make_float4(0.f,0.f,0.f,0.f);
            breg0 = *(const float4*)(Bptr0 + (size_t)(k0 + DBK)*Nn);
            breg1 = *(const float4*)(Bptr1 + (size_t)(k0 + DBK)*Nn);
        }
        #pragma unroll
        for (int kk = 0; kk < DBK; kk++) {
            float4 a4 = *(const float4*)&As[kk][ty << 2];
            ulonglong2 b01 = *(const ulonglong2*)&Bs[kk][tx << 2];
            ulonglong2 b23 = *(const ulonglong2*)&Bs[kk][64 + (tx << 2)];
            unsigned long long ap0 = pack2(a4.x), ap1 = pack2(a4.y),
                               ap2 = pack2(a4.z), ap3 = pack2(a4.w);
            ffma2(acc[0][0], ap0, b01.x); ffma2(acc[0][1], ap0, b01.y);
            ffma2(acc[0][2], ap0, b23.x); ffma2(acc[0][3], ap0, b23.y);
            ffma2(acc[1][0], ap1, b01.x); ffma2(acc[1][1], ap1, b01.y);
            ffma2(acc[1][2], ap1, b23.x); ffma2(acc[1][3], ap1, b23.y);
            ffma2(acc[2][0], ap2, b01.x); ffma2(acc[2][1], ap2, b01.y);
            ffma2(acc[2][2], ap2, b23.x); ffma2(acc[2][3], ap2, b23.y);
            ffma2(acc[3][0], ap3, b01.x); ffma2(acc[3][1], ap3, b01.y);
            ffma2(acc[3][2], ap3, b23.x); ffma2(acc[3][3], ap3, b23.y);
        }
        __syncthreads();
    }
    #pragma unroll
    for (int i = 0; i < 4; i++) {
        int m = row0 + (ty << 2) + i;
        if (m < M) {
            float2 p0 = unpack2(acc[i][0]), p1 = unpack2(acc[i][1]);
            float2 p2 = unpack2(acc[i][2]), p3 = unpack2(acc[i][3]);
            *(float4*)(C + (size_t)m*Nn + col0 + (tx << 2))
                = make_float4(p0.x, p0.y, p1.x, p1.y);
            *(float4*)(C + (size_t)m*Nn + col0 + 64 + (tx << 2))
                = make_float4(p2.x, p2.y, p3.x, p3.y);
        }
    }
}

// one-time: Sf2T = SfT @ SfT = (Sf^2)^T ; same for Sb
__global__ __launch_bounds__(256) void square_kernel() {
    const float* S = blockIdx.z ? g_SbT : g_SfT;
    float*       D = blockIdx.z ? g_Sb2T : g_Sf2T;
    gemm_nn_f32x2(S, S, D, Nn);
}

// per-step diffusion: 4 independent GEMMs (Sf, Sf^2, Sb, Sb^2) from z (or zc2)
__global__ __launch_bounds__(256) void diff_kernel(int use2) {
    const float* A = use2 ? g_zc2 : g_zc;
    const float* B; float* C;
    switch (blockIdx.z) {
        case 0:  B = g_SfT;  C = g_zc + 1*(size_t)BS; break;
        case 1:  B = g_Sf2T; C = g_zc + 2*(size_t)BS; break;
        case 2:  B = g_SbT;  C = g_zc + 3*(size_t)BS; break;
        default: B = g_Sb2T; C = g_zc + 4*(size_t)BS; break;
    }
    gemm_nn_f32x2(A, B, C, M_DIFF);
}

__global__ void zero_h_kernel() {
    int i = blockIdx.x*256 + threadIdx.x;
    if (i < Bt*Hh*Nn) g_h[i] = 0.f;
}

// ---------------- per-step: x_hat, outputs, build z ----------------
__global__ __launch_bounds__(128) void pre_kernel(
    const float* __restrict__ x, const void* __restrict__ mask,
    const float* __restrict__ Wout, const float* __restrict__ bout,
    float* __restrict__ out, int t)
{
    int n = blockIdx.x*128 + threadIdx.x;
    int b = blockIdx.y;
    __shared__ float ws[Hh];
    if (threadIdx.x < Hh) ws[threadIdx.x] = Wout[threadIdx.x];
    __syncthreads();
    float acc = 0.f;
    #pragma unroll 4
    for (int hh = 0; hh < Hh; hh++) {
        float hv = g_h[((size_t)(b*Hh + hh))*Nn + n];
        acc += hv * ws[hh];
        g_zc[((size_t)(b*C1 + 2 + hh))*Nn + n] = hv;
        out[PRED_SZ + (((size_t)(b*Hh + hh))*Nn + n)*Tt + t] = hv;
    }
    float xhat = acc + bout[0];
    out[((size_t)(b*Nn) + n)*Tt + t] = xhat;
    size_t xi = ((size_t)b*Nn + n)*Tt + t;
    float xv = x[xi];
    bool m;
    if (g_masktype == 0)
        m = ((const unsigned char*)mask)[xi] != 0;
    else
        m = ((const unsigned int*)mask)[xi] != 0u;
    float xin = m ? xv : xhat;
    g_zc[((size_t)(b*C1) + 0)*Nn + n] = xin;
    g_zc[((size_t)(b*C1) + 1)*Nn + n] = m ? 1.f : 0.f;
}

// ---------------- gates r,u: sigmoid(W . zc + b); fold r*h into zc2 ----------------
__global__ __launch_bounds__(256) void gates_kernel(
    const float* __restrict__ Wr, const float* __restrict__ br,
    const float* __restrict__ Wu, const float* __restrict__ bu)
{
    int b = blockIdx.y, gate = blockIdx.z;
    int col0 = blockIdx.x*64;
    const float* W    = gate ? Wu : Wr;
    const float* bias = gate ? bu : br;
    __shared__ float As[BKk*PAD];
    __shared__ float Bs[BKk*PAD];
    int tid = threadIdx.x;
    int alr = tid >> 3, alc = (tid & 7) << 2;
    int blr = tid >> 4, blc = (tid & 15) << 2;
    int tx = tid & 15, ty = tid >> 4;
    unsigned long long acc[4][2];
    #pragma unroll
    for (int i = 0; i < 4; i++) { acc[i][0] = 0ULL; acc[i][1] = 0ULL; }

    for (int k0 = 0; k0 < KC; k0 += BKk) {
        #pragma unroll
        for (int p = 0; p < 2; p++) {
            int o = alr + p*32;
            #pragma unroll
            for (int i = 0; i < 4; i++) {
                int kf = k0 + alc + i;
                As[(alc+i)*PAD + o] = (kf < KC) ? W[o*KC + kf] : 0.f;
            }
            int kf = k0 + blr + p*16;
            float4 bv = make_float4(0.f,0.f,0.f,0.f);
            if (kf < KC) {
                int kb = kf / C1, c = kf - kb*C1;
                const float* src = g_zc + ((size_t)((kb*Bt + b)*C1 + c))*Nn;
                bv = *reinterpret_cast<const float4*>(src + col0 + blc);
            }
            *reinterpret_cast<float4*>(&Bs[(blr + p*16)*PAD + blc]) = bv;
        }
        __syncthreads();
        #pragma unroll
        for (int kk = 0; kk < BKk; kk++) {
            float4 a = *reinterpret_cast<const float4*>(&As[kk*PAD + (ty<<2)]);
            ulonglong2 b2 = *reinterpret_cast<const ulonglong2*>(&Bs[kk*PAD + (tx<<2)]);
            unsigned long long ap0 = pack2(a.x), ap1 = pack2(a.y),
                               ap2 = pack2(a.z), ap3 = pack2(a.w);
            ffma2(acc[0][0], ap0, b2.x); ffma2(acc[0][1], ap0, b2.y);
            ffma2(acc[1][0], ap1, b2.x); ffma2(acc[1][1], ap1, b2.y);
            ffma2(acc[2][0], ap2, b2.x); ffma2(acc[2][1], ap2, b2.y);
            ffma2(acc[3][0], ap3, b2.x); ffma2(acc[3][1], ap3, b2.y);
        }
        __syncthreads();
    }
    #pragma unroll
    for (int i = 0; i < 4; i++) {
        int o = (ty<<2) + i;
        int n = col0 + (tx<<2);
        float bb = bias[o];
        float2 q0 = unpack2(acc[i][0]), q1 = unpack2(acc[i][1]);
        float4 s;
        s.x = 1.f/(1.f + expf(-(q0.x + bb)));
        s.y = 1.f/(1.f + expf(-(q0.y + bb)));
        s.z = 1.f/(1.f + expf(-(q1.x + bb)));
        s.w = 1.f/(1.f + expf(-(q1.y + bb)));
        size_t idx = ((size_t)(b*Hh + o))*Nn + n;
        if (gate == 0) {
            float4 hv = *reinterpret_cast<const float4*>(g_h + idx);
            float4 rh = make_float4(s.x*hv.x, s.y*hv.y, s.z*hv.z, s.w*hv.w);
            *reinterpret_cast<float4*>(g_zc2 + ((size_t)(b*C1 + 2 + o))*Nn + n) = rh;
        } else {
            *reinterpret_cast<float4*>(g_u + idx) = s;
        }
    }
    if (gate == 0 && tid < 128) {   // copy inp channels (0,1) into zc2
        int ch = tid >> 6, n = col0 + (tid & 63);
        g_zc2[((size_t)(b*C1 + ch))*Nn + n] = g_zc[((size_t)(b*C1 + ch))*Nn + n];
    }
}

// ---------------- update: c = tanh(Wc . zc2-set + bc); h = u*h + (1-u)*c ----------------
__global__ __launch_bounds__(256) void update_kernel(
    const float* __restrict__ Wc, const float* __restrict__ bc)
{
    int b = blockIdx.y;
    int col0 = blockIdx.x*64;
    __shared__ float As[BKk*PAD];
    __shared__ float Bs[BKk*PAD];
    int tid = threadIdx.x;
    int alr = tid >> 3, alc = (tid & 7) << 2;
    int blr = tid >> 4, blc = (tid & 15) << 2;
    int tx = tid & 15, ty = tid >> 4;
    unsigned long long acc[4][2];
    #pragma unroll
    for (int i = 0; i < 4; i++) { acc[i][0] = 0ULL; acc[i][1] = 0ULL; }

    for (int k0 = 0; k0 < KC; k0 += BKk) {
        #pragma unroll
        for (int p = 0; p < 2; p++) {
            int o = alr + p*32;
            #pragma unroll
            for (int i = 0; i < 4; i++) {
                int kf = k0 + alc + i;
                As[(alc+i)*PAD + o] = (kf < KC) ? Wc[o*KC + kf] : 0.f;
            }
            int kf = k0 + blr + p*16;
            float4 bv = make_float4(0.f,0.f,0.f,0.f);
            if (kf < KC) {
                int kb = kf / C1, c = kf - kb*C1;
                const float* src = (kb == 0)
                    ? (g_zc2 + ((size_t)(b*C1 + c))*Nn)
                    : (g_zc  + ((size_t)((kb*Bt + b)*C1 + c))*Nn);
                bv = *reinterpret_cast<const float4*>(src + col0 + blc);
            }
            *reinterpret_cast<float4*>(&Bs[(blr + p*16)*PAD + blc]) = bv;
        }
        __syncthreads();
        #pragma unroll
        for (int kk = 0; kk < BKk; kk++) {
            float4 a = *reinterpret_cast<const float4*>(&As[kk*PAD + (ty<<2)]);
            ulonglong2 b2 = *reinterpret_cast<const ulonglong2*>(&Bs[kk*PAD + (tx<<2)]);
            unsigned long long ap0 = pack2(a.x), ap1 = pack2(a.y),
                               ap2 = pack2(a.z), ap3 = pack2(a.w);
            ffma2(acc[0][0], ap0, b2.x); ffma2(acc[0][1], ap0, b2.y);
            ffma2(acc[1][0], ap1, b2.x); ffma2(acc[1][1], ap1, b2.y);
            ffma2(acc[2][0], ap2, b2.x); ffma2(acc[2][1], ap2, b2.y);
            ffma2(acc[3][0], ap3, b2.x); ffma2(acc[3][1], ap3, b2.y);
        }
        __syncthreads();
    }
    #pragma unroll
    for (int i = 0; i < 4; i++) {
        int o = (ty<<2) + i;
        int n = col0 + (tx<<2);
        float bb = bc[o];
        size_t idx = ((size_t)(b*Hh + o))*Nn + n;
        float2 q0 = unpack2(acc[i][0]), q1 = unpack2(acc[i][1]);
        float4 uu = *reinterpret_cast<const float4*>(g_u + idx);
        float4 hh = *reinterpret_cast<const float4*>(g_h + idx);
        float4 hn;
        hn.x = uu.x*hh.x + (1.f-uu.x)*tanhf(q0.x + bb);
        hn.y = uu.y*hh.y + (1.f-uu.y)*tanhf(q0.y + bb);
        hn.z = uu.z*hh.z + (1.f-uu.z)*tanhf(q1.x + bb);
        hn.w = uu.w*hh.w + (1.f-uu.w)*tanhf(q1.y + bb);
        *reinterpret_cast<float4*>(g_h + idx) = hn;
    }
}

// ---------------- launch ----------------
extern "C" void kernel_launch(void* const* d_in, const int* in_sizes, int n_in,
                              void* d_out, int out_size) {
    int ix, imask, iadj, iWr, ibr, iWu, ibu, iWc, ibc, iWout, ibout;
    if (in_sizes[0] == 21120) {
        // alphabetical: Wc, Wout, Wr, Wu, adj, bc, bout, br, bu, mask, x
        iWc = 0; iWout = 1; iWr = 2; iWu = 3; iadj = 4; ibc = 5;
        ibout = 6; ibr = 7; ibu = 8; imask = 9; ix = 10;
    } else {
        // dict order: x, mask, adj, Wr, br, Wu, bu, Wc, bc, Wout, bout
        ix = 0; imask = 1; iadj = 2; iWr = 3; ibr = 4; iWu = 5;
        ibu = 6; iWc = 7; ibc = 8; iWout = 9; ibout = 10;
    }
    const float* x    = (const float*)d_in[ix];
    const void*  mask = d_in[imask];
    const float* adj  = (const float*)d_in[iadj];
    const float* Wr   = (const float*)d_in[iWr];
    const float* br   = (const float*)d_in[ibr];
    const float* Wu   = (const float*)d_in[iWu];
    const float* bu   = (const float*)d_in[ibu];
    const float* Wc   = (const float*)d_in[iWc];
    const float* bc   = (const float*)d_in[ibc];
    const float* Wout = (const float*)d_in[iWout];
    const float* bout = (const float*)d_in[ibout];
    float* out = (float*)d_out;

    detect_mask_kernel<<<1, 32>>>((const unsigned int*)mask);
    norm_kernel<<<Nn, 256>>>(adj);
    transpose_kernel<<<dim3(32,32,2), dim3(32,8)>>>();
    square_kernel<<<dim3(Nn/DBN, Nn/DBM, 2), 256>>>();
    zero_h_kernel<<<(Bt*Hh*Nn + 255)/256, 256>>>();

    for (int t = 0; t < Tt; t++) {
        pre_kernel<<<dim3(Nn/128, Bt), 128>>>(x, mask, Wout, bout, out, t);
        diff_kernel<<<dim3(Nn/DBN, (M_DIFF + DBM - 1)/DBM, 4), 256>>>(0);
        gates_kernel<<<dim3(16, Bt, 2), 256>>>(Wr, br, Wu, bu);
        diff_kernel<<<dim3(Nn/DBN, (M_DIFF + DBM - 1)/DBM, 4), 256>>>(1);
        update_kernel<<<dim3(16, Bt), 256>>>(Wc, bc);
    }
}

// round 11
// speedup vs baseline: 1.3585x; 1.1137x over previous
#include <cuda_runtime.h>
#include <cuda_bf16.h>
#include <math.h>
#include <stdint.h>

#define Bt 8
#define Nn 1024
#define Hh 64
#define Tt 128
#define C1 66              // channels in xh = 2 + H
#define KC 330             // 5 * C1
#define M_DIFF (Bt*C1)     // 528
#define M_PAD 640          // padded A rows (5 tiles of 128)
#define BS (Bt*C1*Nn)      // one zc block: 540672 floats
#define PRED_SZ (Bt*Nn*Tt) // 1048576

#define BKk 32
#define PAD 68

// f32x2 square-GEMM tile
#define DBM 64
#define DBN 128
#define DBK 16
#define APAD 68
#define BPAD 132

// HMMA diffusion kernel layout
#define SROW 40                        // 32 data + 8 pad bf16 (80B rows, 16B aligned)
#define BUF_B (128*SROW*2)             // 10240 bytes per buffer
#define STAGE_B (4*BUF_B)              // 40960 bytes per stage
#define DIFF_SMEM (2*STAGE_B)          // 81920 bytes

// ---------------- f32x2 packed-FMA helpers ----------------
__device__ __forceinline__ unsigned long long pack2(float v) {
    unsigned long long r;
    asm("mov.b64 %0, {%1, %1};" : "=l"(r) : "f"(v));
    return r;
}
__device__ __forceinline__ void ffma2(unsigned long long& d,
                                      unsigned long long a, unsigned long long b) {
    asm("fma.rn.f32x2 %0, %1, %2, %0;" : "+l"(d) : "l"(a), "l"(b));
}
__device__ __forceinline__ float2 unpack2(unsigned long long v) {
    float2 f;
    asm("mov.b64 {%0, %1}, %2;" : "=f"(f.x), "=f"(f.y) : "l"(v));
    return f;
}

// ---------------- HMMA helpers (sm_80-era PTX; valid on plain sm_103) ----------------
__device__ __forceinline__ uint32_t smem_u32(const void* p) {
    uint32_t a;
    asm("{ .reg .u64 t; cvta.to.shared.u64 t, %1; cvt.u32.u64 %0, t; }" : "=r"(a) : "l"(p));
    return a;
}
__device__ __forceinline__ void ldsm4(uint32_t& r0, uint32_t& r1, uint32_t& r2, uint32_t& r3,
                                      uint32_t addr) {
    asm volatile("ldmatrix.sync.aligned.m8n8.x4.shared.b16 {%0,%1,%2,%3}, [%4];"
                 : "=r"(r0), "=r"(r1), "=r"(r2), "=r"(r3) : "r"(addr));
}
__device__ __forceinline__ void mma_bf16(float* c, const uint32_t* a, uint32_t b0, uint32_t b1) {
    asm volatile(
        "mma.sync.aligned.m16n8k16.row.col.f32.bf16.bf16.f32 "
        "{%0,%1,%2,%3}, {%4,%5,%6,%7}, {%8,%9}, {%0,%1,%2,%3};"
        : "+f"(c[0]), "+f"(c[1]), "+f"(c[2]), "+f"(c[3])
        : "r"(a[0]), "r"(a[1]), "r"(a[2]), "r"(a[3]), "r"(b0), "r"(b1));
}
__device__ __forceinline__ void cp16(uint32_t saddr, const void* gaddr) {
    asm volatile("cp.async.cg.shared.global [%0], [%1], 16;" :: "r"(saddr), "l"(gaddr));
}
#define CP_COMMIT() asm volatile("cp.async.commit_group;" ::: "memory")
#define CP_WAIT1()  asm volatile("cp.async.wait_group 1;" ::: "memory")

// ---------------- device globals (scratch; allocation-free) ----------------
__device__ float g_Sf [Nn*Nn];
__device__ float g_Sb [Nn*Nn];
__device__ float g_Sf2[Nn*Nn];    // Sf @ Sf
__device__ float g_Sb2[Nn*Nn];    // Sb @ Sb
__device__ float g_zc [5*BS];     // [k][b][c][n]; k=0 is z, k=1..4 diffused (fp32)
__device__ float g_zc2[BS];       // c-path input fp32 [b][c][n]
__device__ float g_h  [Bt*Hh*Nn];
__device__ float g_u  [Bt*Hh*Nn];
__device__ int   g_masktype;
// bf16 split operands for tensor-core diffusion
__device__ __nv_bfloat16 g_zAhi[2][M_PAD*Nn];   // set 0: z, set 1: zc2
__device__ __nv_bfloat16 g_zAlo[2][M_PAD*Nn];
__device__ __nv_bfloat16 g_SBhi[4][Nn*Nn];      // Sf, Sf2, Sb, Sb2 (row-major [w][v])
__device__ __nv_bfloat16 g_SBlo[4][Nn*Nn];

__device__ __forceinline__ void split_store(float v, __nv_bfloat16* hi, __nv_bfloat16* lo,
                                            size_t idx) {
    __nv_bfloat16 h = __float2bfloat16(v);
    hi[idx] = h;
    lo[idx] = __float2bfloat16(v - __bfloat162float(h));
}

// ---------------- mask dtype sniffer ----------------
__global__ void detect_mask_kernel(const unsigned int* __restrict__ m) {
    if (threadIdx.x != 0 || blockIdx.x != 0) return;
    int byte_like = 0;
    for (int i = 0; i < 1024; i++) {
        unsigned int w = m[i];
        if (w == 0u || w == 1u || w == 0x3F800000u) continue;
        unsigned int b0 = w & 255u, b1 = (w >> 8) & 255u,
                     b2 = (w >> 16) & 255u, b3 = w >> 24;
        if (b0 <= 1u && b1 <= 1u && b2 <= 1u && b3 <= 1u) { byte_like = 1; break; }
    }
    g_masktype = byte_like ? 0 : 1;
}

// ---------------- support normalization ----------------
__global__ void norm_kernel(const float* __restrict__ adj) {
    int w = blockIdx.x;
    int tid = threadIdx.x;
    __shared__ float sred[256];
    float rs = 0.f, cs = 0.f;
    for (int v = tid; v < Nn; v += 256) {
        rs += adj[w*Nn + v];
        cs += adj[v*Nn + w];
    }
    sred[tid] = rs; __syncthreads();
    for (int s = 128; s > 0; s >>= 1) { if (tid < s) sred[tid] += sred[tid+s]; __syncthreads(); }
    float rsum = sred[0] + 1e-8f; __syncthreads();
    sred[tid] = cs; __syncthreads();
    for (int s = 128; s > 0; s >>= 1) { if (tid < s) sred[tid] += sred[tid+s]; __syncthreads(); }
    float csum = sred[0] + 1e-8f; __syncthreads();
    for (int v = tid; v < Nn; v += 256) {
        g_Sf[w*Nn + v] = adj[w*Nn + v] / rsum;
        g_Sb[w*Nn + v] = adj[v*Nn + w] / csum;
    }
}

// ---------------- f32x2 GEMM-NN (used once for S^2) ----------------
__device__ __forceinline__ void gemm_nn_f32x2(const float* __restrict__ A,
                                              const float* __restrict__ B,
                                              float* __restrict__ C, int M)
{
    __shared__ float As[DBK][APAD];
    __shared__ float Bs[DBK][BPAD];
    const int tid  = threadIdx.x;
    const int row0 = blockIdx.y*DBM, col0 = blockIdx.x*DBN;
    const int am = tid >> 2, ak = (tid & 3) << 2;
    const int bk = tid >> 5, bn = (tid & 31) << 2;
    const int tx = tid & 15, ty = tid >> 4;

    unsigned long long acc[4][4];
    #pragma unroll
    for (int i = 0; i < 4; i++)
        #pragma unroll
        for (int p = 0; p < 4; p++) acc[i][p] = 0ULL;

    const bool arow_ok = (row0 + am) < M;
    const float* Aptr  = A + (size_t)(row0 + am)*Nn + ak;
    const float* Bptr0 = B + (size_t)bk*Nn + col0 + bn;
    const float* Bptr1 = B + (size_t)(bk + 8)*Nn + col0 + bn;

    float4 areg  = arow_ok ? *(const float4*)Aptr : make_float4(0.f,0.f,0.f,0.f);
    float4 breg0 = *(const float4*)Bptr0;
    float4 breg1 = *(const float4*)Bptr1;

    for (int k0 = 0; k0 < Nn; k0 += DBK) {
        As[ak+0][am] = areg.x; As[ak+1][am] = areg.y;
        As[ak+2][am] = areg.z; As[ak+3][am] = areg.w;
        *(float4*)&Bs[bk][bn]   = breg0;
        *(float4*)&Bs[bk+8][bn] = breg1;
        __syncthreads();
        if (k0 + DBK < Nn) {
            areg  = arow_ok ? *(const float4*)(Aptr + k0 + DBK) : make_float4(0.f,0.f,0.f,0.f);
            breg0 = *(const float4*)(Bptr0 + (size_t)(k0 + DBK)*Nn);
            breg1 = *(const float4*)(Bptr1 + (size_t)(k0 + DBK)*Nn);
        }
        #pragma unroll
        for (int kk = 0; kk < DBK; kk++) {
            float4 a4 = *(const float4*)&As[kk][ty << 2];
            ulonglong2 b01 = *(const ulonglong2*)&Bs[kk][tx << 2];
            ulonglong2 b23 = *(const ulonglong2*)&Bs[kk][64 + (tx << 2)];
            unsigned long long ap0 = pack2(a4.x), ap1 = pack2(a4.y),
                               ap2 = pack2(a4.z), ap3 = pack2(a4.w);
            ffma2(acc[0][0], ap0, b01.x); ffma2(acc[0][1], ap0, b01.y);
            ffma2(acc[0][2], ap0, b23.x); ffma2(acc[0][3], ap0, b23.y);
            ffma2(acc[1][0], ap1, b01.x); ffma2(acc[1][1], ap1, b01.y);
            ffma2(acc[1][2], ap1, b23.x); ffma2(acc[1][3], ap1, b23.y);
            ffma2(acc[2][0], ap2, b01.x); ffma2(acc[2][1], ap2, b01.y);
            ffma2(acc[2][2], ap2, b23.x); ffma2(acc[2][3], ap2, b23.y);
            ffma2(acc[3][0], ap3, b01.x); ffma2(acc[3][1], ap3, b01.y);
            ffma2(acc[3][2], ap3, b23.x); ffma2(acc[3][3], ap3, b23.y);
        }
        __syncthreads();
    }
    #pragma unroll
    for (int i = 0; i < 4; i++) {
        int m = row0 + (ty << 2) + i;
        if (m < M) {
            float2 p0 = unpack2(acc[i][0]), p1 = unpack2(acc[i][1]);
            float2 p2 = unpack2(acc[i][2]), p3 = unpack2(acc[i][3]);
            *(float4*)(C + (size_t)m*Nn + col0 + (tx << 2))
                = make_float4(p0.x, p0.y, p1.x, p1.y);
            *(float4*)(C + (size_t)m*Nn + col0 + 64 + (tx << 2))
                = make_float4(p2.x, p2.y, p3.x, p3.y);
        }
    }
}

// one-time: Sf2 = Sf @ Sf ; Sb2 = Sb @ Sb
__global__ __launch_bounds__(256) void square_kernel() {
    const float* S = blockIdx.z ? g_Sb : g_Sf;
    float*       D = blockIdx.z ? g_Sb2 : g_Sf2;
    gemm_nn_f32x2(S, S, D, Nn);
}

// one-time: supports -> bf16 hi/lo
__global__ void conv_support_kernel() {
    int s = blockIdx.y;
    const float* src = (s == 0) ? g_Sf : (s == 1) ? g_Sf2 : (s == 2) ? g_Sb : g_Sb2;
    size_t i = (size_t)blockIdx.x*256 + threadIdx.x;
    split_store(src[i], g_SBhi[s], g_SBlo[s], i);
}

// one-time: zero pad rows [528,640) of bf16 A buffers
__global__ void zero_pad_kernel() {
    size_t i = (size_t)blockIdx.x*256 + threadIdx.x;   // < 112*1024
    int w = blockIdx.y;
    __nv_bfloat16 z = __float2bfloat16(0.f);
    size_t off = (size_t)M_DIFF*Nn + i;
    if (w == 0) g_zAhi[0][off] = z;
    else if (w == 1) g_zAlo[0][off] = z;
    else if (w == 2) g_zAhi[1][off] = z;
    else g_zAlo[1][off] = z;
}

__global__ void zero_h_kernel() {
    int i = blockIdx.x*256 + threadIdx.x;
    if (i < Bt*Hh*Nn) g_h[i] = 0.f;
}

// ---------------- HMMA diffusion: D[m][w] = sum_v A[m][v] * S[w][v] ----------------
// grid (8 N-tiles, 5 M-tiles, 4 supports), 256 threads (8 warps of 64x32 tiles),
// bf16 split 3-pass, cp.async 2-stage pipeline.
__global__ __launch_bounds__(256) void diff_mma_kernel(int set) {
    extern __shared__ char smem[];
    const uint32_t sb = smem_u32(smem);
    const int tid = threadIdx.x, wid = tid >> 5, lane = tid & 31;
    const int n0 = blockIdx.x*128, m0 = blockIdx.y*128, s = blockIdx.z;
    const int wm = (wid >> 2) << 6;    // 0 or 64
    const int wn = (wid & 3) << 5;     // 0,32,64,96

    const __nv_bfloat16* __restrict__ Ah = g_zAhi[set] + (size_t)m0*Nn;
    const __nv_bfloat16* __restrict__ Al = g_zAlo[set] + (size_t)m0*Nn;
    const __nv_bfloat16* __restrict__ Bh = g_SBhi[s]   + (size_t)n0*Nn;
    const __nv_bfloat16* __restrict__ Bl = g_SBlo[s]   + (size_t)n0*Nn;
    const __nv_bfloat16* srcs[4] = {Ah, Al, Bh, Bl};

    // cp.async mapping: 8 chunks of 16B per thread per stage
    int crow[8], cseg[8], cbuf[8];
    #pragma unroll
    for (int j = 0; j < 8; j++) {
        int c = j*256 + tid;           // 0..2047
        cbuf[j] = c >> 9;              // buffer 0..3
        int cr  = c & 511;
        crow[j] = cr >> 2;             // row 0..127
        cseg[j] = cr & 3;              // 16B segment 0..3
    }

    float acc[4][4][4];
    #pragma unroll
    for (int mt = 0; mt < 4; mt++)
        #pragma unroll
        for (int nb = 0; nb < 4; nb++)
            #pragma unroll
            for (int q = 0; q < 4; q++) acc[mt][nb][q] = 0.f;

    // prologue: stage 0 (chunk 0), stage 1 (chunk 1)
    #pragma unroll
    for (int st = 0; st < 2; st++) {
        int k0 = st*32;
        #pragma unroll
        for (int j = 0; j < 8; j++) {
            uint32_t da = sb + st*STAGE_B + cbuf[j]*BUF_B + (crow[j]*SROW + cseg[j]*8)*2;
            cp16(da, srcs[cbuf[j]] + (size_t)crow[j]*Nn + k0 + cseg[j]*8);
        }
        CP_COMMIT();
    }

    const int ar = lane & 15;            // ldmatrix row-in-16
    const int ac = (lane >> 4) << 3;     // ldmatrix col half

    for (int c = 0; c < 32; c++) {
        const int st = c & 1;
        const uint32_t so = sb + st*STAGE_B;
        CP_WAIT1();
        __syncthreads();

        #pragma unroll
        for (int kk = 0; kk < 2; kk++) {
            const int k = kk << 4;
            uint32_t ah[4][4], al[4][4], bh[2][4], bl[2][4];
            #pragma unroll
            for (int mt = 0; mt < 4; mt++) {
                uint32_t off = ((wm + mt*16 + ar)*SROW + k + ac)*2;
                ldsm4(ah[mt][0], ah[mt][1], ah[mt][2], ah[mt][3], so + 0*BUF_B + off);
                ldsm4(al[mt][0], al[mt][1], al[mt][2], al[mt][3], so + 1*BUF_B + off);
            }
            #pragma unroll
            for (int nt = 0; nt < 2; nt++) {
                uint32_t off = ((wn + nt*16 + ar)*SROW + k + ac)*2;
                ldsm4(bh[nt][0], bh[nt][1], bh[nt][2], bh[nt][3], so + 2*BUF_B + off);
                ldsm4(bl[nt][0], bl[nt][1], bl[nt][2], bl[nt][3], so + 3*BUF_B + off);
            }
            // b frag for n8-block nb: nt = nb>>1, half = nb&1 -> regs (half, 2+half)
            #pragma unroll
            for (int mt = 0; mt < 4; mt++)
                #pragma unroll
                for (int nb = 0; nb < 4; nb++) {
                    int nt = nb >> 1, hf = nb & 1;
                    mma_bf16(acc[mt][nb], ah[mt], bh[nt][hf], bh[nt][2+hf]);
                    mma_bf16(acc[mt][nb], ah[mt], bl[nt][hf], bl[nt][2+hf]);
                    mma_bf16(acc[mt][nb], al[mt], bh[nt][hf], bh[nt][2+hf]);
                }
        }
        __syncthreads();
        if (c + 2 < 32) {
            int k0 = (c + 2)*32;
            #pragma unroll
            for (int j = 0; j < 8; j++) {
                uint32_t da = sb + st*STAGE_B + cbuf[j]*BUF_B + (crow[j]*SROW + cseg[j]*8)*2;
                cp16(da, srcs[cbuf[j]] + (size_t)crow[j]*Nn + k0 + cseg[j]*8);
            }
        }
        CP_COMMIT();
    }

    // epilogue: fp32 store to g_zc[s+1]
    float* C = g_zc + (size_t)(s + 1)*BS;
    const int mr = lane >> 2, nc = (lane & 3) << 1;
    #pragma unroll
    for (int mt = 0; mt < 4; mt++) {
        #pragma unroll
        for (int nb = 0; nb < 4; nb++) {
            int m = m0 + wm + mt*16 + mr;
            int n = n0 + wn + nb*8 + nc;
            if (m < M_DIFF)
                *(float2*)(C + (size_t)m*Nn + n) = make_float2(acc[mt][nb][0], acc[mt][nb][1]);
            if (m + 8 < M_DIFF)
                *(float2*)(C + (size_t)(m + 8)*Nn + n) = make_float2(acc[mt][nb][2], acc[mt][nb][3]);
        }
    }
}

// ---------------- per-step: x_hat, outputs, build z (fp32 + bf16 split) ----------------
__global__ __launch_bounds__(128) void pre_kernel(
    const float* __restrict__ x, const void* __restrict__ mask,
    const float* __restrict__ Wout, const float* __restrict__ bout,
    float* __restrict__ out, int t)
{
    int n = blockIdx.x*128 + threadIdx.x;
    int b = blockIdx.y;
    __shared__ float ws[Hh];
    if (threadIdx.x < Hh) ws[threadIdx.x] = Wout[threadIdx.x];
    __syncthreads();
    float acc = 0.f;
    #pragma unroll 4
    for (int hh = 0; hh < Hh; hh++) {
        float hv = g_h[((size_t)(b*Hh + hh))*Nn + n];
        acc += hv * ws[hh];
        size_t ridx = ((size_t)(b*C1 + 2 + hh))*Nn + n;
        g_zc[ridx] = hv;
        split_store(hv, g_zAhi[0], g_zAlo[0], ridx);
        out[PRED_SZ + (((size_t)(b*Hh + hh))*Nn + n)*Tt + t] = hv;
    }
    float xhat = acc + bout[0];
    out[((size_t)(b*Nn) + n)*Tt + t] = xhat;
    size_t xi = ((size_t)b*Nn + n)*Tt + t;
    float xv = x[xi];
    bool m;
    if (g_masktype == 0)
        m = ((const unsigned char*)mask)[xi] != 0;
    else
        m = ((const unsigned int*)mask)[xi] != 0u;
    float xin = m ? xv : xhat;
    float mf  = m ? 1.f : 0.f;
    size_t r0 = ((size_t)(b*C1) + 0)*Nn + n;
    size_t r1 = ((size_t)(b*C1) + 1)*Nn + n;
    g_zc[r0] = xin;  split_store(xin, g_zAhi[0], g_zAlo[0], r0);
    g_zc[r1] = mf;   split_store(mf,  g_zAhi[0], g_zAlo[0], r1);
}

// ---------------- gates r,u ----------------
__global__ __launch_bounds__(256) void gates_kernel(
    const float* __restrict__ Wr, const float* __restrict__ br,
    const float* __restrict__ Wu, const float* __restrict__ bu)
{
    int b = blockIdx.y, gate = blockIdx.z;
    int col0 = blockIdx.x*64;
    const float* W    = gate ? Wu : Wr;
    const float* bias = gate ? bu : br;
    __shared__ float As[BKk*PAD];
    __shared__ float Bs[BKk*PAD];
    int tid = threadIdx.x;
    int alr = tid >> 3, alc = (tid & 7) << 2;
    int blr = tid >> 4, blc = (tid & 15) << 2;
    int tx = tid & 15, ty = tid >> 4;
    unsigned long long acc[4][2];
    #pragma unroll
    for (int i = 0; i < 4; i++) { acc[i][0] = 0ULL; acc[i][1] = 0ULL; }

    for (int k0 = 0; k0 < KC; k0 += BKk) {
        #pragma unroll
        for (int p = 0; p < 2; p++) {
            int o = alr + p*32;
            #pragma unroll
            for (int i = 0; i < 4; i++) {
                int kf = k0 + alc + i;
                As[(alc+i)*PAD + o] = (kf < KC) ? W[o*KC + kf] : 0.f;
            }
            int kf = k0 + blr + p*16;
            float4 bv = make_float4(0.f,0.f,0.f,0.f);
            if (kf < KC) {
                int kb = kf / C1, c = kf - kb*C1;
                const float* src = g_zc + ((size_t)((kb*Bt + b)*C1 + c))*Nn;
                bv = *reinterpret_cast<const float4*>(src + col0 + blc);
            }
            *reinterpret_cast<float4*>(&Bs[(blr + p*16)*PAD + blc]) = bv;
        }
        __syncthreads();
        #pragma unroll
        for (int kk = 0; kk < BKk; kk++) {
            float4 a = *reinterpret_cast<const float4*>(&As[kk*PAD + (ty<<2)]);
            ulonglong2 b2 = *reinterpret_cast<const ulonglong2*>(&Bs[kk*PAD + (tx<<2)]);
            unsigned long long ap0 = pack2(a.x), ap1 = pack2(a.y),
                               ap2 = pack2(a.z), ap3 = pack2(a.w);
            ffma2(acc[0][0], ap0, b2.x); ffma2(acc[0][1], ap0, b2.y);
            ffma2(acc[1][0], ap1, b2.x); ffma2(acc[1][1], ap1, b2.y);
            ffma2(acc[2][0], ap2, b2.x); ffma2(acc[2][1], ap2, b2.y);
            ffma2(acc[3][0], ap3, b2.x); ffma2(acc[3][1], ap3, b2.y);
        }
        __syncthreads();
    }
    #pragma unroll
    for (int i = 0; i < 4; i++) {
        int o = (ty<<2) + i;
        int n = col0 + (tx<<2);
        float bb = bias[o];
        float2 q0 = unpack2(acc[i][0]), q1 = unpack2(acc[i][1]);
        float4 s;
        s.x = 1.f/(1.f + expf(-(q0.x + bb)));
        s.y = 1.f/(1.f + expf(-(q0.y + bb)));
        s.z = 1.f/(1.f + expf(-(q1.x + bb)));
        s.w = 1.f/(1.f + expf(-(q1.y + bb)));
        size_t idx = ((size_t)(b*Hh + o))*Nn + n;
        if (gate == 0) {
            float4 hv = *reinterpret_cast<const float4*>(g_h + idx);
            float4 rh = make_float4(s.x*hv.x, s.y*hv.y, s.z*hv.z, s.w*hv.w);
            size_t zi = ((size_t)(b*C1 + 2 + o))*Nn + n;
            *reinterpret_cast<float4*>(g_zc2 + zi) = rh;
            split_store(rh.x, g_zAhi[1], g_zAlo[1], zi + 0);
            split_store(rh.y, g_zAhi[1], g_zAlo[1], zi + 1);
            split_store(rh.z, g_zAhi[1], g_zAlo[1], zi + 2);
            split_store(rh.w, g_zAhi[1], g_zAlo[1], zi + 3);
        } else {
            *reinterpret_cast<float4*>(g_u + idx) = s;
        }
    }
    if (gate == 0 && tid < 128) {   // copy inp channels (0,1) into zc2 (+ bf16)
        int ch = tid >> 6, n = col0 + (tid & 63);
        size_t zi = ((size_t)(b*C1 + ch))*Nn + n;
        float v = g_zc[zi];
        g_zc2[zi] = v;
        split_store(v, g_zAhi[1], g_zAlo[1], zi);
    }
}

// ---------------- update: c = tanh(Wc . zc2-set + bc); h = u*h + (1-u)*c ----------------
__global__ __launch_bounds__(256) void update_kernel(
    const float* __restrict__ Wc, const float* __restrict__ bc)
{
    int b = blockIdx.y;
    int col0 = blockIdx.x*64;
    __shared__ float As[BKk*PAD];
    __shared__ float Bs[BKk*PAD];
    int tid = threadIdx.x;
    int alr = tid >> 3, alc = (tid & 7) << 2;
    int blr = tid >> 4, blc = (tid & 15) << 2;
    int tx = tid & 15, ty = tid >> 4;
    unsigned long long acc[4][2];
    #pragma unroll
    for (int i = 0; i < 4; i++) { acc[i][0] = 0ULL; acc[i][1] = 0ULL; }

    for (int k0 = 0; k0 < KC; k0 += BKk) {
        #pragma unroll
        for (int p = 0; p < 2; p++) {
            int o = alr + p*32;
            #pragma unroll
            for (int i = 0; i < 4; i++) {
                int kf = k0 + alc + i;
                As[(alc+i)*PAD + o] = (kf < KC) ? Wc[o*KC + kf] : 0.f;
            }
            int kf = k0 + blr + p*16;
            float4 bv = make_float4(0.f,0.f,0.f,0.f);
            if (kf < KC) {
                int kb = kf / C1, c = kf - kb*C1;
                const float* src = (kb == 0)
                    ? (g_zc2 + ((size_t)(b*C1 + c))*Nn)
                    : (g_zc  + ((size_t)((kb*Bt + b)*C1 + c))*Nn);
                bv = *reinterpret_cast<const float4*>(src + col0 + blc);
            }
            *reinterpret_cast<float4*>(&Bs[(blr + p*16)*PAD + blc]) = bv;
        }
        __syncthreads();
        #pragma unroll
        for (int kk = 0; kk < BKk; kk++) {
            float4 a = *reinterpret_cast<const float4*>(&As[kk*PAD + (ty<<2)]);
            ulonglong2 b2 = *reinterpret_cast<const ulonglong2*>(&Bs[kk*PAD + (tx<<2)]);
            unsigned long long ap0 = pack2(a.x), ap1 = pack2(a.y),
                               ap2 = pack2(a.z), ap3 = pack2(a.w);
            ffma2(acc[0][0], ap0, b2.x); ffma2(acc[0][1], ap0, b2.y);
            ffma2(acc[1][0], ap1, b2.x); ffma2(acc[1][1], ap1, b2.y);
            ffma2(acc[2][0], ap2, b2.x); ffma2(acc[2][1], ap2, b2.y);
            ffma2(acc[3][0], ap3, b2.x); ffma2(acc[3][1], ap3, b2.y);
        }
        __syncthreads();
    }
    #pragma unroll
    for (int i = 0; i < 4; i++) {
        int o = (ty<<2) + i;
        int n = col0 + (tx<<2);
        float bb = bc[o];
        size_t idx = ((size_t)(b*Hh + o))*Nn + n;
        float2 q0 = unpack2(acc[i][0]), q1 = unpack2(acc[i][1]);
        float4 uu = *reinterpret_cast<const float4*>(g_u + idx);
        float4 hh = *reinterpret_cast<const float4*>(g_h + idx);
        float4 hn;
        hn.x = uu.x*hh.x + (1.f-uu.x)*tanhf(q0.x + bb);
        hn.y = uu.y*hh.y + (1.f-uu.y)*tanhf(q0.y + bb);
        hn.z = uu.z*hh.z + (1.f-uu.z)*tanhf(q1.x + bb);
        hn.w = uu.w*hh.w + (1.f-uu.w)*tanhf(q1.y + bb);
        *reinterpret_cast<float4*>(g_h + idx) = hn;
    }
}

// ---------------- launch ----------------
extern "C" void kernel_launch(void* const* d_in, const int* in_sizes, int n_in,
                              void* d_out, int out_size) {
    int ix, imask, iadj, iWr, ibr, iWu, ibu, iWc, ibc, iWout, ibout;
    if (in_sizes[0] == 21120) {
        // alphabetical: Wc, Wout, Wr, Wu, adj, bc, bout, br, bu, mask, x
        iWc = 0; iWout = 1; iWr = 2; iWu = 3; iadj = 4; ibc = 5;
        ibout = 6; ibr = 7; ibu = 8; imask = 9; ix = 10;
    } else {
        // dict order: x, mask, adj, Wr, br, Wu, bu, Wc, bc, Wout, bout
        ix = 0; imask = 1; iadj = 2; iWr = 3; ibr = 4; iWu = 5;
        ibu = 6; iWc = 7; ibc = 8; iWout = 9; ibout = 10;
    }
    const float* x    = (const float*)d_in[ix];
    const void*  mask = d_in[imask];
    const float* adj  = (const float*)d_in[iadj];
    const float* Wr   = (const float*)d_in[iWr];
    const float* br   = (const float*)d_in[ibr];
    const float* Wu   = (const float*)d_in[iWu];
    const float* bu   = (const float*)d_in[ibu];
    const float* Wc   = (const float*)d_in[iWc];
    const float* bc   = (const float*)d_in[ibc];
    const float* Wout = (const float*)d_in[iWout];
    const float* bout = (const float*)d_in[ibout];
    float* out = (float*)d_out;

    cudaFuncSetAttribute(diff_mma_kernel,
                         cudaFuncAttributeMaxDynamicSharedMemorySize, DIFF_SMEM);

    detect_mask_kernel<<<1, 32>>>((const unsigned int*)mask);
    norm_kernel<<<Nn, 256>>>(adj);
    square_kernel<<<dim3(Nn/DBN, Nn/DBM, 2), 256>>>();
    conv_support_kernel<<<dim3(Nn*Nn/256, 4), 256>>>();
    zero_pad_kernel<<<dim3((M_PAD - M_DIFF)*Nn/256, 4), 256>>>();
    zero_h_kernel<<<(Bt*Hh*Nn + 255)/256, 256>>>();

    for (int t = 0; t < Tt; t++) {
        pre_kernel<<<dim3(Nn/128, Bt), 128>>>(x, mask, Wout, bout, out, t);
        diff_mma_kernel<<<dim3(8, 5, 4), 256, DIFF_SMEM>>>(0);
        gates_kernel<<<dim3(16, Bt, 2), 256>>>(Wr, br, Wu, bu);
        diff_mma_kernel<<<dim3(8, 5, 4), 256, DIFF_SMEM>>>(1);
        update_kernel<<<dim3(16, Bt), 256>>>(Wc, bc);
    }
}

// round 13
// speedup vs baseline: 3.2769x; 2.4122x over previous
#include <cuda_runtime.h>
#include <cuda_bf16.h>
#include <math.h>
#include <stdint.h>

#define Bt 8
#define Nn 1024
#define Hh 64
#define Tt 128
#define C1 66              // channels in xh = 2 + H
#define KC 330             // 5 * C1
#define M_DIFF (Bt*C1)     // 528
#define M_PAD 576          // padded A rows (9 tiles of 64)
#define BS (Bt*C1*Nn)      // one zc block: 540672 floats
#define PRED_SZ (Bt*Nn*Tt) // 1048576

#define BKk 32
#define PAD 68

// f32x2 square-GEMM tile
#define DBM 64
#define DBN 128
#define DBK 16
#define APAD 68
#define BPAD 132

// HMMA diffusion kernel layout: tile 64(M) x 128(N), 2-stage pipeline
#define SROW 40                        // 32 data + 8 pad bf16 (80B rows)
#define A_BUF (64*SROW*2)              // 5120 B
#define B_BUF (128*SROW*2)             // 10240 B
#define OFF_AHI 0
#define OFF_ALO A_BUF
#define OFF_BHI (2*A_BUF)
#define OFF_BLO (2*A_BUF + B_BUF)
#define STG (2*A_BUF + 2*B_BUF)        // 30720 B
#define DIFF_SMEM (2*STG)              // 61440 B

// ---------------- f32x2 packed-FMA helpers ----------------
__device__ __forceinline__ unsigned long long pack2(float v) {
    unsigned long long r;
    asm("mov.b64 %0, {%1, %1};" : "=l"(r) : "f"(v));
    return r;
}
__device__ __forceinline__ void ffma2(unsigned long long& d,
                                      unsigned long long a, unsigned long long b) {
    asm("fma.rn.f32x2 %0, %1, %2, %0;" : "+l"(d) : "l"(a), "l"(b));
}
__device__ __forceinline__ float2 unpack2(unsigned long long v) {
    float2 f;
    asm("mov.b64 {%0, %1}, %2;" : "=f"(f.x), "=f"(f.y) : "l"(v));
    return f;
}

// ---------------- HMMA helpers ----------------
__device__ __forceinline__ uint32_t smem_u32(const void* p) {
    uint32_t a;
    asm("{ .reg .u64 t; cvta.to.shared.u64 t, %1; cvt.u32.u64 %0, t; }" : "=r"(a) : "l"(p));
    return a;
}
__device__ __forceinline__ void ldsm4(uint32_t& r0, uint32_t& r1, uint32_t& r2, uint32_t& r3,
                                      uint32_t addr) {
    asm volatile("ldmatrix.sync.aligned.m8n8.x4.shared.b16 {%0,%1,%2,%3}, [%4];"
                 : "=r"(r0), "=r"(r1), "=r"(r2), "=r"(r3) : "r"(addr));
}
__device__ __forceinline__ void mma_bf16(float* c, const uint32_t* a, uint32_t b0, uint32_t b1) {
    asm volatile(
        "mma.sync.aligned.m16n8k16.row.col.f32.bf16.bf16.f32 "
        "{%0,%1,%2,%3}, {%4,%5,%6,%7}, {%8,%9}, {%0,%1,%2,%3};"
        : "+f"(c[0]), "+f"(c[1]), "+f"(c[2]), "+f"(c[3])
        : "r"(a[0]), "r"(a[1]), "r"(a[2]), "r"(a[3]), "r"(b0), "r"(b1));
}
__device__ __forceinline__ void cp16(uint32_t saddr, const void* gaddr) {
    asm volatile("cp.async.cg.shared.global [%0], [%1], 16;" :: "r"(saddr), "l"(gaddr));
}
#define CP_COMMIT() asm volatile("cp.async.commit_group;" ::: "memory")
#define CP_WAIT1()  asm volatile("cp.async.wait_group 1;" ::: "memory")

// ---------------- device globals (scratch; allocation-free) ----------------
__device__ float g_Sf [Nn*Nn];
__device__ float g_Sb [Nn*Nn];
__device__ float g_Sf2[Nn*Nn];
__device__ float g_Sb2[Nn*Nn];
__device__ float g_zc [5*BS];     // [k][b][c][n]; k=0 is z, k=1..4 diffused (fp32)
__device__ float g_zc2[BS];       // c-path input fp32
__device__ float g_h  [Bt*Hh*Nn];
__device__ float g_u  [Bt*Hh*Nn];
__device__ int   g_masktype;
__device__ __nv_bfloat16 g_zAhi[2][M_PAD*Nn];
__device__ __nv_bfloat16 g_zAlo[2][M_PAD*Nn];
__device__ __nv_bfloat16 g_SBhi[4][Nn*Nn];
__device__ __nv_bfloat16 g_SBlo[4][Nn*Nn];

__device__ __forceinline__ void split_store(float v, __nv_bfloat16* hi, __nv_bfloat16* lo,
                                            size_t idx) {
    __nv_bfloat16 h = __float2bfloat16(v);
    hi[idx] = h;
    lo[idx] = __float2bfloat16(v - __bfloat162float(h));
}

// ---------------- mask dtype sniffer ----------------
__global__ void detect_mask_kernel(const unsigned int* __restrict__ m) {
    if (threadIdx.x != 0 || blockIdx.x != 0) return;
    int byte_like = 0;
    for (int i = 0; i < 1024; i++) {
        unsigned int w = m[i];
        if (w == 0u || w == 1u || w == 0x3F800000u) continue;
        unsigned int b0 = w & 255u, b1 = (w >> 8) & 255u,
                     b2 = (w >> 16) & 255u, b3 = w >> 24;
        if (b0 <= 1u && b1 <= 1u && b2 <= 1u && b3 <= 1u) { byte_like = 1; break; }
    }
    g_masktype = byte_like ? 0 : 1;
}

// ---------------- support normalization ----------------
__global__ void norm_kernel(const float* __restrict__ adj) {
    int w = blockIdx.x;
    int tid = threadIdx.x;
    __shared__ float sred[256];
    float rs = 0.f, cs = 0.f;
    for (int v = tid; v < Nn; v += 256) {
        rs += adj[w*Nn + v];
        cs += adj[v*Nn + w];
    }
    sred[tid] = rs; __syncthreads();
    for (int s = 128; s > 0; s >>= 1) { if (tid < s) sred[tid] += sred[tid+s]; __syncthreads(); }
    float rsum = sred[0] + 1e-8f; __syncthreads();
    sred[tid] = cs; __syncthreads();
    for (int s = 128; s > 0; s >>= 1) { if (tid < s) sred[tid] += sred[tid+s]; __syncthreads(); }
    float csum = sred[0] + 1e-8f; __syncthreads();
    for (int v = tid; v < Nn; v += 256) {
        g_Sf[w*Nn + v] = adj[w*Nn + v] / rsum;
        g_Sb[w*Nn + v] = adj[v*Nn + w] / csum;
    }
}

// ---------------- f32x2 GEMM-NN (once for S^2) ----------------
__device__ __forceinline__ void gemm_nn_f32x2(const float* __restrict__ A,
                                              const float* __restrict__ B,
                                              float* __restrict__ C, int M)
{
    __shared__ float As[DBK][APAD];
    __shared__ float Bs[DBK][BPAD];
    const int tid  = threadIdx.x;
    const int row0 = blockIdx.y*DBM, col0 = blockIdx.x*DBN;
    const int am = tid >> 2, ak = (tid & 3) << 2;
    const int bk = tid >> 5, bn = (tid & 31) << 2;
    const int tx = tid & 15, ty = tid >> 4;

    unsigned long long acc[4][4];
    #pragma unroll
    for (int i = 0; i < 4; i++)
        #pragma unroll
        for (int p = 0; p < 4; p++) acc[i][p] = 0ULL;

    const bool arow_ok = (row0 + am) < M;
    const float* Aptr  = A + (size_t)(row0 + am)*Nn + ak;
    const float* Bptr0 = B + (size_t)bk*Nn + col0 + bn;
    const float* Bptr1 = B + (size_t)(bk + 8)*Nn + col0 + bn;

    float4 areg  = arow_ok ? *(const float4*)Aptr : make_float4(0.f,0.f,0.f,0.f);
    float4 breg0 = *(const float4*)Bptr0;
    float4 breg1 = *(const float4*)Bptr1;

    for (int k0 = 0; k0 < Nn; k0 += DBK) {
        As[ak+0][am] = areg.x; As[ak+1][am] = areg.y;
        As[ak+2][am] = areg.z; As[ak+3][am] = areg.w;
        *(float4*)&Bs[bk][bn]   = breg0;
        *(float4*)&Bs[bk+8][bn] = breg1;
        __syncthreads();
        if (k0 + DBK < Nn) {
            areg  = arow_ok ? *(const float4*)(Aptr + k0 + DBK) : make_float4(0.f,0.f,0.f,0.f);
            breg0 = *(const float4*)(Bptr0 + (size_t)(k0 + DBK)*Nn);
            breg1 = *(const float4*)(Bptr1 + (size_t)(k0 + DBK)*Nn);
        }
        #pragma unroll
        for (int kk = 0; kk < DBK; kk++) {
            float4 a4 = *(const float4*)&As[kk][ty << 2];
            ulonglong2 b01 = *(const ulonglong2*)&Bs[kk][tx << 2];
            ulonglong2 b23 = *(const ulonglong2*)&Bs[kk][64 + (tx << 2)];
            unsigned long long ap0 = pack2(a4.x), ap1 = pack2(a4.y),
                               ap2 = pack2(a4.z), ap3 = pack2(a4.w);
            ffma2(acc[0][0], ap0, b01.x); ffma2(acc[0][1], ap0, b01.y);
            ffma2(acc[0][2], ap0, b23.x); ffma2(acc[0][3], ap0, b23.y);
            ffma2(acc[1][0], ap1, b01.x); ffma2(acc[1][1], ap1, b01.y);
            ffma2(acc[1][2], ap1, b23.x); ffma2(acc[1][3], ap1, b23.y);
            ffma2(acc[2][0], ap2, b01.x); ffma2(acc[2][1], ap2, b01.y);
            ffma2(acc[2][2], ap2, b23.x); ffma2(acc[2][3], ap2, b23.y);
            ffma2(acc[3][0], ap3, b01.x); ffma2(acc[3][1], ap3, b01.y);
            ffma2(acc[3][2], ap3, b23.x); ffma2(acc[3][3], ap3, b23.y);
        }
        __syncthreads();
    }
    #pragma unroll
    for (int i = 0; i < 4; i++) {
        int m = row0 + (ty << 2) + i;
        if (m < M) {
            float2 p0 = unpack2(acc[i][0]), p1 = unpack2(acc[i][1]);
            float2 p2 = unpack2(acc[i][2]), p3 = unpack2(acc[i][3]);
            *(float4*)(C + (size_t)m*Nn + col0 + (tx << 2))
                = make_float4(p0.x, p0.y, p1.x, p1.y);
            *(float4*)(C + (size_t)m*Nn + col0 + 64 + (tx << 2))
                = make_float4(p2.x, p2.y, p3.x, p3.y);
        }
    }
}

__global__ __launch_bounds__(256) void square_kernel() {
    const float* S = blockIdx.z ? g_Sb : g_Sf;
    float*       D = blockIdx.z ? g_Sb2 : g_Sf2;
    gemm_nn_f32x2(S, S, D, Nn);
}

__global__ void conv_support_kernel() {
    int s = blockIdx.y;
    const float* src = (s == 0) ? g_Sf : (s == 1) ? g_Sf2 : (s == 2) ? g_Sb : g_Sb2;
    size_t i = (size_t)blockIdx.x*256 + threadIdx.x;
    split_store(src[i], g_SBhi[s], g_SBlo[s], i);
}

__global__ void zero_pad_kernel() {
    size_t i = (size_t)blockIdx.x*256 + threadIdx.x;   // < 48*1024
    int w = blockIdx.y;
    __nv_bfloat16 z = __float2bfloat16(0.f);
    size_t off = (size_t)M_DIFF*Nn + i;
    if (w == 0) g_zAhi[0][off] = z;
    else if (w == 1) g_zAlo[0][off] = z;
    else if (w == 2) g_zAhi[1][off] = z;
    else g_zAlo[1][off] = z;
}

__global__ void zero_h_kernel() {
    int i = blockIdx.x*256 + threadIdx.x;
    if (i < Bt*Hh*Nn) g_h[i] = 0.f;
}

// ---------------- HMMA diffusion: D[m][w] = sum_v A[m][v] * S[w][v] ----------------
// tile 64x128, grid (8 N-tiles, 9 M-tiles, 4 supports) = 288 CTAs, 256 threads,
// 8 warps of 32x32 tiles, bf16 3-pass split, cp.async 2-stage pipeline.
__global__ __launch_bounds__(256) void diff_mma_kernel(int set) {
    extern __shared__ char smem[];
    const uint32_t sb = smem_u32(smem);
    const int tid = threadIdx.x, wid = tid >> 5, lane = tid & 31;
    const int n0 = blockIdx.x*128, m0 = blockIdx.y*64, s = blockIdx.z;
    const int wm = (wid >> 2) << 5;    // 0/32
    const int wn = (wid & 3) << 5;     // 0,32,64,96

    const __nv_bfloat16* __restrict__ Ah = g_zAhi[set] + (size_t)m0*Nn;
    const __nv_bfloat16* __restrict__ Al = g_zAlo[set] + (size_t)m0*Nn;
    const __nv_bfloat16* __restrict__ Bh = g_SBhi[s]   + (size_t)n0*Nn;
    const __nv_bfloat16* __restrict__ Bl = g_SBlo[s]   + (size_t)n0*Nn;

    const int pr = tid >> 2, ps = (tid & 3) << 3;   // row 0..63, col seg*8

    float acc[2][4][4];
    #pragma unroll
    for (int mt = 0; mt < 2; mt++)
        #pragma unroll
        for (int nb = 0; nb < 4; nb++)
            #pragma unroll
            for (int q = 0; q < 4; q++) acc[mt][nb][q] = 0.f;

    // prologue: stage 0, stage 1
    #pragma unroll
    for (int st = 0; st < 2; st++) {
        int k0 = st*32;
        uint32_t so = sb + st*STG;
        uint32_t rb = (pr*SROW + ps)*2;
        cp16(so + OFF_AHI + rb, Ah + (size_t)pr*Nn + k0 + ps);
        cp16(so + OFF_ALO + rb, Al + (size_t)pr*Nn + k0 + ps);
        cp16(so + OFF_BHI + rb, Bh + (size_t)pr*Nn + k0 + ps);
        cp16(so + OFF_BHI + rb + 64*SROW*2, Bh + (size_t)(pr + 64)*Nn + k0 + ps);
        cp16(so + OFF_BLO + rb, Bl + (size_t)pr*Nn + k0 + ps);
        cp16(so + OFF_BLO + rb + 64*SROW*2, Bl + (size_t)(pr + 64)*Nn + k0 + ps);
        CP_COMMIT();
    }

    const int ar = lane & 15;
    const int ac = (lane >> 4) << 3;

    for (int c = 0; c < 32; c++) {
        const int st = c & 1;
        const uint32_t so = sb + st*STG;
        CP_WAIT1();
        __syncthreads();

        #pragma unroll
        for (int kk = 0; kk < 2; kk++) {
            const int k = kk << 4;
            uint32_t ah[2][4], al[2][4], bh[2][4], bl[2][4];
            #pragma unroll
            for (int mt = 0; mt < 2; mt++) {
                uint32_t off = ((wm + mt*16 + ar)*SROW + k + ac)*2;
                ldsm4(ah[mt][0], ah[mt][1], ah[mt][2], ah[mt][3], so + OFF_AHI + off);
                ldsm4(al[mt][0], al[mt][1], al[mt][2], al[mt][3], so + OFF_ALO + off);
            }
            #pragma unroll
            for (int nt = 0; nt < 2; nt++) {
                uint32_t off = ((wn + nt*16 + ar)*SROW + k + ac)*2;
                ldsm4(bh[nt][0], bh[nt][1], bh[nt][2], bh[nt][3], so + OFF_BHI + off);
                ldsm4(bl[nt][0], bl[nt][1], bl[nt][2], bl[nt][3], so + OFF_BLO + off);
            }
            #pragma unroll
            for (int mt = 0; mt < 2; mt++)
                #pragma unroll
                for (int nb = 0; nb < 4; nb++) {
                    int nt = nb >> 1, hf = nb & 1;
                    mma_bf16(acc[mt][nb], ah[mt], bh[nt][hf], bh[nt][2+hf]);
                    mma_bf16(acc[mt][nb], ah[mt], bl[nt][hf], bl[nt][2+hf]);
                    mma_bf16(acc[mt][nb], al[mt], bh[nt][hf], bh[nt][2+hf]);
                }
        }
        __syncthreads();
        if (c + 2 < 32) {
            int k0 = (c + 2)*32;
            uint32_t rb = (pr*SROW + ps)*2;
            cp16(so + OFF_AHI + rb, Ah + (size_t)pr*Nn + k0 + ps);
            cp16(so + OFF_ALO + rb, Al + (size_t)pr*Nn + k0 + ps);
            cp16(so + OFF_BHI + rb, Bh + (size_t)pr*Nn + k0 + ps);
            cp16(so + OFF_BHI + rb + 64*SROW*2, Bh + (size_t)(pr + 64)*Nn + k0 + ps);
            cp16(so + OFF_BLO + rb, Bl + (size_t)pr*Nn + k0 + ps);
            cp16(so + OFF_BLO + rb + 64*SROW*2, Bl + (size_t)(pr + 64)*Nn + k0 + ps);
        }
        CP_COMMIT();
    }

    // epilogue
    float* C = g_zc + (size_t)(s + 1)*BS;
    const int mr = lane >> 2, nc = (lane & 3) << 1;
    #pragma unroll
    for (int mt = 0; mt < 2; mt++) {
        #pragma unroll
        for (int nb = 0; nb < 4; nb++) {
            int m = m0 + wm + mt*16 + mr;
            int n = n0 + wn + nb*8 + nc;
            if (m < M_DIFF)
                *(float2*)(C + (size_t)m*Nn + n) = make_float2(acc[mt][nb][0], acc[mt][nb][1]);
            if (m + 8 < M_DIFF)
                *(float2*)(C + (size_t)(m + 8)*Nn + n) = make_float2(acc[mt][nb][2], acc[mt][nb][3]);
        }
    }
}

// ---------------- pre (t=0 only): x_hat, outputs, build z ----------------
__global__ __launch_bounds__(128) void pre_kernel(
    const float* __restrict__ x, const void* __restrict__ mask,
    const float* __restrict__ Wout, const float* __restrict__ bout,
    float* __restrict__ out, int t)
{
    int n = blockIdx.x*128 + threadIdx.x;
    int b = blockIdx.y;
    __shared__ float ws[Hh];
    if (threadIdx.x < Hh) ws[threadIdx.x] = Wout[threadIdx.x];
    __syncthreads();
    float acc = 0.f;
    #pragma unroll 4
    for (int hh = 0; hh < Hh; hh++) {
        float hv = g_h[((size_t)(b*Hh + hh))*Nn + n];
        acc += hv * ws[hh];
        size_t ridx = ((size_t)(b*C1 + 2 + hh))*Nn + n;
        g_zc[ridx] = hv;
        split_store(hv, g_zAhi[0], g_zAlo[0], ridx);
        out[PRED_SZ + (((size_t)(b*Hh + hh))*Nn + n)*Tt + t] = hv;
    }
    float xhat = acc + bout[0];
    out[((size_t)(b*Nn) + n)*Tt + t] = xhat;
    size_t xi = ((size_t)b*Nn + n)*Tt + t;
    float xv = x[xi];
    bool m;
    if (g_masktype == 0)
        m = ((const unsigned char*)mask)[xi] != 0;
    else
        m = ((const unsigned int*)mask)[xi] != 0u;
    float xin = m ? xv : xhat;
    float mf  = m ? 1.f : 0.f;
    size_t r0 = ((size_t)(b*C1) + 0)*Nn + n;
    size_t r1 = ((size_t)(b*C1) + 1)*Nn + n;
    g_zc[r0] = xin;  split_store(xin, g_zAhi[0], g_zAlo[0], r0);
    g_zc[r1] = mf;   split_store(mf,  g_zAhi[0], g_zAlo[0], r1);
}

// ---------------- fused gates r+u: single pass over zc ----------------
__global__ __launch_bounds__(256) void gates_kernel(
    const float* __restrict__ Wr, const float* __restrict__ br,
    const float* __restrict__ Wu, const float* __restrict__ bu)
{
    int b = blockIdx.y;
    int col0 = blockIdx.x*64;
    __shared__ float As[BKk*PAD];
    __shared__ float Au[BKk*PAD];
    __shared__ float Bs[BKk*PAD];
    int tid = threadIdx.x;
    int alr = tid >> 3, alc = (tid & 7) << 2;
    int blr = tid >> 4, blc = (tid & 15) << 2;
    int tx = tid & 15, ty = tid >> 4;
    unsigned long long accr[4][2], accu[4][2];
    #pragma unroll
    for (int i = 0; i < 4; i++) {
        accr[i][0] = 0ULL; accr[i][1] = 0ULL;
        accu[i][0] = 0ULL; accu[i][1] = 0ULL;
    }

    for (int k0 = 0; k0 < KC; k0 += BKk) {
        #pragma unroll
        for (int p = 0; p < 2; p++) {
            int o = alr + p*32;
            #pragma unroll
            for (int i = 0; i < 4; i++) {
                int kf = k0 + alc + i;
                As[(alc+i)*PAD + o] = (kf < KC) ? Wr[o*KC + kf] : 0.f;
                Au[(alc+i)*PAD + o] = (kf < KC) ? Wu[o*KC + kf] : 0.f;
            }
            int kf = k0 + blr + p*16;
            float4 bv = make_float4(0.f,0.f,0.f,0.f);
            if (kf < KC) {
                int kb = kf / C1, c = kf - kb*C1;
                const float* src = g_zc + ((size_t)((kb*Bt + b)*C1 + c))*Nn;
                bv = *reinterpret_cast<const float4*>(src + col0 + blc);
            }
            *reinterpret_cast<float4*>(&Bs[(blr + p*16)*PAD + blc]) = bv;
        }
        __syncthreads();
        #pragma unroll
        for (int kk = 0; kk < BKk; kk++) {
            float4 a  = *reinterpret_cast<const float4*>(&As[kk*PAD + (ty<<2)]);
            float4 au = *reinterpret_cast<const float4*>(&Au[kk*PAD + (ty<<2)]);
            ulonglong2 b2 = *reinterpret_cast<const ulonglong2*>(&Bs[kk*PAD + (tx<<2)]);
            unsigned long long ap0 = pack2(a.x), ap1 = pack2(a.y),
                               ap2 = pack2(a.z), ap3 = pack2(a.w);
            unsigned long long uq0 = pack2(au.x), uq1 = pack2(au.y),
                               uq2 = pack2(au.z), uq3 = pack2(au.w);
            ffma2(accr[0][0], ap0, b2.x); ffma2(accr[0][1], ap0, b2.y);
            ffma2(accr[1][0], ap1, b2.x); ffma2(accr[1][1], ap1, b2.y);
            ffma2(accr[2][0], ap2, b2.x); ffma2(accr[2][1], ap2, b2.y);
            ffma2(accr[3][0], ap3, b2.x); ffma2(accr[3][1], ap3, b2.y);
            ffma2(accu[0][0], uq0, b2.x); ffma2(accu[0][1], uq0, b2.y);
            ffma2(accu[1][0], uq1, b2.x); ffma2(accu[1][1], uq1, b2.y);
            ffma2(accu[2][0], uq2, b2.x); ffma2(accu[2][1], uq2, b2.y);
            ffma2(accu[3][0], uq3, b2.x); ffma2(accu[3][1], uq3, b2.y);
        }
        __syncthreads();
    }
    #pragma unroll
    for (int i = 0; i < 4; i++) {
        int o = (ty<<2) + i;
        int n = col0 + (tx<<2);
        size_t idx = ((size_t)(b*Hh + o))*Nn + n;
        float bbr = br[o], bbu = bu[o];
        float2 r0 = unpack2(accr[i][0]), r1 = unpack2(accr[i][1]);
        float2 u0 = unpack2(accu[i][0]), u1 = unpack2(accu[i][1]);
        float4 sr, su;
        sr.x = 1.f/(1.f + expf(-(r0.x + bbr)));
        sr.y = 1.f/(1.f + expf(-(r0.y + bbr)));
        sr.z = 1.f/(1.f + expf(-(r1.x + bbr)));
        sr.w = 1.f/(1.f + expf(-(r1.y + bbr)));
        su.x = 1.f/(1.f + expf(-(u0.x + bbu)));
        su.y = 1.f/(1.f + expf(-(u0.y + bbu)));
        su.z = 1.f/(1.f + expf(-(u1.x + bbu)));
        su.w = 1.f/(1.f + expf(-(u1.y + bbu)));
        float4 hv = *reinterpret_cast<const float4*>(g_h + idx);
        float4 rh = make_float4(sr.x*hv.x, sr.y*hv.y, sr.z*hv.z, sr.w*hv.w);
        size_t zi = ((size_t)(b*C1 + 2 + o))*Nn + n;
        *reinterpret_cast<float4*>(g_zc2 + zi) = rh;
        split_store(rh.x, g_zAhi[1], g_zAlo[1], zi + 0);
        split_store(rh.y, g_zAhi[1], g_zAlo[1], zi + 1);
        split_store(rh.z, g_zAhi[1], g_zAlo[1], zi + 2);
        split_store(rh.w, g_zAhi[1], g_zAlo[1], zi + 3);
        *reinterpret_cast<float4*>(g_u + idx) = su;
    }
    if (tid < 128) {   // copy inp channels (0,1) into zc2 (+ bf16)
        int ch = tid >> 6, n = col0 + (tid & 63);
        size_t zi = ((size_t)(b*C1 + ch))*Nn + n;
        float v = g_zc[zi];
        g_zc2[zi] = v;
        split_store(v, g_zAhi[1], g_zAlo[1], zi);
    }
}

// ---------------- fused update + pre(t+1) ----------------
__global__ __launch_bounds__(256) void update_kernel(
    const float* __restrict__ Wc, const float* __restrict__ bc,
    const float* __restrict__ x, const void* __restrict__ mask,
    const float* __restrict__ Wout, const float* __restrict__ bout,
    float* __restrict__ out, int t)
{
    int b = blockIdx.y;
    int col0 = blockIdx.x*64;
    __shared__ float As[BKk*PAD];
    __shared__ float Bs[BKk*PAD];
    __shared__ float hbuf[Hh*68];
    __shared__ float ws[Hh];
    __shared__ float xpart[4*64];
    int tid = threadIdx.x;
    if (tid < Hh) ws[tid] = Wout[tid];
    int alr = tid >> 3, alc = (tid & 7) << 2;
    int blr = tid >> 4, blc = (tid & 15) << 2;
    int tx = tid & 15, ty = tid >> 4;
    unsigned long long acc[4][2];
    #pragma unroll
    for (int i = 0; i < 4; i++) { acc[i][0] = 0ULL; acc[i][1] = 0ULL; }

    for (int k0 = 0; k0 < KC; k0 += BKk) {
        #pragma unroll
        for (int p = 0; p < 2; p++) {
            int o = alr + p*32;
            #pragma unroll
            for (int i = 0; i < 4; i++) {
                int kf = k0 + alc + i;
                As[(alc+i)*PAD + o] = (kf < KC) ? Wc[o*KC + kf] : 0.f;
            }
            int kf = k0 + blr + p*16;
            float4 bv = make_float4(0.f,0.f,0.f,0.f);
            if (kf < KC) {
                int kb = kf / C1, c = kf - kb*C1;
                const float* src = (kb == 0)
                    ? (g_zc2 + ((size_t)(b*C1 + c))*Nn)
                    : (g_zc  + ((size_t)((kb*Bt + b)*C1 + c))*Nn);
                bv = *reinterpret_cast<const float4*>(src + col0 + blc);
            }
            *reinterpret_cast<float4*>(&Bs[(blr + p*16)*PAD + blc]) = bv;
        }
        __syncthreads();
        #pragma unroll
        for (int kk = 0; kk < BKk; kk++) {
            float4 a = *reinterpret_cast<const float4*>(&As[kk*PAD + (ty<<2)]);
            ulonglong2 b2 = *reinterpret_cast<const ulonglong2*>(&Bs[kk*PAD + (tx<<2)]);
            unsigned long long ap0 = pack2(a.x), ap1 = pack2(a.y),
                               ap2 = pack2(a.z), ap3 = pack2(a.w);
            ffma2(acc[0][0], ap0, b2.x); ffma2(acc[0][1], ap0, b2.y);
            ffma2(acc[1][0], ap1, b2.x); ffma2(acc[1][1], ap1, b2.y);
            ffma2(acc[2][0], ap2, b2.x); ffma2(acc[2][1], ap2, b2.y);
            ffma2(acc[3][0], ap3, b2.x); ffma2(acc[3][1], ap3, b2.y);
        }
        __syncthreads();
    }
    #pragma unroll
    for (int i = 0; i < 4; i++) {
        int o = (ty<<2) + i;
        int nl = tx<<2;
        float bb = bc[o];
        size_t idx = ((size_t)(b*Hh + o))*Nn + col0 + nl;
        float2 q0 = unpack2(acc[i][0]), q1 = unpack2(acc[i][1]);
        float4 uu = *reinterpret_cast<const float4*>(g_u + idx);
        float4 hh = *reinterpret_cast<const float4*>(g_h + idx);
        float4 hn;
        hn.x = uu.x*hh.x + (1.f-uu.x)*tanhf(q0.x + bb);
        hn.y = uu.y*hh.y + (1.f-uu.y)*tanhf(q0.y + bb);
        hn.z = uu.z*hh.z + (1.f-uu.z)*tanhf(q1.x + bb);
        hn.w = uu.w*hh.w + (1.f-uu.w)*tanhf(q1.y + bb);
        *reinterpret_cast<float4*>(g_h + idx) = hn;
        hbuf[o*68 + nl + 0] = hn.x;
        hbuf[o*68 + nl + 1] = hn.y;
        hbuf[o*68 + nl + 2] = hn.z;
        hbuf[o*68 + nl + 3] = hn.w;
    }
    __syncthreads();

    // ---- fused pre for step t+1 ----
    if (t + 1 < Tt) {
        int tn = t + 1;
        int group = tid >> 6, nl = tid & 63, n = col0 + nl;
        float part = 0.f;
        #pragma unroll
        for (int oo = 0; oo < 16; oo++) {
            int o = group*16 + oo;
            float hv = hbuf[o*68 + nl];
            part += ws[o] * hv;
            out[PRED_SZ + (((size_t)(b*Hh + o))*Nn + n)*Tt + tn] = hv;
            size_t zi = ((size_t)(b*C1 + 2 + o))*Nn + n;
            g_zc[zi] = hv;
            split_store(hv, g_zAhi[0], g_zAlo[0], zi);
        }
        xpart[group*64 + nl] = part;
        __syncthreads();
        if (group == 0) {
            float xhat = xpart[nl] + xpart[64+nl] + xpart[128+nl] + xpart[192+nl] + bout[0];
            out[((size_t)(b*Nn) + n)*Tt + tn] = xhat;
            size_t xi = ((size_t)b*Nn + n)*Tt + tn;
            float xv = x[xi];
            bool m;
            if (g_masktype == 0)
                m = ((const unsigned char*)mask)[xi] != 0;
            else
                m = ((const unsigned int*)mask)[xi] != 0u;
            float xin = m ? xv : xhat;
            float mf  = m ? 1.f : 0.f;
            size_t r0 = ((size_t)(b*C1) + 0)*Nn + n;
            size_t r1 = ((size_t)(b*C1) + 1)*Nn + n;
            g_zc[r0] = xin;  split_store(xin, g_zAhi[0], g_zAlo[0], r0);
            g_zc[r1] = mf;   split_store(mf,  g_zAhi[0], g_zAlo[0], r1);
        }
    }
}

// ---------------- launch ----------------
extern "C" void kernel_launch(void* const* d_in, const int* in_sizes, int n_in,
                              void* d_out, int out_size) {
    int ix, imask, iadj, iWr, ibr, iWu, ibu, iWc, ibc, iWout, ibout;
    if (in_sizes[0] == 21120) {
        iWc = 0; iWout = 1; iWr = 2; iWu = 3; iadj = 4; ibc = 5;
        ibout = 6; ibr = 7; ibu = 8; imask = 9; ix = 10;
    } else {
        ix = 0; imask = 1; iadj = 2; iWr = 3; ibr = 4; iWu = 5;
        ibu = 6; iWc = 7; ibc = 8; iWout = 9; ibout = 10;
    }
    const float* x    = (const float*)d_in[ix];
    const void*  mask = d_in[imask];
    const float* adj  = (const float*)d_in[iadj];
    const float* Wr   = (const float*)d_in[iWr];
    const float* br   = (const float*)d_in[ibr];
    const float* Wu   = (const float*)d_in[iWu];
    const float* bu   = (const float*)d_in[ibu];
    const float* Wc   = (const float*)d_in[iWc];
    const float* bc   = (const float*)d_in[ibc];
    const float* Wout = (const float*)d_in[iWout];
    const float* bout = (const float*)d_in[ibout];
    float* out = (float*)d_out;

    cudaFuncSetAttribute(diff_mma_kernel,
                         cudaFuncAttributeMaxDynamicSharedMemorySize, DIFF_SMEM);

    detect_mask_kernel<<<1, 32>>>((const unsigned int*)mask);
    norm_kernel<<<Nn, 256>>>(adj);
    square_kernel<<<dim3(Nn/DBN, Nn/DBM, 2), 256>>>();
    conv_support_kernel<<<dim3(Nn*Nn/256, 4), 256>>>();
    zero_pad_kernel<<<dim3((M_PAD - M_DIFF)*Nn/256, 4), 256>>>();
    zero_h_kernel<<<(Bt*Hh*Nn + 255)/256, 256>>>();

    pre_kernel<<<dim3(Nn/128, Bt), 128>>>(x, mask, Wout, bout, out, 0);
    for (int t = 0; t < Tt; t++) {
        diff_mma_kernel<<<dim3(8, 9, 4), 256, DIFF_SMEM>>>(0);
        gates_kernel<<<dim3(16, Bt), 256>>>(Wr, br, Wu, bu);
        diff_mma_kernel<<<dim3(8, 9, 4), 256, DIFF_SMEM>>>(1);
        update_kernel<<<dim3(16, Bt), 256>>>(Wc, bc, x, mask, Wout, bout, out, t);
    }
}

// round 14
// speedup vs baseline: 3.5788x; 1.0921x over previous
#include <cuda_runtime.h>
#include <cuda_bf16.h>
#include <math.h>
#include <stdint.h>

#define Bt 8
#define Nn 1024
#define Hh 64
#define Tt 128
#define C1 66              // channels in xh = 2 + H
#define KC 330             // 5 * C1
#define KCP 352            // padded K for gate GEMMs (22 * 16)
#define ZBROW 352
#define M_DIFF (Bt*C1)     // 528
#define M_PAD 576          // padded diff A rows (9 tiles of 64)
#define PRED_SZ (Bt*Nn*Tt) // 1048576

// f32x2 square-GEMM tile
#define DBM 64
#define DBN 128
#define DBK 16
#define APAD 68
#define BPAD 132

// HMMA diffusion kernel layout: tile 64(M) x 128(N), 2-stage pipeline
#define SROW 40                        // 32 data + 8 pad bf16 (80B rows)
#define A_BUF (64*SROW*2)              // 5120 B
#define B_BUF (128*SROW*2)             // 10240 B
#define OFF_AHI 0
#define OFF_ALO A_BUF
#define OFF_BHI (2*A_BUF)
#define OFF_BLO (2*A_BUF + B_BUF)
#define STG (2*A_BUF + 2*B_BUF)        // 30720 B
#define DIFF_SMEM (2*STG)              // 61440 B

// gates/update HMMA layout: tile 64(M) x 128(N), K chunks of 32
#define GBROW 136                      // 128 data + 8 pad
#define GA_HI 0
#define GA_LO (64*SROW*2)              // 5120
#define GB_HI (2*64*SROW*2)            // 10240
#define GB_LO (GB_HI + 32*GBROW*2)     // 18944
#define GSTG  (GB_LO + 32*GBROW*2)     // 27648
#define GATES_SMEM (2*GSTG)            // 55296
#define NCH 11                         // 352/32 K chunks

// ---------------- helpers ----------------
__device__ __forceinline__ uint32_t smem_u32(const void* p) {
    uint32_t a;
    asm("{ .reg .u64 t; cvta.to.shared.u64 t, %1; cvt.u32.u64 %0, t; }" : "=r"(a) : "l"(p));
    return a;
}
__device__ __forceinline__ void ldsm4(uint32_t& r0, uint32_t& r1, uint32_t& r2, uint32_t& r3,
                                      uint32_t addr) {
    asm volatile("ldmatrix.sync.aligned.m8n8.x4.shared.b16 {%0,%1,%2,%3}, [%4];"
                 : "=r"(r0), "=r"(r1), "=r"(r2), "=r"(r3) : "r"(addr));
}
__device__ __forceinline__ void ldsm4t(uint32_t& r0, uint32_t& r1, uint32_t& r2, uint32_t& r3,
                                       uint32_t addr) {
    asm volatile("ldmatrix.sync.aligned.m8n8.x4.trans.shared.b16 {%0,%1,%2,%3}, [%4];"
                 : "=r"(r0), "=r"(r1), "=r"(r2), "=r"(r3) : "r"(addr));
}
__device__ __forceinline__ void mma_bf16(float* c, const uint32_t* a, uint32_t b0, uint32_t b1) {
    asm volatile(
        "mma.sync.aligned.m16n8k16.row.col.f32.bf16.bf16.f32 "
        "{%0,%1,%2,%3}, {%4,%5,%6,%7}, {%8,%9}, {%0,%1,%2,%3};"
        : "+f"(c[0]), "+f"(c[1]), "+f"(c[2]), "+f"(c[3])
        : "r"(a[0]), "r"(a[1]), "r"(a[2]), "r"(a[3]), "r"(b0), "r"(b1));
}
__device__ __forceinline__ void cp16(uint32_t saddr, const void* gaddr) {
    asm volatile("cp.async.cg.shared.global [%0], [%1], 16;" :: "r"(saddr), "l"(gaddr));
}
#define CP_COMMIT() asm volatile("cp.async.commit_group;" ::: "memory")
#define CP_WAIT1()  asm volatile("cp.async.wait_group 1;" ::: "memory")

// f32x2 (for the one-time S^2 GEMM)
__device__ __forceinline__ unsigned long long pack2(float v) {
    unsigned long long r;
    asm("mov.b64 %0, {%1, %1};" : "=l"(r) : "f"(v));
    return r;
}
__device__ __forceinline__ void ffma2(unsigned long long& d,
                                      unsigned long long a, unsigned long long b) {
    asm("fma.rn.f32x2 %0, %1, %2, %0;" : "+l"(d) : "l"(a), "l"(b));
}
__device__ __forceinline__ float2 unpack2(unsigned long long v) {
    float2 f;
    asm("mov.b64 {%0, %1}, %2;" : "=f"(f.x), "=f"(f.y) : "l"(v));
    return f;
}

// ---------------- device globals ----------------
__device__ float g_Sf [Nn*Nn];
__device__ float g_Sb [Nn*Nn];
__device__ float g_Sf2[Nn*Nn];
__device__ float g_Sb2[Nn*Nn];
__device__ float g_h  [Bt*Hh*Nn];
__device__ float g_u  [Bt*Hh*Nn];
__device__ int   g_masktype;
__device__ __nv_bfloat16 g_zAhi[2][M_PAD*Nn];     // diff A operand (hi)
__device__ __nv_bfloat16 g_zAlo[2][M_PAD*Nn];
__device__ __nv_bfloat16 g_SBhi[4][Nn*Nn];        // supports (hi)
__device__ __nv_bfloat16 g_SBlo[4][Nn*Nn];
__device__ __nv_bfloat16 g_zbh[2*Bt*ZBROW*Nn];    // gates B operand [set][b][352][1024]
__device__ __nv_bfloat16 g_zbl[2*Bt*ZBROW*Nn];
__device__ __nv_bfloat16 g_Wgh[2][Hh*KCP];        // Wr, Wu splits
__device__ __nv_bfloat16 g_Wgl[2][Hh*KCP];
__device__ __nv_bfloat16 g_Wch[Hh*KCP];           // Wc split
__device__ __nv_bfloat16 g_Wcl[Hh*KCP];

__device__ __forceinline__ void split_store(float v, __nv_bfloat16* hi, __nv_bfloat16* lo,
                                            size_t idx) {
    __nv_bfloat16 h = __float2bfloat16(v);
    hi[idx] = h;
    lo[idx] = __float2bfloat16(v - __bfloat162float(h));
}
// split a pair (n, n+1) into packed u32 hi/lo words
__device__ __forceinline__ void split2(float v0, float v1, uint32_t& hi, uint32_t& lo) {
    __nv_bfloat16 h0 = __float2bfloat16(v0), h1 = __float2bfloat16(v1);
    float l0 = v0 - __bfloat162float(h0), l1 = v1 - __bfloat162float(h1);
    hi = (uint32_t)__bfloat16_as_ushort(h0) | ((uint32_t)__bfloat16_as_ushort(h1) << 16);
    lo = (uint32_t)__bfloat16_as_ushort(__float2bfloat16(l0))
       | ((uint32_t)__bfloat16_as_ushort(__float2bfloat16(l1)) << 16);
}

// ---------------- mask dtype sniffer ----------------
__global__ void detect_mask_kernel(const unsigned int* __restrict__ m) {
    if (threadIdx.x != 0 || blockIdx.x != 0) return;
    int byte_like = 0;
    for (int i = 0; i < 1024; i++) {
        unsigned int w = m[i];
        if (w == 0u || w == 1u || w == 0x3F800000u) continue;
        unsigned int b0 = w & 255u, b1 = (w >> 8) & 255u,
                     b2 = (w >> 16) & 255u, b3 = w >> 24;
        if (b0 <= 1u && b1 <= 1u && b2 <= 1u && b3 <= 1u) { byte_like = 1; break; }
    }
    g_masktype = byte_like ? 0 : 1;
}

// ---------------- support normalization ----------------
__global__ void norm_kernel(const float* __restrict__ adj) {
    int w = blockIdx.x;
    int tid = threadIdx.x;
    __shared__ float sred[256];
    float rs = 0.f, cs = 0.f;
    for (int v = tid; v < Nn; v += 256) {
        rs += adj[w*Nn + v];
        cs += adj[v*Nn + w];
    }
    sred[tid] = rs; __syncthreads();
    for (int s = 128; s > 0; s >>= 1) { if (tid < s) sred[tid] += sred[tid+s]; __syncthreads(); }
    float rsum = sred[0] + 1e-8f; __syncthreads();
    sred[tid] = cs; __syncthreads();
    for (int s = 128; s > 0; s >>= 1) { if (tid < s) sred[tid] += sred[tid+s]; __syncthreads(); }
    float csum = sred[0] + 1e-8f; __syncthreads();
    for (int v = tid; v < Nn; v += 256) {
        g_Sf[w*Nn + v] = adj[w*Nn + v] / rsum;
        g_Sb[w*Nn + v] = adj[v*Nn + w] / csum;
    }
}

// ---------------- f32x2 GEMM (once, for S^2) ----------------
__device__ __forceinline__ void gemm_nn_f32x2(const float* __restrict__ A,
                                              const float* __restrict__ B,
                                              float* __restrict__ C, int M)
{
    __shared__ float As[DBK][APAD];
    __shared__ float Bs[DBK][BPAD];
    const int tid  = threadIdx.x;
    const int row0 = blockIdx.y*DBM, col0 = blockIdx.x*DBN;
    const int am = tid >> 2, ak = (tid & 3) << 2;
    const int bk = tid >> 5, bn = (tid & 31) << 2;
    const int tx = tid & 15, ty = tid >> 4;

    unsigned long long acc[4][4];
    #pragma unroll
    for (int i = 0; i < 4; i++)
        #pragma unroll
        for (int p = 0; p < 4; p++) acc[i][p] = 0ULL;

    const bool arow_ok = (row0 + am) < M;
    const float* Aptr  = A + (size_t)(row0 + am)*Nn + ak;
    const float* Bptr0 = B + (size_t)bk*Nn + col0 + bn;
    const float* Bptr1 = B + (size_t)(bk + 8)*Nn + col0 + bn;

    float4 areg  = arow_ok ? *(const float4*)Aptr : make_float4(0.f,0.f,0.f,0.f);
    float4 breg0 = *(const float4*)Bptr0;
    float4 breg1 = *(const float4*)Bptr1;

    for (int k0 = 0; k0 < Nn; k0 += DBK) {
        As[ak+0][am] = areg.x; As[ak+1][am] = areg.y;
        As[ak+2][am] = areg.z; As[ak+3][am] = areg.w;
        *(float4*)&Bs[bk][bn]   = breg0;
        *(float4*)&Bs[bk+8][bn] = breg1;
        __syncthreads();
        if (k0 + DBK < Nn) {
            areg  = arow_ok ? *(const float4*)(Aptr + k0 + DBK) : make_float4(0.f,0.f,0.f,0.f);
            breg0 = *(const float4*)(Bptr0 + (size_t)(k0 + DBK)*Nn);
            breg1 = *(const float4*)(Bptr1 + (size_t)(k0 + DBK)*Nn);
        }
        #pragma unroll
        for (int kk = 0; kk < DBK; kk++) {
            float4 a4 = *(const float4*)&As[kk][ty << 2];
            ulonglong2 b01 = *(const ulonglong2*)&Bs[kk][tx << 2];
            ulonglong2 b23 = *(const ulonglong2*)&Bs[kk][64 + (tx << 2)];
            unsigned long long ap0 = pack2(a4.x), ap1 = pack2(a4.y),
                               ap2 = pack2(a4.z), ap3 = pack2(a4.w);
            ffma2(acc[0][0], ap0, b01.x); ffma2(acc[0][1], ap0, b01.y);
            ffma2(acc[0][2], ap0, b23.x); ffma2(acc[0][3], ap0, b23.y);
            ffma2(acc[1][0], ap1, b01.x); ffma2(acc[1][1], ap1, b01.y);
            ffma2(acc[1][2], ap1, b23.x); ffma2(acc[1][3], ap1, b23.y);
            ffma2(acc[2][0], ap2, b01.x); ffma2(acc[2][1], ap2, b01.y);
            ffma2(acc[2][2], ap2, b23.x); ffma2(acc[2][3], ap2, b23.y);
            ffma2(acc[3][0], ap3, b01.x); ffma2(acc[3][1], ap3, b01.y);
            ffma2(acc[3][2], ap3, b23.x); ffma2(acc[3][3], ap3, b23.y);
        }
        __syncthreads();
    }
    #pragma unroll
    for (int i = 0; i < 4; i++) {
        int m = row0 + (ty << 2) + i;
        if (m < M) {
            float2 p0 = unpack2(acc[i][0]), p1 = unpack2(acc[i][1]);
            float2 p2 = unpack2(acc[i][2]), p3 = unpack2(acc[i][3]);
            *(float4*)(C + (size_t)m*Nn + col0 + (tx << 2))
                = make_float4(p0.x, p0.y, p1.x, p1.y);
            *(float4*)(C + (size_t)m*Nn + col0 + 64 + (tx << 2))
                = make_float4(p2.x, p2.y, p3.x, p3.y);
        }
    }
}

__global__ __launch_bounds__(256) void square_kernel() {
    const float* S = blockIdx.z ? g_Sb : g_Sf;
    float*       D = blockIdx.z ? g_Sb2 : g_Sf2;
    gemm_nn_f32x2(S, S, D, Nn);
}

__global__ void conv_support_kernel() {
    int s = blockIdx.y;
    const float* src = (s == 0) ? g_Sf : (s == 1) ? g_Sf2 : (s == 2) ? g_Sb : g_Sb2;
    size_t i = (size_t)blockIdx.x*256 + threadIdx.x;
    split_store(src[i], g_SBhi[s], g_SBlo[s], i);
}

// weights -> bf16 hi/lo, K padded 330 -> 352
__global__ void conv_w_kernel(const float* __restrict__ Wr,
                              const float* __restrict__ Wu,
                              const float* __restrict__ Wc) {
    int wsel = blockIdx.y;
    int idx = blockIdx.x*256 + threadIdx.x;     // < 64*352
    if (idx >= Hh*KCP) return;
    int o = idx / KCP, kf = idx % KCP;
    const float* W = (wsel == 0) ? Wr : (wsel == 1) ? Wu : Wc;
    float v = (kf < KC) ? W[o*KC + kf] : 0.f;
    if (wsel < 2) split_store(v, g_Wgh[wsel], g_Wgl[wsel], idx);
    else          split_store(v, g_Wch, g_Wcl, idx);
}

__global__ void zero_pad_kernel() {                 // zA rows [528,576)
    size_t i = (size_t)blockIdx.x*256 + threadIdx.x;
    int w = blockIdx.y;
    __nv_bfloat16 z = __float2bfloat16(0.f);
    size_t off = (size_t)M_DIFF*Nn + i;
    if (w == 0) g_zAhi[0][off] = z;
    else if (w == 1) g_zAlo[0][off] = z;
    else if (w == 2) g_zAhi[1][off] = z;
    else g_zAlo[1][off] = z;
}

__global__ void zero_zb_pad_kernel() {              // zb rows [330,352) all sets/batches
    int idx = blockIdx.x*256 + threadIdx.x;         // < 16*22*1024
    int sb = idx / (22*1024);
    int rem = idx % (22*1024);
    int row = 330 + rem / 1024, n = rem % 1024;
    size_t a = ((size_t)sb*ZBROW + row)*Nn + n;
    __nv_bfloat16 z = __float2bfloat16(0.f);
    g_zbh[a] = z; g_zbl[a] = z;
}

__global__ void zero_h_kernel() {
    int i = blockIdx.x*256 + threadIdx.x;
    if (i < Bt*Hh*Nn) g_h[i] = 0.f;
}

// ---------------- HMMA diffusion: writes bf16 hi/lo into g_zb ----------------
__global__ __launch_bounds__(256) void diff_mma_kernel(int set) {
    extern __shared__ char smem[];
    const uint32_t sb = smem_u32(smem);
    const int tid = threadIdx.x, wid = tid >> 5, lane = tid & 31;
    const int n0 = blockIdx.x*128, m0 = blockIdx.y*64, s = blockIdx.z;
    const int wm = (wid >> 2) << 5;
    const int wn = (wid & 3) << 5;

    const __nv_bfloat16* __restrict__ Ah = g_zAhi[set] + (size_t)m0*Nn;
    const __nv_bfloat16* __restrict__ Al = g_zAlo[set] + (size_t)m0*Nn;
    const __nv_bfloat16* __restrict__ Bh = g_SBhi[s]   + (size_t)n0*Nn;
    const __nv_bfloat16* __restrict__ Bl = g_SBlo[s]   + (size_t)n0*Nn;

    const int pr = tid >> 2, ps = (tid & 3) << 3;

    float acc[2][4][4];
    #pragma unroll
    for (int mt = 0; mt < 2; mt++)
        #pragma unroll
        for (int nb = 0; nb < 4; nb++)
            #pragma unroll
            for (int q = 0; q < 4; q++) acc[mt][nb][q] = 0.f;

    #pragma unroll
    for (int st = 0; st < 2; st++) {
        int k0 = st*32;
        uint32_t so = sb + st*STG;
        uint32_t rb = (pr*SROW + ps)*2;
        cp16(so + OFF_AHI + rb, Ah + (size_t)pr*Nn + k0 + ps);
        cp16(so + OFF_ALO + rb, Al + (size_t)pr*Nn + k0 + ps);
        cp16(so + OFF_BHI + rb, Bh + (size_t)pr*Nn + k0 + ps);
        cp16(so + OFF_BHI + rb + 64*SROW*2, Bh + (size_t)(pr + 64)*Nn + k0 + ps);
        cp16(so + OFF_BLO + rb, Bl + (size_t)pr*Nn + k0 + ps);
        cp16(so + OFF_BLO + rb + 64*SROW*2, Bl + (size_t)(pr + 64)*Nn + k0 + ps);
        CP_COMMIT();
    }

    const int ar = lane & 15;
    const int ac = (lane >> 4) << 3;

    for (int c = 0; c < 32; c++) {
        const int st = c & 1;
        const uint32_t so = sb + st*STG;
        CP_WAIT1();
        __syncthreads();

        #pragma unroll
        for (int kk = 0; kk < 2; kk++) {
            const int k = kk << 4;
            uint32_t ah[2][4], al[2][4], bh[2][4], bl[2][4];
            #pragma unroll
            for (int mt = 0; mt < 2; mt++) {
                uint32_t off = ((wm + mt*16 + ar)*SROW + k + ac)*2;
                ldsm4(ah[mt][0], ah[mt][1], ah[mt][2], ah[mt][3], so + OFF_AHI + off);
                ldsm4(al[mt][0], al[mt][1], al[mt][2], al[mt][3], so + OFF_ALO + off);
            }
            #pragma unroll
            for (int nt = 0; nt < 2; nt++) {
                uint32_t off = ((wn + nt*16 + ar)*SROW + k + ac)*2;
                ldsm4(bh[nt][0], bh[nt][1], bh[nt][2], bh[nt][3], so + OFF_BHI + off);
                ldsm4(bl[nt][0], bl[nt][1], bl[nt][2], bl[nt][3], so + OFF_BLO + off);
            }
            #pragma unroll
            for (int mt = 0; mt < 2; mt++)
                #pragma unroll
                for (int nb = 0; nb < 4; nb++) {
                    int nt = nb >> 1, hf = nb & 1;
                    mma_bf16(acc[mt][nb], ah[mt], bh[nt][hf], bh[nt][2+hf]);
                    mma_bf16(acc[mt][nb], ah[mt], bl[nt][hf], bl[nt][2+hf]);
                    mma_bf16(acc[mt][nb], al[mt], bh[nt][hf], bh[nt][2+hf]);
                }
        }
        __syncthreads();
        if (c + 2 < 32) {
            int k0 = (c + 2)*32;
            uint32_t rb = (pr*SROW + ps)*2;
            cp16(so + OFF_AHI + rb, Ah + (size_t)pr*Nn + k0 + ps);
            cp16(so + OFF_ALO + rb, Al + (size_t)pr*Nn + k0 + ps);
            cp16(so + OFF_BHI + rb, Bh + (size_t)pr*Nn + k0 + ps);
            cp16(so + OFF_BHI + rb + 64*SROW*2, Bh + (size_t)(pr + 64)*Nn + k0 + ps);
            cp16(so + OFF_BLO + rb, Bl + (size_t)pr*Nn + k0 + ps);
            cp16(so + OFF_BLO + rb + 64*SROW*2, Bl + (size_t)(pr + 64)*Nn + k0 + ps);
        }
        CP_COMMIT();
    }

    // epilogue: split fp32 acc into bf16 hi/lo rows of g_zb[set]
    const int mr = lane >> 2, nc = (lane & 3) << 1;
    #pragma unroll
    for (int mt = 0; mt < 2; mt++) {
        #pragma unroll
        for (int nb = 0; nb < 4; nb++) {
            int n = n0 + wn + nb*8 + nc;
            int m = m0 + wm + mt*16 + mr;
            #pragma unroll
            for (int hv = 0; hv < 2; hv++) {
                int mm = m + hv*8;
                if (mm < M_DIFF) {
                    int bb = mm / C1, cc = mm - bb*C1;
                    size_t a = (((size_t)(set*Bt + bb))*ZBROW + (s+1)*C1 + cc)*Nn + n;
                    uint32_t hi, lo;
                    split2(acc[mt][nb][hv*2], acc[mt][nb][hv*2+1], hi, lo);
                    *(uint32_t*)((char*)g_zbh + a*2) = hi;
                    *(uint32_t*)((char*)g_zbl + a*2) = lo;
                }
            }
        }
    }
}

// ---------------- gates r+u on HMMA: grid (8 n-tiles, 2 gates, 8 b) ----------------
__global__ __launch_bounds__(256) void gates_mma_kernel(
    const float* __restrict__ br, const float* __restrict__ bu)
{
    extern __shared__ char smem[];
    const uint32_t sb = smem_u32(smem);
    const int tid = threadIdx.x, wid = tid >> 5, lane = tid & 31;
    const int n0 = blockIdx.x*128, gate = blockIdx.y, b = blockIdx.z;
    const int wm = (wid >> 2) << 5;
    const int wn = (wid & 3) << 5;

    const __nv_bfloat16* __restrict__ Ah = g_Wgh[gate];
    const __nv_bfloat16* __restrict__ Al = g_Wgl[gate];
    const __nv_bfloat16* __restrict__ Bhp = g_zbh + (size_t)b*ZBROW*Nn;   // set 0
    const __nv_bfloat16* __restrict__ Blp = g_zbl + (size_t)b*ZBROW*Nn;

    const int ra = tid >> 2, sa = (tid & 3) << 3;        // A: 64 rows x 32 k
    float acc[2][4][4];
    #pragma unroll
    for (int mt = 0; mt < 2; mt++)
        #pragma unroll
        for (int nb = 0; nb < 4; nb++)
            #pragma unroll
            for (int q = 0; q < 4; q++) acc[mt][nb][q] = 0.f;

    #pragma unroll
    for (int st = 0; st < 2; st++) {
        int k0 = st*32;
        uint32_t so = sb + st*GSTG;
        cp16(so + GA_HI + (ra*SROW + sa)*2, Ah + (size_t)ra*KCP + k0 + sa);
        cp16(so + GA_LO + (ra*SROW + sa)*2, Al + (size_t)ra*KCP + k0 + sa);
        #pragma unroll
        for (int q = 0; q < 2; q++) {
            int idx = q*256 + tid;
            int rb = idx >> 4, sg = (idx & 15) << 3;
            cp16(so + GB_HI + (rb*GBROW + sg)*2, Bhp + (size_t)(k0 + rb)*Nn + n0 + sg);
            cp16(so + GB_LO + (rb*GBROW + sg)*2, Blp + (size_t)(k0 + rb)*Nn + n0 + sg);
        }
        CP_COMMIT();
    }

    const int ar = lane & 15;
    const int ac = (lane >> 4) << 3;

    for (int c = 0; c < NCH; c++) {
        const int st = c & 1;
        const uint32_t so = sb + st*GSTG;
        CP_WAIT1();
        __syncthreads();

        #pragma unroll
        for (int kk = 0; kk < 2; kk++) {
            const int k = kk << 4;
            uint32_t ah[2][4], al[2][4], bh[2][4], bl[2][4];
            #pragma unroll
            for (int mt = 0; mt < 2; mt++) {
                uint32_t off = ((wm + mt*16 + ar)*SROW + k + ac)*2;
                ldsm4(ah[mt][0], ah[mt][1], ah[mt][2], ah[mt][3], so + GA_HI + off);
                ldsm4(al[mt][0], al[mt][1], al[mt][2], al[mt][3], so + GA_LO + off);
            }
            #pragma unroll
            for (int nt = 0; nt < 2; nt++) {
                uint32_t off = ((k + ar)*GBROW + wn + nt*16 + ac)*2;
                ldsm4t(bh[nt][0], bh[nt][1], bh[nt][2], bh[nt][3], so + GB_HI + off);
                ldsm4t(bl[nt][0], bl[nt][1], bl[nt][2], bl[nt][3], so + GB_LO + off);
            }
            #pragma unroll
            for (int mt = 0; mt < 2; mt++)
                #pragma unroll
                for (int nb = 0; nb < 4; nb++) {
                    int nt = nb >> 1, p = (nb & 1) << 1;
                    mma_bf16(acc[mt][nb], ah[mt], bh[nt][p], bh[nt][p+1]);
                    mma_bf16(acc[mt][nb], ah[mt], bl[nt][p], bl[nt][p+1]);
                    mma_bf16(acc[mt][nb], al[mt], bh[nt][p], bh[nt][p+1]);
                }
        }
        __syncthreads();
        if (c + 2 < NCH) {
            int k0 = (c + 2)*32;
            cp16(so + GA_HI + (ra*SROW + sa)*2, Ah + (size_t)ra*KCP + k0 + sa);
            cp16(so + GA_LO + (ra*SROW + sa)*2, Al + (size_t)ra*KCP + k0 + sa);
            #pragma unroll
            for (int q = 0; q < 2; q++) {
                int idx = q*256 + tid;
                int rb = idx >> 4, sg = (idx & 15) << 3;
                cp16(so + GB_HI + (rb*GBROW + sg)*2, Bhp + (size_t)(k0 + rb)*Nn + n0 + sg);
                cp16(so + GB_LO + (rb*GBROW + sg)*2, Blp + (size_t)(k0 + rb)*Nn + n0 + sg);
            }
        }
        CP_COMMIT();
    }

    // epilogue
    const int mr = lane >> 2, nc = (lane & 3) << 1;
    const float* bias = gate ? bu : br;
    #pragma unroll
    for (int mt = 0; mt < 2; mt++) {
        #pragma unroll
        for (int nb = 0; nb < 4; nb++) {
            int n = n0 + wn + nb*8 + nc;
            #pragma unroll
            for (int hv = 0; hv < 2; hv++) {
                int o = wm + mt*16 + mr + hv*8;
                float bb = bias[o];
                float s0 = 1.f/(1.f + expf(-(acc[mt][nb][hv*2]   + bb)));
                float s1 = 1.f/(1.f + expf(-(acc[mt][nb][hv*2+1] + bb)));
                size_t hidx = ((size_t)(b*Hh + o))*Nn + n;
                if (gate == 0) {
                    float2 hvv = *(const float2*)(g_h + hidx);
                    float r0 = s0*hvv.x, r1 = s1*hvv.y;
                    uint32_t hi, lo;
                    split2(r0, r1, hi, lo);
                    size_t za = ((size_t)(b*C1 + 2 + o))*Nn + n;            // zA[1]
                    *(uint32_t*)((char*)&g_zAhi[1][0] + za*2) = hi;
                    *(uint32_t*)((char*)&g_zAlo[1][0] + za*2) = lo;
                    size_t zb = (((size_t)(Bt + b))*ZBROW + 2 + o)*Nn + n;  // zb set 1
                    *(uint32_t*)((char*)g_zbh + zb*2) = hi;
                    *(uint32_t*)((char*)g_zbl + zb*2) = lo;
                } else {
                    *(float2*)(g_u + hidx) = make_float2(s0, s1);
                }
            }
        }
    }
    if (gate == 0) {  // copy rows 0,1 (x_in, mask) set0 -> set1 + zA[1]
        int row = tid >> 7, nl = tid & 127, n = n0 + nl;
        size_t src = ((size_t)b*ZBROW + row)*Nn + n;
        __nv_bfloat16 vh = g_zbh[src], vl = g_zbl[src];
        size_t dst = (((size_t)(Bt + b))*ZBROW + row)*Nn + n;
        g_zbh[dst] = vh; g_zbl[dst] = vl;
        size_t za = ((size_t)(b*C1 + row))*Nn + n;
        g_zAhi[1][za] = vh; g_zAlo[1][za] = vl;
    }
}

// ---------------- update on HMMA + fused pre(t+1): grid (8 n-tiles, 8 b) ----------------
__global__ __launch_bounds__(256) void update_mma_kernel(
    const float* __restrict__ bc,
    const float* __restrict__ x, const void* __restrict__ mask,
    const float* __restrict__ Wout, const float* __restrict__ bout,
    float* __restrict__ out, int t)
{
    extern __shared__ char smem[];
    const uint32_t sb = smem_u32(smem);
    const int tid = threadIdx.x, wid = tid >> 5, lane = tid & 31;
    const int n0 = blockIdx.x*128, b = blockIdx.y;
    const int wm = (wid >> 2) << 5;
    const int wn = (wid & 3) << 5;
    __shared__ float ws[Hh];
    __shared__ float xpart[2*128];
    if (tid < Hh) ws[tid] = Wout[tid];

    const __nv_bfloat16* __restrict__ Bhp = g_zbh + ((size_t)(Bt + b))*ZBROW*Nn;  // set 1
    const __nv_bfloat16* __restrict__ Blp = g_zbl + ((size_t)(Bt + b))*ZBROW*Nn;

    const int ra = tid >> 2, sa = (tid & 3) << 3;
    float acc[2][4][4];
    #pragma unroll
    for (int mt = 0; mt < 2; mt++)
        #pragma unroll
        for (int nb = 0; nb < 4; nb++)
            #pragma unroll
            for (int q = 0; q < 4; q++) acc[mt][nb][q] = 0.f;

    #pragma unroll
    for (int st = 0; st < 2; st++) {
        int k0 = st*32;
        uint32_t so = sb + st*GSTG;
        cp16(so + GA_HI + (ra*SROW + sa)*2, g_Wch + (size_t)ra*KCP + k0 + sa);
        cp16(so + GA_LO + (ra*SROW + sa)*2, g_Wcl + (size_t)ra*KCP + k0 + sa);
        #pragma unroll
        for (int q = 0; q < 2; q++) {
            int idx = q*256 + tid;
            int rb = idx >> 4, sg = (idx & 15) << 3;
            cp16(so + GB_HI + (rb*GBROW + sg)*2, Bhp + (size_t)(k0 + rb)*Nn + n0 + sg);
            cp16(so + GB_LO + (rb*GBROW + sg)*2, Blp + (size_t)(k0 + rb)*Nn + n0 + sg);
        }
        CP_COMMIT();
    }

    const int ar = lane & 15;
    const int ac = (lane >> 4) << 3;

    for (int c = 0; c < NCH; c++) {
        const int st = c & 1;
        const uint32_t so = sb + st*GSTG;
        CP_WAIT1();
        __syncthreads();

        #pragma unroll
        for (int kk = 0; kk < 2; kk++) {
            const int k = kk << 4;
            uint32_t ah[2][4], al[2][4], bh[2][4], bl[2][4];
            #pragma unroll
            for (int mt = 0; mt < 2; mt++) {
                uint32_t off = ((wm + mt*16 + ar)*SROW + k + ac)*2;
                ldsm4(ah[mt][0], ah[mt][1], ah[mt][2], ah[mt][3], so + GA_HI + off);
                ldsm4(al[mt][0], al[mt][1], al[mt][2], al[mt][3], so + GA_LO + off);
            }
            #pragma unroll
            for (int nt = 0; nt < 2; nt++) {
                uint32_t off = ((k + ar)*GBROW + wn + nt*16 + ac)*2;
                ldsm4t(bh[nt][0], bh[nt][1], bh[nt][2], bh[nt][3], so + GB_HI + off);
                ldsm4t(bl[nt][0], bl[nt][1], bl[nt][2], bl[nt][3], so + GB_LO + off);
            }
            #pragma unroll
            for (int mt = 0; mt < 2; mt++)
                #pragma unroll
                for (int nb = 0; nb < 4; nb++) {
                    int nt = nb >> 1, p = (nb & 1) << 1;
                    mma_bf16(acc[mt][nb], ah[mt], bh[nt][p], bh[nt][p+1]);
                    mma_bf16(acc[mt][nb], ah[mt], bl[nt][p], bl[nt][p+1]);
                    mma_bf16(acc[mt][nb], al[mt], bh[nt][p], bh[nt][p+1]);
                }
        }
        __syncthreads();
        if (c + 2 < NCH) {
            int k0 = (c + 2)*32;
            cp16(so + GA_HI + (ra*SROW + sa)*2, g_Wch + (size_t)ra*KCP + k0 + sa);
            cp16(so + GA_LO + (ra*SROW + sa)*2, g_Wcl + (size_t)ra*KCP + k0 + sa);
            #pragma unroll
            for (int q = 0; q < 2; q++) {
                int idx = q*256 + tid;
                int rb = idx >> 4, sg = (idx & 15) << 3;
                cp16(so + GB_HI + (rb*GBROW + sg)*2, Bhp + (size_t)(k0 + rb)*Nn + n0 + sg);
                cp16(so + GB_LO + (rb*GBROW + sg)*2, Blp + (size_t)(k0 + rb)*Nn + n0 + sg);
            }
        }
        CP_COMMIT();
    }

    // epilogue: h update; stage hn into smem (aliased over GEMM buffers)
    float* hb = (float*)smem;    // [64][132]
    const int mr = lane >> 2, nc = (lane & 3) << 1;
    #pragma unroll
    for (int mt = 0; mt < 2; mt++) {
        #pragma unroll
        for (int nb = 0; nb < 4; nb++) {
            int nl = wn + nb*8 + nc;
            int n = n0 + nl;
            #pragma unroll
            for (int hv = 0; hv < 2; hv++) {
                int o = wm + mt*16 + mr + hv*8;
                float bb = bc[o];
                size_t hidx = ((size_t)(b*Hh + o))*Nn + n;
                float2 uu = *(const float2*)(g_u + hidx);
                float2 hh = *(const float2*)(g_h + hidx);
                float c0 = tanhf(acc[mt][nb][hv*2]   + bb);
                float c1 = tanhf(acc[mt][nb][hv*2+1] + bb);
                float h0 = uu.x*hh.x + (1.f - uu.x)*c0;
                float h1 = uu.y*hh.y + (1.f - uu.y)*c1;
                *(float2*)(g_h + hidx) = make_float2(h0, h1);
                hb[o*132 + nl]     = h0;
                hb[o*132 + nl + 1] = h1;
            }
        }
    }
    __syncthreads();

    // fused pre for step t+1
    if (t + 1 < Tt) {
        int tn = t + 1;
        int group = tid >> 7, nl = tid & 127, n = n0 + nl;
        float part = 0.f;
        #pragma unroll
        for (int oo = 0; oo < 32; oo++) {
            int o = group*32 + oo;
            float hv = hb[o*132 + nl];
            part += ws[o] * hv;
            out[PRED_SZ + (((size_t)(b*Hh + o))*Nn + n)*Tt + tn] = hv;
            size_t za = ((size_t)(b*C1 + 2 + o))*Nn + n;
            split_store(hv, g_zAhi[0], g_zAlo[0], za);
            size_t zb = ((size_t)b*ZBROW + 2 + o)*Nn + n;
            split_store(hv, g_zbh, g_zbl, zb);
        }
        xpart[group*128 + nl] = part;
        __syncthreads();
        if (group == 0) {
            float xhat = xpart[nl] + xpart[128 + nl] + bout[0];
            out[((size_t)(b*Nn) + n)*Tt + tn] = xhat;
            size_t xi = ((size_t)b*Nn + n)*Tt + tn;
            float xv = x[xi];
            bool m;
            if (g_masktype == 0)
                m = ((const unsigned char*)mask)[xi] != 0;
            else
                m = ((const unsigned int*)mask)[xi] != 0u;
            float xin = m ? xv : xhat;
            float mf  = m ? 1.f : 0.f;
            size_t za0 = ((size_t)(b*C1) + 0)*Nn + n;
            size_t za1 = ((size_t)(b*C1) + 1)*Nn + n;
            split_store(xin, g_zAhi[0], g_zAlo[0], za0);
            split_store(mf,  g_zAhi[0], g_zAlo[0], za1);
            size_t zb0 = ((size_t)b*ZBROW + 0)*Nn + n;
            size_t zb1 = ((size_t)b*ZBROW + 1)*Nn + n;
            split_store(xin, g_zbh, g_zbl, zb0);
            split_store(mf,  g_zbh, g_zbl, zb1);
        }
    }
}

// ---------------- pre (t=0 only) ----------------
__global__ __launch_bounds__(128) void pre_kernel(
    const float* __restrict__ x, const void* __restrict__ mask,
    const float* __restrict__ Wout, const float* __restrict__ bout,
    float* __restrict__ out)
{
    int n = blockIdx.x*128 + threadIdx.x;
    int b = blockIdx.y;
    __shared__ float ws[Hh];
    if (threadIdx.x < Hh) ws[threadIdx.x] = Wout[threadIdx.x];
    __syncthreads();
    float acc = 0.f;
    #pragma unroll 4
    for (int hh = 0; hh < Hh; hh++) {
        float hv = g_h[((size_t)(b*Hh + hh))*Nn + n];
        acc += hv * ws[hh];
        size_t za = ((size_t)(b*C1 + 2 + hh))*Nn + n;
        split_store(hv, g_zAhi[0], g_zAlo[0], za);
        split_store(hv, g_zbh, g_zbl, ((size_t)b*ZBROW + 2 + hh)*Nn + n);
        out[PRED_SZ + (((size_t)(b*Hh + hh))*Nn + n)*Tt + 0] = hv;
    }
    float xhat = acc + bout[0];
    out[((size_t)(b*Nn) + n)*Tt + 0] = xhat;
    size_t xi = ((size_t)b*Nn + n)*Tt + 0;
    float xv = x[xi];
    bool m;
    if (g_masktype == 0)
        m = ((const unsigned char*)mask)[xi] != 0;
    else
        m = ((const unsigned int*)mask)[xi] != 0u;
    float xin = m ? xv : xhat;
    float mf  = m ? 1.f : 0.f;
    split_store(xin, g_zAhi[0], g_zAlo[0], ((size_t)(b*C1) + 0)*Nn + n);
    split_store(mf,  g_zAhi[0], g_zAlo[0], ((size_t)(b*C1) + 1)*Nn + n);
    split_store(xin, g_zbh, g_zbl, ((size_t)b*ZBROW + 0)*Nn + n);
    split_store(mf,  g_zbh, g_zbl, ((size_t)b*ZBROW + 1)*Nn + n);
}

// ---------------- launch ----------------
extern "C" void kernel_launch(void* const* d_in, const int* in_sizes, int n_in,
                              void* d_out, int out_size) {
    int ix, imask, iadj, iWr, ibr, iWu, ibu, iWc, ibc, iWout, ibout;
    if (in_sizes[0] == 21120) {
        iWc = 0; iWout = 1; iWr = 2; iWu = 3; iadj = 4; ibc = 5;
        ibout = 6; ibr = 7; ibu = 8; imask = 9; ix = 10;
    } else {
        ix = 0; imask = 1; iadj = 2; iWr = 3; ibr = 4; iWu = 5;
        ibu = 6; iWc = 7; ibc = 8; iWout = 9; ibout = 10;
    }
    const float* x    = (const float*)d_in[ix];
    const void*  mask = d_in[imask];
    const float* adj  = (const float*)d_in[iadj];
    const float* Wr   = (const float*)d_in[iWr];
    const float* br   = (const float*)d_in[ibr];
    const float* Wu   = (const float*)d_in[iWu];
    const float* bu   = (const float*)d_in[ibu];
    const float* Wc   = (const float*)d_in[iWc];
    const float* bc   = (const float*)d_in[ibc];
    const float* Wout = (const float*)d_in[iWout];
    const float* bout = (const float*)d_in[ibout];
    float* out = (float*)d_out;

    cudaFuncSetAttribute(diff_mma_kernel,
                         cudaFuncAttributeMaxDynamicSharedMemorySize, DIFF_SMEM);
    cudaFuncSetAttribute(gates_mma_kernel,
                         cudaFuncAttributeMaxDynamicSharedMemorySize, GATES_SMEM);
    cudaFuncSetAttribute(update_mma_kernel,
                         cudaFuncAttributeMaxDynamicSharedMemorySize, GATES_SMEM);

    detect_mask_kernel<<<1, 32>>>((const unsigned int*)mask);
    norm_kernel<<<Nn, 256>>>(adj);
    square_kernel<<<dim3(Nn/DBN, Nn/DBM, 2), 256>>>();
    conv_support_kernel<<<dim3(Nn*Nn/256, 4), 256>>>();
    conv_w_kernel<<<dim3((Hh*KCP + 255)/256, 3), 256>>>(Wr, Wu, Wc);
    zero_pad_kernel<<<dim3((M_PAD - M_DIFF)*Nn/256, 4), 256>>>();
    zero_zb_pad_kernel<<<(2*Bt*22*Nn + 255)/256, 256>>>();
    zero_h_kernel<<<(Bt*Hh*Nn + 255)/256, 256>>>();

    pre_kernel<<<dim3(Nn/128, Bt), 128>>>(x, mask, Wout, bout, out);
    for (int t = 0; t < Tt; t++) {
        diff_mma_kernel<<<dim3(8, 9, 4), 256, DIFF_SMEM>>>(0);
        gates_mma_kernel<<<dim3(8, 2, Bt), 256, GATES_SMEM>>>(br, bu);
        diff_mma_kernel<<<dim3(8, 9, 4), 256, DIFF_SMEM>>>(1);
        update_mma_kernel<<<dim3(8, Bt), 256, GATES_SMEM>>>(bc, x, mask, Wout, bout, out, t);
    }
}

// round 15
// speedup vs baseline: 4.5977x; 1.2847x over previous
#include <cuda_runtime.h>
#include <cuda_fp16.h>
#include <math.h>
#include <stdint.h>

#define Bt 8
#define Nn 1024
#define Hh 64
#define Tt 128
#define C1 66              // channels in xh = 2 + H
#define KC 330             // 5 * C1
#define KCP 352            // padded K for gate GEMMs (22 * 16)
#define ZBROW 352
#define M_DIFF (Bt*C1)     // 528
#define M_PAD 576          // padded diff A rows (9 tiles of 64)
#define PRED_SZ (Bt*Nn*Tt) // 1048576

// f32x2 square-GEMM tile
#define DBM 64
#define DBN 128
#define DBK 16
#define APAD 68
#define BPAD 132

// HMMA diffusion layout: tile 64(M) x 128(N), fp16, B hi-only, 2-stage
#define SROW 40                        // 32 data + 8 pad halves (80B rows)
#define D_AHI 0
#define D_ALO (64*SROW*2)              // 5120
#define D_BHI (2*64*SROW*2)            // 10240
#define D_STG (D_BHI + 128*SROW*2)     // 20480
#define DIFF_SMEM (2*D_STG)            // 40960

// gates/update HMMA layout (same as R14, fp16): tile 64 x 128, K chunks of 32
#define GBROW 136                      // 128 data + 8 pad
#define GA_HI 0
#define GA_LO (64*SROW*2)              // 5120
#define GB_HI (2*64*SROW*2)            // 10240
#define GB_LO (GB_HI + 32*GBROW*2)     // 18944
#define GSTG  (GB_LO + 32*GBROW*2)     // 27648
#define GATES_SMEM (2*GSTG)            // 55296
#define NCH 11                         // 352/32 K chunks

// ---------------- helpers ----------------
__device__ __forceinline__ uint32_t smem_u32(const void* p) {
    uint32_t a;
    asm("{ .reg .u64 t; cvta.to.shared.u64 t, %1; cvt.u32.u64 %0, t; }" : "=r"(a) : "l"(p));
    return a;
}
__device__ __forceinline__ void ldsm4(uint32_t& r0, uint32_t& r1, uint32_t& r2, uint32_t& r3,
                                      uint32_t addr) {
    asm volatile("ldmatrix.sync.aligned.m8n8.x4.shared.b16 {%0,%1,%2,%3}, [%4];"
                 : "=r"(r0), "=r"(r1), "=r"(r2), "=r"(r3) : "r"(addr));
}
__device__ __forceinline__ void ldsm4t(uint32_t& r0, uint32_t& r1, uint32_t& r2, uint32_t& r3,
                                       uint32_t addr) {
    asm volatile("ldmatrix.sync.aligned.m8n8.x4.trans.shared.b16 {%0,%1,%2,%3}, [%4];"
                 : "=r"(r0), "=r"(r1), "=r"(r2), "=r"(r3) : "r"(addr));
}
__device__ __forceinline__ void mma_f16(float* c, const uint32_t* a, uint32_t b0, uint32_t b1) {
    asm volatile(
        "mma.sync.aligned.m16n8k16.row.col.f32.f16.f16.f32 "
        "{%0,%1,%2,%3}, {%4,%5,%6,%7}, {%8,%9}, {%0,%1,%2,%3};"
        : "+f"(c[0]), "+f"(c[1]), "+f"(c[2]), "+f"(c[3])
        : "r"(a[0]), "r"(a[1]), "r"(a[2]), "r"(a[3]), "r"(b0), "r"(b1));
}
__device__ __forceinline__ void cp16(uint32_t saddr, const void* gaddr) {
    asm volatile("cp.async.cg.shared.global [%0], [%1], 16;" :: "r"(saddr), "l"(gaddr));
}
#define CP_COMMIT() asm volatile("cp.async.commit_group;" ::: "memory")
#define CP_WAIT1()  asm volatile("cp.async.wait_group 1;" ::: "memory")

// f32x2 (for the one-time S^2 GEMM)
__device__ __forceinline__ unsigned long long pack2(float v) {
    unsigned long long r;
    asm("mov.b64 %0, {%1, %1};" : "=l"(r) : "f"(v));
    return r;
}
__device__ __forceinline__ void ffma2(unsigned long long& d,
                                      unsigned long long a, unsigned long long b) {
    asm("fma.rn.f32x2 %0, %1, %2, %0;" : "+l"(d) : "l"(a), "l"(b));
}
__device__ __forceinline__ float2 unpack2(unsigned long long v) {
    float2 f;
    asm("mov.b64 {%0, %1}, %2;" : "=f"(f.x), "=f"(f.y) : "l"(v));
    return f;
}

// ---------------- device globals ----------------
__device__ float g_Sf [Nn*Nn];
__device__ float g_Sb [Nn*Nn];
__device__ float g_Sf2[Nn*Nn];
__device__ float g_Sb2[Nn*Nn];
__device__ float g_h  [Bt*Hh*Nn];
__device__ float g_u  [Bt*Hh*Nn];
__device__ int   g_masktype;
__device__ __half g_zAhi[2][M_PAD*Nn];     // diff A operand (hi)
__device__ __half g_zAlo[2][M_PAD*Nn];
__device__ __half g_SBh[4][Nn*Nn];         // supports, fp16 hi only
__device__ __half g_zbh[2*Bt*ZBROW*Nn];    // gates B operand [set][b][352][1024]
__device__ __half g_zbl[2*Bt*ZBROW*Nn];
__device__ __half g_Wgh[2][Hh*KCP];        // Wr, Wu splits
__device__ __half g_Wgl[2][Hh*KCP];
__device__ __half g_Wch[Hh*KCP];           // Wc split
__device__ __half g_Wcl[Hh*KCP];

__device__ __forceinline__ void split_store_h(float v, __half* hi, __half* lo, size_t idx) {
    __half h = __float2half(v);
    hi[idx] = h;
    lo[idx] = __float2half(v - __half2float(h));
}
__device__ __forceinline__ void split2h(float v0, float v1, uint32_t& hi, uint32_t& lo) {
    __half h0 = __float2half(v0), h1 = __float2half(v1);
    float l0 = v0 - __half2float(h0), l1 = v1 - __half2float(h1);
    hi = (uint32_t)__half_as_ushort(h0) | ((uint32_t)__half_as_ushort(h1) << 16);
    lo = (uint32_t)__half_as_ushort(__float2half(l0))
       | ((uint32_t)__half_as_ushort(__float2half(l1)) << 16);
}

// ---------------- mask dtype sniffer ----------------
__global__ void detect_mask_kernel(const unsigned int* __restrict__ m) {
    if (threadIdx.x != 0 || blockIdx.x != 0) return;
    int byte_like = 0;
    for (int i = 0; i < 1024; i++) {
        unsigned int w = m[i];
        if (w == 0u || w == 1u || w == 0x3F800000u) continue;
        unsigned int b0 = w & 255u, b1 = (w >> 8) & 255u,
                     b2 = (w >> 16) & 255u, b3 = w >> 24;
        if (b0 <= 1u && b1 <= 1u && b2 <= 1u && b3 <= 1u) { byte_like = 1; break; }
    }
    g_masktype = byte_like ? 0 : 1;
}

// ---------------- support normalization ----------------
__global__ void norm_kernel(const float* __restrict__ adj) {
    int w = blockIdx.x;
    int tid = threadIdx.x;
    __shared__ float sred[256];
    float rs = 0.f, cs = 0.f;
    for (int v = tid; v < Nn; v += 256) {
        rs += adj[w*Nn + v];
        cs += adj[v*Nn + w];
    }
    sred[tid] = rs; __syncthreads();
    for (int s = 128; s > 0; s >>= 1) { if (tid < s) sred[tid] += sred[tid+s]; __syncthreads(); }
    float rsum = sred[0] + 1e-8f; __syncthreads();
    sred[tid] = cs; __syncthreads();
    for (int s = 128; s > 0; s >>= 1) { if (tid < s) sred[tid] += sred[tid+s]; __syncthreads(); }
    float csum = sred[0] + 1e-8f; __syncthreads();
    for (int v = tid; v < Nn; v += 256) {
        g_Sf[w*Nn + v] = adj[w*Nn + v] / rsum;
        g_Sb[w*Nn + v] = adj[v*Nn + w] / csum;
    }
}

// ---------------- f32x2 GEMM (once, for S^2) ----------------
__device__ __forceinline__ void gemm_nn_f32x2(const float* __restrict__ A,
                                              const float* __restrict__ B,
                                              float* __restrict__ C, int M)
{
    __shared__ float As[DBK][APAD];
    __shared__ float Bs[DBK][BPAD];
    const int tid  = threadIdx.x;
    const int row0 = blockIdx.y*DBM, col0 = blockIdx.x*DBN;
    const int am = tid >> 2, ak = (tid & 3) << 2;
    const int bk = tid >> 5, bn = (tid & 31) << 2;
    const int tx = tid & 15, ty = tid >> 4;

    unsigned long long acc[4][4];
    #pragma unroll
    for (int i = 0; i < 4; i++)
        #pragma unroll
        for (int p = 0; p < 4; p++) acc[i][p] = 0ULL;

    const bool arow_ok = (row0 + am) < M;
    const float* Aptr  = A + (size_t)(row0 + am)*Nn + ak;
    const float* Bptr0 = B + (size_t)bk*Nn + col0 + bn;
    const float* Bptr1 = B + (size_t)(bk + 8)*Nn + col0 + bn;

    float4 areg  = arow_ok ? *(const float4*)Aptr : make_float4(0.f,0.f,0.f,0.f);
    float4 breg0 = *(const float4*)Bptr0;
    float4 breg1 = *(const float4*)Bptr1;

    for (int k0 = 0; k0 < Nn; k0 += DBK) {
        As[ak+0][am] = areg.x; As[ak+1][am] = areg.y;
        As[ak+2][am] = areg.z; As[ak+3][am] = areg.w;
        *(float4*)&Bs[bk][bn]   = breg0;
        *(float4*)&Bs[bk+8][bn] = breg1;
        __syncthreads();
        if (k0 + DBK < Nn) {
            areg  = arow_ok ? *(const float4*)(Aptr + k0 + DBK) : make_float4(0.f,0.f,0.f,0.f);
            breg0 = *(const float4*)(Bptr0 + (size_t)(k0 + DBK)*Nn);
            breg1 = *(const float4*)(Bptr1 + (size_t)(k0 + DBK)*Nn);
        }
        #pragma unroll
        for (int kk = 0; kk < DBK; kk++) {
            float4 a4 = *(const float4*)&As[kk][ty << 2];
            ulonglong2 b01 = *(const ulonglong2*)&Bs[kk][tx << 2];
            ulonglong2 b23 = *(const ulonglong2*)&Bs[kk][64 + (tx << 2)];
            unsigned long long ap0 = pack2(a4.x), ap1 = pack2(a4.y),
                               ap2 = pack2(a4.z), ap3 = pack2(a4.w);
            ffma2(acc[0][0], ap0, b01.x); ffma2(acc[0][1], ap0, b01.y);
            ffma2(acc[0][2], ap0, b23.x); ffma2(acc[0][3], ap0, b23.y);
            ffma2(acc[1][0], ap1, b01.x); ffma2(acc[1][1], ap1, b01.y);
            ffma2(acc[1][2], ap1, b23.x); ffma2(acc[1][3], ap1, b23.y);
            ffma2(acc[2][0], ap2, b01.x); ffma2(acc[2][1], ap2, b01.y);
            ffma2(acc[2][2], ap2, b23.x); ffma2(acc[2][3], ap2, b23.y);
            ffma2(acc[3][0], ap3, b01.x); ffma2(acc[3][1], ap3, b01.y);
            ffma2(acc[3][2], ap3, b23.x); ffma2(acc[3][3], ap3, b23.y);
        }
        __syncthreads();
    }
    #pragma unroll
    for (int i = 0; i < 4; i++) {
        int m = row0 + (ty << 2) + i;
        if (m < M) {
            float2 p0 = unpack2(acc[i][0]), p1 = unpack2(acc[i][1]);
            float2 p2 = unpack2(acc[i][2]), p3 = unpack2(acc[i][3]);
            *(float4*)(C + (size_t)m*Nn + col0 + (tx << 2))
                = make_float4(p0.x, p0.y, p1.x, p1.y);
            *(float4*)(C + (size_t)m*Nn + col0 + 64 + (tx << 2))
                = make_float4(p2.x, p2.y, p3.x, p3.y);
        }
    }
}

__global__ __launch_bounds__(256) void square_kernel() {
    const float* S = blockIdx.z ? g_Sb : g_Sf;
    float*       D = blockIdx.z ? g_Sb2 : g_Sf2;
    gemm_nn_f32x2(S, S, D, Nn);
}

// ---------------- fused one-time conversions / zero-init (ONE launch) ----------------
__global__ void setup_convert_kernel(const float* __restrict__ Wr,
                                     const float* __restrict__ Wu,
                                     const float* __restrict__ Wc) {
    int bid = blockIdx.x;
    int tid = threadIdx.x;
    if (bid < 16384) {                                  // supports -> fp16 hi
        size_t idx = (size_t)bid*256 + tid;
        int s = (int)(idx >> 20);
        size_t i = idx & 1048575u;
        const float* src = (s == 0) ? g_Sf : (s == 1) ? g_Sf2 : (s == 2) ? g_Sb : g_Sb2;
        g_SBh[s][i] = __float2half(src[i]);
    } else if (bid < 16648) {                           // weights -> fp16 hi/lo
        int idx = (bid - 16384)*256 + tid;
        if (idx < 3*Hh*KCP) {
            int wsel = idx / (Hh*KCP), rem = idx % (Hh*KCP);
            int o = rem / KCP, kf = rem % KCP;
            const float* W = (wsel == 0) ? Wr : (wsel == 1) ? Wu : Wc;
            float v = (kf < KC) ? W[o*KC + kf] : 0.f;
            if (wsel < 2) split_store_h(v, g_Wgh[wsel], g_Wgl[wsel], rem);
            else          split_store_h(v, g_Wch, g_Wcl, rem);
        }
    } else if (bid < 17416) {                           // zA pad rows [528,576)
        size_t i = (size_t)(bid - 16648)*256 + tid;     // < 196608
        int w = (int)(i / 49152);
        size_t off = (size_t)M_DIFF*Nn + (i % 49152);
        __half z = __float2half(0.f);
        if (w == 0) g_zAhi[0][off] = z;
        else if (w == 1) g_zAlo[0][off] = z;
        else if (w == 2) g_zAhi[1][off] = z;
        else g_zAlo[1][off] = z;
    } else if (bid < 18824) {                           // zb pad rows [330,352)
        int idx = (bid - 17416)*256 + tid;
        if (idx < 16*22*1024) {
            int sbi = idx / (22*1024);
            int rem = idx % (22*1024);
            int row = 330 + rem/1024, n = rem % 1024;
            size_t a = ((size_t)sbi*ZBROW + row)*Nn + n;
            __half z = __float2half(0.f);
            g_zbh[a] = z; g_zbl[a] = z;
        }
    } else {                                            // zero h
        int i = (bid - 18824)*256 + tid;
        if (i < Bt*Hh*Nn) g_h[i] = 0.f;
    }
}

// ---------------- HMMA diffusion (fp16, B hi-only, 2 passes) ----------------
__global__ __launch_bounds__(256) void diff_mma_kernel(int set) {
    extern __shared__ char smem[];
    const uint32_t sb = smem_u32(smem);
    const int tid = threadIdx.x, wid = tid >> 5, lane = tid & 31;
    const int n0 = blockIdx.x*128, m0 = blockIdx.y*64, s = blockIdx.z;
    const int wm = (wid >> 2) << 5;
    const int wn = (wid & 3) << 5;

    const __half* __restrict__ Ah = g_zAhi[set] + (size_t)m0*Nn;
    const __half* __restrict__ Al = g_zAlo[set] + (size_t)m0*Nn;
    const __half* __restrict__ Bh = g_SBh[s]    + (size_t)n0*Nn;

    const int pr = tid >> 2, ps = (tid & 3) << 3;

    float acc[2][4][4];
    #pragma unroll
    for (int mt = 0; mt < 2; mt++)
        #pragma unroll
        for (int nb = 0; nb < 4; nb++)
            #pragma unroll
            for (int q = 0; q < 4; q++) acc[mt][nb][q] = 0.f;

    #pragma unroll
    for (int st = 0; st < 2; st++) {
        int k0 = st*32;
        uint32_t so = sb + st*D_STG;
        uint32_t rb = (pr*SROW + ps)*2;
        cp16(so + D_AHI + rb, Ah + (size_t)pr*Nn + k0 + ps);
        cp16(so + D_ALO + rb, Al + (size_t)pr*Nn + k0 + ps);
        cp16(so + D_BHI + rb, Bh + (size_t)pr*Nn + k0 + ps);
        cp16(so + D_BHI + rb + 64*SROW*2, Bh + (size_t)(pr + 64)*Nn + k0 + ps);
        CP_COMMIT();
    }

    const int ar = lane & 15;
    const int ac = (lane >> 4) << 3;

    for (int c = 0; c < 32; c++) {
        const int st = c & 1;
        const uint32_t so = sb + st*D_STG;
        CP_WAIT1();
        __syncthreads();

        #pragma unroll
        for (int kk = 0; kk < 2; kk++) {
            const int k = kk << 4;
            uint32_t ah[2][4], al[2][4], bh[2][4];
            #pragma unroll
            for (int mt = 0; mt < 2; mt++) {
                uint32_t off = ((wm + mt*16 + ar)*SROW + k + ac)*2;
                ldsm4(ah[mt][0], ah[mt][1], ah[mt][2], ah[mt][3], so + D_AHI + off);
                ldsm4(al[mt][0], al[mt][1], al[mt][2], al[mt][3], so + D_ALO + off);
            }
            #pragma unroll
            for (int nt = 0; nt < 2; nt++) {
                uint32_t off = ((wn + nt*16 + ar)*SROW + k + ac)*2;
                ldsm4(bh[nt][0], bh[nt][1], bh[nt][2], bh[nt][3], so + D_BHI + off);
            }
            #pragma unroll
            for (int mt = 0; mt < 2; mt++)
                #pragma unroll
                for (int nb = 0; nb < 4; nb++) {
                    int nt = nb >> 1, hf = nb & 1;
                    mma_f16(acc[mt][nb], ah[mt], bh[nt][hf], bh[nt][2+hf]);
                    mma_f16(acc[mt][nb], al[mt], bh[nt][hf], bh[nt][2+hf]);
                }
        }
        __syncthreads();
        if (c + 2 < 32) {
            int k0 = (c + 2)*32;
            uint32_t rb = (pr*SROW + ps)*2;
            cp16(so + D_AHI + rb, Ah + (size_t)pr*Nn + k0 + ps);
            cp16(so + D_ALO + rb, Al + (size_t)pr*Nn + k0 + ps);
            cp16(so + D_BHI + rb, Bh + (size_t)pr*Nn + k0 + ps);
            cp16(so + D_BHI + rb + 64*SROW*2, Bh + (size_t)(pr + 64)*Nn + k0 + ps);
        }
        CP_COMMIT();
    }

    // epilogue: split fp32 acc into fp16 hi/lo rows of g_zb[set]
    const int mr = lane >> 2, nc = (lane & 3) << 1;
    #pragma unroll
    for (int mt = 0; mt < 2; mt++) {
        #pragma unroll
        for (int nb = 0; nb < 4; nb++) {
            int n = n0 + wn + nb*8 + nc;
            int m = m0 + wm + mt*16 + mr;
            #pragma unroll
            for (int hv = 0; hv < 2; hv++) {
                int mm = m + hv*8;
                if (mm < M_DIFF) {
                    int bb = mm / C1, cc = mm - bb*C1;
                    size_t a = (((size_t)(set*Bt + bb))*ZBROW + (s+1)*C1 + cc)*Nn + n;
                    uint32_t hi, lo;
                    split2h(acc[mt][nb][hv*2], acc[mt][nb][hv*2+1], hi, lo);
                    *(uint32_t*)((char*)g_zbh + a*2) = hi;
                    *(uint32_t*)((char*)g_zbl + a*2) = lo;
                }
            }
        }
    }
}

// ---------------- gates r+u on HMMA (fp16, 3-pass, as R14) ----------------
__global__ __launch_bounds__(256) void gates_mma_kernel(
    const float* __restrict__ br, const float* __restrict__ bu)
{
    extern __shared__ char smem[];
    const uint32_t sb = smem_u32(smem);
    const int tid = threadIdx.x, wid = tid >> 5, lane = tid & 31;
    const int n0 = blockIdx.x*128, gate = blockIdx.y, b = blockIdx.z;
    const int wm = (wid >> 2) << 5;
    const int wn = (wid & 3) << 5;

    const __half* __restrict__ Ah = g_Wgh[gate];
    const __half* __restrict__ Al = g_Wgl[gate];
    const __half* __restrict__ Bhp = g_zbh + (size_t)b*ZBROW*Nn;   // set 0
    const __half* __restrict__ Blp = g_zbl + (size_t)b*ZBROW*Nn;

    const int ra = tid >> 2, sa = (tid & 3) << 3;
    float acc[2][4][4];
    #pragma unroll
    for (int mt = 0; mt < 2; mt++)
        #pragma unroll
        for (int nb = 0; nb < 4; nb++)
            #pragma unroll
            for (int q = 0; q < 4; q++) acc[mt][nb][q] = 0.f;

    #pragma unroll
    for (int st = 0; st < 2; st++) {
        int k0 = st*32;
        uint32_t so = sb + st*GSTG;
        cp16(so + GA_HI + (ra*SROW + sa)*2, Ah + (size_t)ra*KCP + k0 + sa);
        cp16(so + GA_LO + (ra*SROW + sa)*2, Al + (size_t)ra*KCP + k0 + sa);
        #pragma unroll
        for (int q = 0; q < 2; q++) {
            int idx = q*256 + tid;
            int rb = idx >> 4, sg = (idx & 15) << 3;
            cp16(so + GB_HI + (rb*GBROW + sg)*2, Bhp + (size_t)(k0 + rb)*Nn + n0 + sg);
            cp16(so + GB_LO + (rb*GBROW + sg)*2, Blp + (size_t)(k0 + rb)*Nn + n0 + sg);
        }
        CP_COMMIT();
    }

    const int ar = lane & 15;
    const int ac = (lane >> 4) << 3;

    for (int c = 0; c < NCH; c++) {
        const int st = c & 1;
        const uint32_t so = sb + st*GSTG;
        CP_WAIT1();
        __syncthreads();

        #pragma unroll
        for (int kk = 0; kk < 2; kk++) {
            const int k = kk << 4;
            uint32_t ah[2][4], al[2][4], bh[2][4], bl[2][4];
            #pragma unroll
            for (int mt = 0; mt < 2; mt++) {
                uint32_t off = ((wm + mt*16 + ar)*SROW + k + ac)*2;
                ldsm4(ah[mt][0], ah[mt][1], ah[mt][2], ah[mt][3], so + GA_HI + off);
                ldsm4(al[mt][0], al[mt][1], al[mt][2], al[mt][3], so + GA_LO + off);
            }
            #pragma unroll
            for (int nt = 0; nt < 2; nt++) {
                uint32_t off = ((k + ar)*GBROW + wn + nt*16 + ac)*2;
                ldsm4t(bh[nt][0], bh[nt][1], bh[nt][2], bh[nt][3], so + GB_HI + off);
                ldsm4t(bl[nt][0], bl[nt][1], bl[nt][2], bl[nt][3], so + GB_LO + off);
            }
            #pragma unroll
            for (int mt = 0; mt < 2; mt++)
                #pragma unroll
                for (int nb = 0; nb < 4; nb++) {
                    int nt = nb >> 1, p = (nb & 1) << 1;
                    mma_f16(acc[mt][nb], ah[mt], bh[nt][p], bh[nt][p+1]);
                    mma_f16(acc[mt][nb], ah[mt], bl[nt][p], bl[nt][p+1]);
                    mma_f16(acc[mt][nb], al[mt], bh[nt][p], bh[nt][p+1]);
                }
        }
        __syncthreads();
        if (c + 2 < NCH) {
            int k0 = (c + 2)*32;
            cp16(so + GA_HI + (ra*SROW + sa)*2, Ah + (size_t)ra*KCP + k0 + sa);
            cp16(so + GA_LO + (ra*SROW + sa)*2, Al + (size_t)ra*KCP + k0 + sa);
            #pragma unroll
            for (int q = 0; q < 2; q++) {
                int idx = q*256 + tid;
                int rb = idx >> 4, sg = (idx & 15) << 3;
                cp16(so + GB_HI + (rb*GBROW + sg)*2, Bhp + (size_t)(k0 + rb)*Nn + n0 + sg);
                cp16(so + GB_LO + (rb*GBROW + sg)*2, Blp + (size_t)(k0 + rb)*Nn + n0 + sg);
            }
        }
        CP_COMMIT();
    }

    // epilogue
    const int mr = lane >> 2, nc = (lane & 3) << 1;
    const float* bias = gate ? bu : br;
    #pragma unroll
    for (int mt = 0; mt < 2; mt++) {
        #pragma unroll
        for (int nb = 0; nb < 4; nb++) {
            int n = n0 + wn + nb*8 + nc;
            #pragma unroll
            for (int hv = 0; hv < 2; hv++) {
                int o = wm + mt*16 + mr + hv*8;
                float bb = bias[o];
                float s0 = 1.f/(1.f + expf(-(acc[mt][nb][hv*2]   + bb)));
                float s1 = 1.f/(1.f + expf(-(acc[mt][nb][hv*2+1] + bb)));
                size_t hidx = ((size_t)(b*Hh + o))*Nn + n;
                if (gate == 0) {
                    float2 hvv = *(const float2*)(g_h + hidx);
                    float r0 = s0*hvv.x, r1 = s1*hvv.y;
                    uint32_t hi, lo;
                    split2h(r0, r1, hi, lo);
                    size_t za = ((size_t)(b*C1 + 2 + o))*Nn + n;            // zA[1]
                    *(uint32_t*)((char*)&g_zAhi[1][0] + za*2) = hi;
                    *(uint32_t*)((char*)&g_zAlo[1][0] + za*2) = lo;
                    size_t zb = (((size_t)(Bt + b))*ZBROW + 2 + o)*Nn + n;  // zb set 1
                    *(uint32_t*)((char*)g_zbh + zb*2) = hi;
                    *(uint32_t*)((char*)g_zbl + zb*2) = lo;
                } else {
                    *(float2*)(g_u + hidx) = make_float2(s0, s1);
                }
            }
        }
    }
    if (gate == 0) {  // copy rows 0,1 (x_in, mask) set0 -> set1 + zA[1]
        int row = tid >> 7, nl = tid & 127, n = n0 + nl;
        size_t src = ((size_t)b*ZBROW + row)*Nn + n;
        __half vh = g_zbh[src], vl = g_zbl[src];
        size_t dst = (((size_t)(Bt + b))*ZBROW + row)*Nn + n;
        g_zbh[dst] = vh; g_zbl[dst] = vl;
        size_t za = ((size_t)(b*C1 + row))*Nn + n;
        g_zAhi[1][za] = vh; g_zAlo[1][za] = vl;
    }
}

// ---------------- update on HMMA + fused pre(t+1) ----------------
__global__ __launch_bounds__(256) void update_mma_kernel(
    const float* __restrict__ bc,
    const float* __restrict__ x, const void* __restrict__ mask,
    const float* __restrict__ Wout, const float* __restrict__ bout,
    float* __restrict__ out, int t)
{
    extern __shared__ char smem[];
    const uint32_t sb = smem_u32(smem);
    const int tid = threadIdx.x, wid = tid >> 5, lane = tid & 31;
    const int n0 = blockIdx.x*128, b = blockIdx.y;
    const int wm = (wid >> 2) << 5;
    const int wn = (wid & 3) << 5;
    __shared__ float ws[Hh];
    __shared__ float xpart[2*128];
    if (tid < Hh) ws[tid] = Wout[tid];

    const __half* __restrict__ Bhp = g_zbh + ((size_t)(Bt + b))*ZBROW*Nn;  // set 1
    const __half* __restrict__ Blp = g_zbl + ((size_t)(Bt + b))*ZBROW*Nn;

    const int ra = tid >> 2, sa = (tid & 3) << 3;
    float acc[2][4][4];
    #pragma unroll
    for (int mt = 0; mt < 2; mt++)
        #pragma unroll
        for (int nb = 0; nb < 4; nb++)
            #pragma unroll
            for (int q = 0; q < 4; q++) acc[mt][nb][q] = 0.f;

    #pragma unroll
    for (int st = 0; st < 2; st++) {
        int k0 = st*32;
        uint32_t so = sb + st*GSTG;
        cp16(so + GA_HI + (ra*SROW + sa)*2, g_Wch + (size_t)ra*KCP + k0 + sa);
        cp16(so + GA_LO + (ra*SROW + sa)*2, g_Wcl + (size_t)ra*KCP + k0 + sa);
        #pragma unroll
        for (int q = 0; q < 2; q++) {
            int idx = q*256 + tid;
            int rb = idx >> 4, sg = (idx & 15) << 3;
            cp16(so + GB_HI + (rb*GBROW + sg)*2, Bhp + (size_t)(k0 + rb)*Nn + n0 + sg);
            cp16(so + GB_LO + (rb*GBROW + sg)*2, Blp + (size_t)(k0 + rb)*Nn + n0 + sg);
        }
        CP_COMMIT();
    }

    const int ar = lane & 15;
    const int ac = (lane >> 4) << 3;

    for (int c = 0; c < NCH; c++) {
        const int st = c & 1;
        const uint32_t so = sb + st*GSTG;
        CP_WAIT1();
        __syncthreads();

        #pragma unroll
        for (int kk = 0; kk < 2; kk++) {
            const int k = kk << 4;
            uint32_t ah[2][4], al[2][4], bh[2][4], bl[2][4];
            #pragma unroll
            for (int mt = 0; mt < 2; mt++) {
                uint32_t off = ((wm + mt*16 + ar)*SROW + k + ac)*2;
                ldsm4(ah[mt][0], ah[mt][1], ah[mt][2], ah[mt][3], so + GA_HI + off);
                ldsm4(al[mt][0], al[mt][1], al[mt][2], al[mt][3], so + GA_LO + off);
            }
            #pragma unroll
            for (int nt = 0; nt < 2; nt++) {
                uint32_t off = ((k + ar)*GBROW + wn + nt*16 + ac)*2;
                ldsm4t(bh[nt][0], bh[nt][1], bh[nt][2], bh[nt][3], so + GB_HI + off);
                ldsm4t(bl[nt][0], bl[nt][1], bl[nt][2], bl[nt][3], so + GB_LO + off);
            }
            #pragma unroll
            for (int mt = 0; mt < 2; mt++)
                #pragma unroll
                for (int nb = 0; nb < 4; nb++) {
                    int nt = nb >> 1, p = (nb & 1) << 1;
                    mma_f16(acc[mt][nb], ah[mt], bh[nt][p], bh[nt][p+1]);
                    mma_f16(acc[mt][nb], ah[mt], bl[nt][p], bl[nt][p+1]);
                    mma_f16(acc[mt][nb], al[mt], bh[nt][p], bh[nt][p+1]);
                }
        }
        __syncthreads();
        if (c + 2 < NCH) {
            int k0 = (c + 2)*32;
            cp16(so + GA_HI + (ra*SROW + sa)*2, g_Wch + (size_t)ra*KCP + k0 + sa);
            cp16(so + GA_LO + (ra*SROW + sa)*2, g_Wcl + (size_t)ra*KCP + k0 + sa);
            #pragma unroll
            for (int q = 0; q < 2; q++) {
                int idx = q*256 + tid;
                int rb = idx >> 4, sg = (idx & 15) << 3;
                cp16(so + GB_HI + (rb*GBROW + sg)*2, Bhp + (size_t)(k0 + rb)*Nn + n0 + sg);
                cp16(so + GB_LO + (rb*GBROW + sg)*2, Blp + (size_t)(k0 + rb)*Nn + n0 + sg);
            }
        }
        CP_COMMIT();
    }

    // epilogue: h update; stage hn into smem (aliased over GEMM buffers)
    float* hb = (float*)smem;    // [64][132]
    const int mr = lane >> 2, nc = (lane & 3) << 1;
    #pragma unroll
    for (int mt = 0; mt < 2; mt++) {
        #pragma unroll
        for (int nb = 0; nb < 4; nb++) {
            int nl = wn + nb*8 + nc;
            int n = n0 + nl;
            #pragma unroll
            for (int hv = 0; hv < 2; hv++) {
                int o = wm + mt*16 + mr + hv*8;
                float bb = bc[o];
                size_t hidx = ((size_t)(b*Hh + o))*Nn + n;
                float2 uu = *(const float2*)(g_u + hidx);
                float2 hh = *(const float2*)(g_h + hidx);
                float c0 = tanhf(acc[mt][nb][hv*2]   + bb);
                float c1 = tanhf(acc[mt][nb][hv*2+1] + bb);
                float h0 = uu.x*hh.x + (1.f - uu.x)*c0;
                float h1 = uu.y*hh.y + (1.f - uu.y)*c1;
                *(float2*)(g_h + hidx) = make_float2(h0, h1);
                hb[o*132 + nl]     = h0;
                hb[o*132 + nl + 1] = h1;
            }
        }
    }
    __syncthreads();

    // fused pre for step t+1
    if (t + 1 < Tt) {
        int tn = t + 1;
        int group = tid >> 7, nl = tid & 127, n = n0 + nl;
        float part = 0.f;
        #pragma unroll
        for (int oo = 0; oo < 32; oo++) {
            int o = group*32 + oo;
            float hv = hb[o*132 + nl];
            part += ws[o] * hv;
            out[PRED_SZ + (((size_t)(b*Hh + o))*Nn + n)*Tt + tn] = hv;
            size_t za = ((size_t)(b*C1 + 2 + o))*Nn + n;
            split_store_h(hv, g_zAhi[0], g_zAlo[0], za);
            size_t zb = ((size_t)b*ZBROW + 2 + o)*Nn + n;
            split_store_h(hv, g_zbh, g_zbl, zb);
        }
        xpart[group*128 + nl] = part;
        __syncthreads();
        if (group == 0) {
            float xhat = xpart[nl] + xpart[128 + nl] + bout[0];
            out[((size_t)(b*Nn) + n)*Tt + tn] = xhat;
            size_t xi = ((size_t)b*Nn + n)*Tt + tn;
            float xv = x[xi];
            bool m;
            if (g_masktype == 0)
                m = ((const unsigned char*)mask)[xi] != 0;
            else
                m = ((const unsigned int*)mask)[xi] != 0u;
            float xin = m ? xv : xhat;
            float mf  = m ? 1.f : 0.f;
            split_store_h(xin, g_zAhi[0], g_zAlo[0], ((size_t)(b*C1) + 0)*Nn + n);
            split_store_h(mf,  g_zAhi[0], g_zAlo[0], ((size_t)(b*C1) + 1)*Nn + n);
            split_store_h(xin, g_zbh, g_zbl, ((size_t)b*ZBROW + 0)*Nn + n);
            split_store_h(mf,  g_zbh, g_zbl, ((size_t)b*ZBROW + 1)*Nn + n);
        }
    }
}

// ---------------- pre (t=0 only) ----------------
__global__ __launch_bounds__(128) void pre_kernel(
    const float* __restrict__ x, const void* __restrict__ mask,
    const float* __restrict__ Wout, const float* __restrict__ bout,
    float* __restrict__ out)
{
    int n = blockIdx.x*128 + threadIdx.x;
    int b = blockIdx.y;
    __shared__ float ws[Hh];
    if (threadIdx.x < Hh) ws[threadIdx.x] = Wout[threadIdx.x];
    __syncthreads();
    float acc = 0.f;
    #pragma unroll 4
    for (int hh = 0; hh < Hh; hh++) {
        float hv = g_h[((size_t)(b*Hh + hh))*Nn + n];
        acc += hv * ws[hh];
        split_store_h(hv, g_zAhi[0], g_zAlo[0], ((size_t)(b*C1 + 2 + hh))*Nn + n);
        split_store_h(hv, g_zbh, g_zbl, ((size_t)b*ZBROW + 2 + hh)*Nn + n);
        out[PRED_SZ + (((size_t)(b*Hh + hh))*Nn + n)*Tt + 0] = hv;
    }
    float xhat = acc + bout[0];
    out[((size_t)(b*Nn) + n)*Tt + 0] = xhat;
    size_t xi = ((size_t)b*Nn + n)*Tt + 0;
    float xv = x[xi];
    bool m;
    if (g_masktype == 0)
        m = ((const unsigned char*)mask)[xi] != 0;
    else
        m = ((const unsigned int*)mask)[xi] != 0u;
    float xin = m ? xv : xhat;
    float mf  = m ? 1.f : 0.f;
    split_store_h(xin, g_zAhi[0], g_zAlo[0], ((size_t)(b*C1) + 0)*Nn + n);
    split_store_h(mf,  g_zAhi[0], g_zAlo[0], ((size_t)(b*C1) + 1)*Nn + n);
    split_store_h(xin, g_zbh, g_zbl, ((size_t)b*ZBROW + 0)*Nn + n);
    split_store_h(mf,  g_zbh, g_zbl, ((size_t)b*ZBROW + 1)*Nn + n);
}

// ---------------- launch ----------------
extern "C" void kernel_launch(void* const* d_in, const int* in_sizes, int n_in,
                              void* d_out, int out_size) {
    int ix, imask, iadj, iWr, ibr, iWu, ibu, iWc, ibc, iWout, ibout;
    if (in_sizes[0] == 21120) {
        iWc = 0; iWout = 1; iWr = 2; iWu = 3; iadj = 4; ibc = 5;
        ibout = 6; ibr = 7; ibu = 8; imask = 9; ix = 10;
    } else {
        ix = 0; imask = 1; iadj = 2; iWr = 3; ibr = 4; iWu = 5;
        ibu = 6; iWc = 7; ibc = 8; iWout = 9; ibout = 10;
    }
    const float* x    = (const float*)d_in[ix];
    const void*  mask = d_in[imask];
    const float* adj  = (const float*)d_in[iadj];
    const float* Wr   = (const float*)d_in[iWr];
    const float* br   = (const float*)d_in[ibr];
    const float* Wu   = (const float*)d_in[iWu];
    const float* bu   = (const float*)d_in[ibu];
    const float* Wc   = (const float*)d_in[iWc];
    const float* bc   = (const float*)d_in[ibc];
    const float* Wout = (const float*)d_in[iWout];
    const float* bout = (const float*)d_in[ibout];
    float* out = (float*)d_out;

    cudaFuncSetAttribute(diff_mma_kernel,
                         cudaFuncAttributeMaxDynamicSharedMemorySize, DIFF_SMEM);
    cudaFuncSetAttribute(gates_mma_kernel,
                         cudaFuncAttributeMaxDynamicSharedMemorySize, GATES_SMEM);
    cudaFuncSetAttribute(update_mma_kernel,
                         cudaFuncAttributeMaxDynamicSharedMemorySize, GATES_SMEM);

    detect_mask_kernel<<<1, 32>>>((const unsigned int*)mask);            // 0
    norm_kernel<<<Nn, 256>>>(adj);                                       // 1
    square_kernel<<<dim3(Nn/DBN, Nn/DBM, 2), 256>>>();                   // 2
    setup_convert_kernel<<<20872, 256>>>(Wr, Wu, Wc);                    // 3
    pre_kernel<<<dim3(Nn/128, Bt), 128>>>(x, mask, Wout, bout, out);     // 4

    for (int t = 0; t < Tt; t++) {
        diff_mma_kernel<<<dim3(8, 9, 4), 256, DIFF_SMEM>>>(0);           // 5 on t=0
        gates_mma_kernel<<<dim3(8, 2, Bt), 256, GATES_SMEM>>>(br, bu);
        diff_mma_kernel<<<dim3(8, 9, 4), 256, DIFF_SMEM>>>(1);
        update_mma_kernel<<<dim3(8, Bt), 256, GATES_SMEM>>>(bc, x, mask, Wout, bout, out, t);
    }
}

// round 16
// speedup vs baseline: 6.5498x; 1.4246x over previous
#include <cuda_runtime.h>
#include <cuda_fp16.h>
#include <math.h>
#include <stdint.h>

#define Bt 8
#define Nn 1024
#define Hh 64
#define Tt 128
#define C1 66              // channels in xh = 2 + H
#define KC 330             // 5 * C1
#define KCP 352            // padded K for gate GEMMs (22 * 16)
#define ZBROW 352
#define M_DIFF (Bt*C1)     // 528
#define M_PAD 576          // padded diff A rows (9 tiles of 64)
#define PRED_SZ (Bt*Nn*Tt) // 1048576

// f32x2 square-GEMM tile
#define DBM 64
#define DBN 128
#define DBK 16
#define APAD 68
#define BPAD 132

// HMMA diffusion layout: tile 64(M) x 128(N), fp16 hi-only, 2-stage
#define SROW 40                        // 32 data + 8 pad halves (80B rows)
#define D_AHI 0
#define D_BHI (64*SROW*2)              // 5120
#define D_STG (D_BHI + 128*SROW*2)     // 15360
#define DIFF_SMEM (2*D_STG)            // 30720

// gates/update HMMA layout: tile 64 x 128, K chunks of 32, z hi-only
#define GBROW 136                      // 128 data + 8 pad
#define GA_HI 0
#define GA_LO (64*SROW*2)              // 5120
#define GB_HI (2*64*SROW*2)            // 10240
#define GSTG  (GB_HI + 32*GBROW*2)     // 18944
#define GATES_SMEM (2*GSTG)            // 37888
#define NCH 11                         // 352/32 K chunks

// ---------------- helpers ----------------
__device__ __forceinline__ uint32_t smem_u32(const void* p) {
    uint32_t a;
    asm("{ .reg .u64 t; cvta.to.shared.u64 t, %1; cvt.u32.u64 %0, t; }" : "=r"(a) : "l"(p));
    return a;
}
__device__ __forceinline__ void ldsm4(uint32_t& r0, uint32_t& r1, uint32_t& r2, uint32_t& r3,
                                      uint32_t addr) {
    asm volatile("ldmatrix.sync.aligned.m8n8.x4.shared.b16 {%0,%1,%2,%3}, [%4];"
                 : "=r"(r0), "=r"(r1), "=r"(r2), "=r"(r3) : "r"(addr));
}
__device__ __forceinline__ void ldsm4t(uint32_t& r0, uint32_t& r1, uint32_t& r2, uint32_t& r3,
                                       uint32_t addr) {
    asm volatile("ldmatrix.sync.aligned.m8n8.x4.trans.shared.b16 {%0,%1,%2,%3}, [%4];"
                 : "=r"(r0), "=r"(r1), "=r"(r2), "=r"(r3) : "r"(addr));
}
__device__ __forceinline__ void mma_f16(float* c, const uint32_t* a, uint32_t b0, uint32_t b1) {
    asm volatile(
        "mma.sync.aligned.m16n8k16.row.col.f32.f16.f16.f32 "
        "{%0,%1,%2,%3}, {%4,%5,%6,%7}, {%8,%9}, {%0,%1,%2,%3};"
        : "+f"(c[0]), "+f"(c[1]), "+f"(c[2]), "+f"(c[3])
        : "r"(a[0]), "r"(a[1]), "r"(a[2]), "r"(a[3]), "r"(b0), "r"(b1));
}
__device__ __forceinline__ void cp16(uint32_t saddr, const void* gaddr) {
    asm volatile("cp.async.cg.shared.global [%0], [%1], 16;" :: "r"(saddr), "l"(gaddr));
}
#define CP_COMMIT() asm volatile("cp.async.commit_group;" ::: "memory")
#define CP_WAIT1()  asm volatile("cp.async.wait_group 1;" ::: "memory")

// f32x2 (for the one-time S^2 GEMM)
__device__ __forceinline__ unsigned long long pack2(float v) {
    unsigned long long r;
    asm("mov.b64 %0, {%1, %1};" : "=l"(r) : "f"(v));
    return r;
}
__device__ __forceinline__ void ffma2(unsigned long long& d,
                                      unsigned long long a, unsigned long long b) {
    asm("fma.rn.f32x2 %0, %1, %2, %0;" : "+l"(d) : "l"(a), "l"(b));
}
__device__ __forceinline__ float2 unpack2(unsigned long long v) {
    float2 f;
    asm("mov.b64 {%0, %1}, %2;" : "=f"(f.x), "=f"(f.y) : "l"(v));
    return f;
}

// ---------------- device globals ----------------
__device__ float g_Sf [Nn*Nn];
__device__ float g_Sb [Nn*Nn];
__device__ float g_Sf2[Nn*Nn];
__device__ float g_Sb2[Nn*Nn];
__device__ float g_h  [Bt*Hh*Nn];
__device__ float g_u  [Bt*Hh*Nn];
__device__ int   g_masktype;
__device__ __half g_zAhi[2][M_PAD*Nn];     // diff A operand (fp16)
__device__ __half g_SBh[4][Nn*Nn];         // supports, fp16
__device__ __half g_zbh[2*Bt*ZBROW*Nn];    // gates B operand [set][b][352][1024], fp16
__device__ __half g_Wgh[2][Hh*KCP];        // Wr, Wu splits (hi)
__device__ __half g_Wgl[2][Hh*KCP];        //               (lo)
__device__ __half g_Wch[Hh*KCP];           // Wc split
__device__ __half g_Wcl[Hh*KCP];

__device__ __forceinline__ void split_store_h(float v, __half* hi, __half* lo, size_t idx) {
    __half h = __float2half(v);
    hi[idx] = h;
    lo[idx] = __float2half(v - __half2float(h));
}
__device__ __forceinline__ uint32_t packh2(float v0, float v1) {
    __half2 p = __floats2half2_rn(v0, v1);
    return *(uint32_t*)&p;
}

// ---------------- mask dtype sniffer ----------------
__global__ void detect_mask_kernel(const unsigned int* __restrict__ m) {
    if (threadIdx.x != 0 || blockIdx.x != 0) return;
    int byte_like = 0;
    for (int i = 0; i < 1024; i++) {
        unsigned int w = m[i];
        if (w == 0u || w == 1u || w == 0x3F800000u) continue;
        unsigned int b0 = w & 255u, b1 = (w >> 8) & 255u,
                     b2 = (w >> 16) & 255u, b3 = w >> 24;
        if (b0 <= 1u && b1 <= 1u && b2 <= 1u && b3 <= 1u) { byte_like = 1; break; }
    }
    g_masktype = byte_like ? 0 : 1;
}

// ---------------- support normalization ----------------
__global__ void norm_kernel(const float* __restrict__ adj) {
    int w = blockIdx.x;
    int tid = threadIdx.x;
    __shared__ float sred[256];
    float rs = 0.f, cs = 0.f;
    for (int v = tid; v < Nn; v += 256) {
        rs += adj[w*Nn + v];
        cs += adj[v*Nn + w];
    }
    sred[tid] = rs; __syncthreads();
    for (int s = 128; s > 0; s >>= 1) { if (tid < s) sred[tid] += sred[tid+s]; __syncthreads(); }
    float rsum = sred[0] + 1e-8f; __syncthreads();
    sred[tid] = cs; __syncthreads();
    for (int s = 128; s > 0; s >>= 1) { if (tid < s) sred[tid] += sred[tid+s]; __syncthreads(); }
    float csum = sred[0] + 1e-8f; __syncthreads();
    for (int v = tid; v < Nn; v += 256) {
        g_Sf[w*Nn + v] = adj[w*Nn + v] / rsum;
        g_Sb[w*Nn + v] = adj[v*Nn + w] / csum;
    }
}

// ---------------- f32x2 GEMM (once, for S^2) ----------------
__device__ __forceinline__ void gemm_nn_f32x2(const float* __restrict__ A,
                                              const float* __restrict__ B,
                                              float* __restrict__ C, int M)
{
    __shared__ float As[DBK][APAD];
    __shared__ float Bs[DBK][BPAD];
    const int tid  = threadIdx.x;
    const int row0 = blockIdx.y*DBM, col0 = blockIdx.x*DBN;
    const int am = tid >> 2, ak = (tid & 3) << 2;
    const int bk = tid >> 5, bn = (tid & 31) << 2;
    const int tx = tid & 15, ty = tid >> 4;

    unsigned long long acc[4][4];
    #pragma unroll
    for (int i = 0; i < 4; i++)
        #pragma unroll
        for (int p = 0; p < 4; p++) acc[i][p] = 0ULL;

    const bool arow_ok = (row0 + am) < M;
    const float* Aptr  = A + (size_t)(row0 + am)*Nn + ak;
    const float* Bptr0 = B + (size_t)bk*Nn + col0 + bn;
    const float* Bptr1 = B + (size_t)(bk + 8)*Nn + col0 + bn;

    float4 areg  = arow_ok ? *(const float4*)Aptr : make_float4(0.f,0.f,0.f,0.f);
    float4 breg0 = *(const float4*)Bptr0;
    float4 breg1 = *(const float4*)Bptr1;

    for (int k0 = 0; k0 < Nn; k0 += DBK) {
        As[ak+0][am] = areg.x; As[ak+1][am] = areg.y;
        As[ak+2][am] = areg.z; As[ak+3][am] = areg.w;
        *(float4*)&Bs[bk][bn]   = breg0;
        *(float4*)&Bs[bk+8][bn] = breg1;
        __syncthreads();
        if (k0 + DBK < Nn) {
            areg  = arow_ok ? *(const float4*)(Aptr + k0 + DBK) : make_float4(0.f,0.f,0.f,0.f);
            breg0 = *(const float4*)(Bptr0 + (size_t)(k0 + DBK)*Nn);
            breg1 = *(const float4*)(Bptr1 + (size_t)(k0 + DBK)*Nn);
        }
        #pragma unroll
        for (int kk = 0; kk < DBK; kk++) {
            float4 a4 = *(const float4*)&As[kk][ty << 2];
            ulonglong2 b01 = *(const ulonglong2*)&Bs[kk][tx << 2];
            ulonglong2 b23 = *(const ulonglong2*)&Bs[kk][64 + (tx << 2)];
            unsigned long long ap0 = pack2(a4.x), ap1 = pack2(a4.y),
                               ap2 = pack2(a4.z), ap3 = pack2(a4.w);
            ffma2(acc[0][0], ap0, b01.x); ffma2(acc[0][1], ap0, b01.y);
            ffma2(acc[0][2], ap0, b23.x); ffma2(acc[0][3], ap0, b23.y);
            ffma2(acc[1][0], ap1, b01.x); ffma2(acc[1][1], ap1, b01.y);
            ffma2(acc[1][2], ap1, b23.x); ffma2(acc[1][3], ap1, b23.y);
            ffma2(acc[2][0], ap2, b01.x); ffma2(acc[2][1], ap2, b01.y);
            ffma2(acc[2][2], ap2, b23.x); ffma2(acc[2][3], ap2, b23.y);
            ffma2(acc[3][0], ap3, b01.x); ffma2(acc[3][1], ap3, b01.y);
            ffma2(acc[3][2], ap3, b23.x); ffma2(acc[3][3], ap3, b23.y);
        }
        __syncthreads();
    }
    #pragma unroll
    for (int i = 0; i < 4; i++) {
        int m = row0 + (ty << 2) + i;
        if (m < M) {
            float2 p0 = unpack2(acc[i][0]), p1 = unpack2(acc[i][1]);
            float2 p2 = unpack2(acc[i][2]), p3 = unpack2(acc[i][3]);
            *(float4*)(C + (size_t)m*Nn + col0 + (tx << 2))
                = make_float4(p0.x, p0.y, p1.x, p1.y);
            *(float4*)(C + (size_t)m*Nn + col0 + 64 + (tx << 2))
                = make_float4(p2.x, p2.y, p3.x, p3.y);
        }
    }
}

__global__ __launch_bounds__(256) void square_kernel() {
    const float* S = blockIdx.z ? g_Sb : g_Sf;
    float*       D = blockIdx.z ? g_Sb2 : g_Sf2;
    gemm_nn_f32x2(S, S, D, Nn);
}

// ---------------- fused one-time conversions / zero-init (ONE launch) ----------------
__global__ void setup_convert_kernel(const float* __restrict__ Wr,
                                     const float* __restrict__ Wu,
                                     const float* __restrict__ Wc) {
    int bid = blockIdx.x;
    int tid = threadIdx.x;
    if (bid < 16384) {                                  // supports -> fp16
        size_t idx = (size_t)bid*256 + tid;
        int s = (int)(idx >> 20);
        size_t i = idx & 1048575u;
        const float* src = (s == 0) ? g_Sf : (s == 1) ? g_Sf2 : (s == 2) ? g_Sb : g_Sb2;
        g_SBh[s][i] = __float2half(src[i]);
    } else if (bid < 16648) {                           // weights -> fp16 hi/lo
        int idx = (bid - 16384)*256 + tid;
        if (idx < 3*Hh*KCP) {
            int wsel = idx / (Hh*KCP), rem = idx % (Hh*KCP);
            int o = rem / KCP, kf = rem % KCP;
            const float* W = (wsel == 0) ? Wr : (wsel == 1) ? Wu : Wc;
            float v = (kf < KC) ? W[o*KC + kf] : 0.f;
            if (wsel < 2) split_store_h(v, g_Wgh[wsel], g_Wgl[wsel], rem);
            else          split_store_h(v, g_Wch, g_Wcl, rem);
        }
    } else if (bid < 17032) {                           // zA pad rows [528,576)
        size_t i = (size_t)(bid - 16648)*256 + tid;     // < 98304
        int w = (int)(i / 49152);
        size_t off = (size_t)M_DIFF*Nn + (i % 49152);
        __half z = __float2half(0.f);
        if (w == 0) g_zAhi[0][off] = z;
        else        g_zAhi[1][off] = z;
    } else if (bid < 18440) {                           // zb pad rows [330,352)
        int idx = (bid - 17032)*256 + tid;
        if (idx < 16*22*1024) {
            int sbi = idx / (22*1024);
            int rem = idx % (22*1024);
            int row = 330 + rem/1024, n = rem % 1024;
            g_zbh[((size_t)sbi*ZBROW + row)*Nn + n] = __float2half(0.f);
        }
    } else {                                            // zero h
        int i = (bid - 18440)*256 + tid;
        if (i < Bt*Hh*Nn) g_h[i] = 0.f;
    }
}

// ---------------- HMMA diffusion (fp16, single pass) ----------------
__global__ __launch_bounds__(256) void diff_mma_kernel(int set) {
    extern __shared__ char smem[];
    const uint32_t sb = smem_u32(smem);
    const int tid = threadIdx.x, wid = tid >> 5, lane = tid & 31;
    const int n0 = blockIdx.x*128, m0 = blockIdx.y*64, s = blockIdx.z;
    const int wm = (wid >> 2) << 5;
    const int wn = (wid & 3) << 5;

    const __half* __restrict__ Ah = g_zAhi[set] + (size_t)m0*Nn;
    const __half* __restrict__ Bh = g_SBh[s]    + (size_t)n0*Nn;

    const int pr = tid >> 2, ps = (tid & 3) << 3;

    float acc[2][4][4];
    #pragma unroll
    for (int mt = 0; mt < 2; mt++)
        #pragma unroll
        for (int nb = 0; nb < 4; nb++)
            #pragma unroll
            for (int q = 0; q < 4; q++) acc[mt][nb][q] = 0.f;

    #pragma unroll
    for (int st = 0; st < 2; st++) {
        int k0 = st*32;
        uint32_t so = sb + st*D_STG;
        uint32_t rb = (pr*SROW + ps)*2;
        cp16(so + D_AHI + rb, Ah + (size_t)pr*Nn + k0 + ps);
        cp16(so + D_BHI + rb, Bh + (size_t)pr*Nn + k0 + ps);
        cp16(so + D_BHI + rb + 64*SROW*2, Bh + (size_t)(pr + 64)*Nn + k0 + ps);
        CP_COMMIT();
    }

    const int ar = lane & 15;
    const int ac = (lane >> 4) << 3;

    for (int c = 0; c < 32; c++) {
        const int st = c & 1;
        const uint32_t so = sb + st*D_STG;
        CP_WAIT1();
        __syncthreads();

        #pragma unroll
        for (int kk = 0; kk < 2; kk++) {
            const int k = kk << 4;
            uint32_t ah[2][4], bh[2][4];
            #pragma unroll
            for (int mt = 0; mt < 2; mt++) {
                uint32_t off = ((wm + mt*16 + ar)*SROW + k + ac)*2;
                ldsm4(ah[mt][0], ah[mt][1], ah[mt][2], ah[mt][3], so + D_AHI + off);
            }
            #pragma unroll
            for (int nt = 0; nt < 2; nt++) {
                uint32_t off = ((wn + nt*16 + ar)*SROW + k + ac)*2;
                ldsm4(bh[nt][0], bh[nt][1], bh[nt][2], bh[nt][3], so + D_BHI + off);
            }
            #pragma unroll
            for (int mt = 0; mt < 2; mt++)
                #pragma unroll
                for (int nb = 0; nb < 4; nb++) {
                    int nt = nb >> 1, hf = nb & 1;
                    mma_f16(acc[mt][nb], ah[mt], bh[nt][hf], bh[nt][2+hf]);
                }
        }
        __syncthreads();
        if (c + 2 < 32) {
            int k0 = (c + 2)*32;
            uint32_t rb = (pr*SROW + ps)*2;
            cp16(so + D_AHI + rb, Ah + (size_t)pr*Nn + k0 + ps);
            cp16(so + D_BHI + rb, Bh + (size_t)pr*Nn + k0 + ps);
            cp16(so + D_BHI + rb + 64*SROW*2, Bh + (size_t)(pr + 64)*Nn + k0 + ps);
        }
        CP_COMMIT();
    }

    // epilogue: fp16 store into g_zb[set] rows 66..329
    const int mr = lane >> 2, nc = (lane & 3) << 1;
    #pragma unroll
    for (int mt = 0; mt < 2; mt++) {
        #pragma unroll
        for (int nb = 0; nb < 4; nb++) {
            int n = n0 + wn + nb*8 + nc;
            int m = m0 + wm + mt*16 + mr;
            #pragma unroll
            for (int hv = 0; hv < 2; hv++) {
                int mm = m + hv*8;
                if (mm < M_DIFF) {
                    int bb = mm / C1, cc = mm - bb*C1;
                    size_t a = (((size_t)(set*Bt + bb))*ZBROW + (s+1)*C1 + cc)*Nn + n;
                    *(uint32_t*)((char*)g_zbh + a*2)
                        = packh2(acc[mt][nb][hv*2], acc[mt][nb][hv*2+1]);
                }
            }
        }
    }
}

// ---------------- gates r+u on HMMA (W hi+lo, z hi; 2 passes) ----------------
__global__ __launch_bounds__(256) void gates_mma_kernel(
    const float* __restrict__ br, const float* __restrict__ bu)
{
    extern __shared__ char smem[];
    const uint32_t sb = smem_u32(smem);
    const int tid = threadIdx.x, wid = tid >> 5, lane = tid & 31;
    const int n0 = blockIdx.x*128, gate = blockIdx.y, b = blockIdx.z;
    const int wm = (wid >> 2) << 5;
    const int wn = (wid & 3) << 5;

    const __half* __restrict__ Ah = g_Wgh[gate];
    const __half* __restrict__ Al = g_Wgl[gate];
    const __half* __restrict__ Bhp = g_zbh + (size_t)b*ZBROW*Nn;   // set 0

    const int ra = tid >> 2, sa = (tid & 3) << 3;
    float acc[2][4][4];
    #pragma unroll
    for (int mt = 0; mt < 2; mt++)
        #pragma unroll
        for (int nb = 0; nb < 4; nb++)
            #pragma unroll
            for (int q = 0; q < 4; q++) acc[mt][nb][q] = 0.f;

    #pragma unroll
    for (int st = 0; st < 2; st++) {
        int k0 = st*32;
        uint32_t so = sb + st*GSTG;
        cp16(so + GA_HI + (ra*SROW + sa)*2, Ah + (size_t)ra*KCP + k0 + sa);
        cp16(so + GA_LO + (ra*SROW + sa)*2, Al + (size_t)ra*KCP + k0 + sa);
        #pragma unroll
        for (int q = 0; q < 2; q++) {
            int idx = q*256 + tid;
            int rb = idx >> 4, sg = (idx & 15) << 3;
            cp16(so + GB_HI + (rb*GBROW + sg)*2, Bhp + (size_t)(k0 + rb)*Nn + n0 + sg);
        }
        CP_COMMIT();
    }

    const int ar = lane & 15;
    const int ac = (lane >> 4) << 3;

    for (int c = 0; c < NCH; c++) {
        const int st = c & 1;
        const uint32_t so = sb + st*GSTG;
        CP_WAIT1();
        __syncthreads();

        #pragma unroll
        for (int kk = 0; kk < 2; kk++) {
            const int k = kk << 4;
            uint32_t ah[2][4], al[2][4], bh[2][4];
            #pragma unroll
            for (int mt = 0; mt < 2; mt++) {
                uint32_t off = ((wm + mt*16 + ar)*SROW + k + ac)*2;
                ldsm4(ah[mt][0], ah[mt][1], ah[mt][2], ah[mt][3], so + GA_HI + off);
                ldsm4(al[mt][0], al[mt][1], al[mt][2], al[mt][3], so + GA_LO + off);
            }
            #pragma unroll
            for (int nt = 0; nt < 2; nt++) {
                uint32_t off = ((k + ar)*GBROW + wn + nt*16 + ac)*2;
                ldsm4t(bh[nt][0], bh[nt][1], bh[nt][2], bh[nt][3], so + GB_HI + off);
            }
            #pragma unroll
            for (int mt = 0; mt < 2; mt++)
                #pragma unroll
                for (int nb = 0; nb < 4; nb++) {
                    int nt = nb >> 1, p = (nb & 1) << 1;
                    mma_f16(acc[mt][nb], ah[mt], bh[nt][p], bh[nt][p+1]);
                    mma_f16(acc[mt][nb], al[mt], bh[nt][p], bh[nt][p+1]);
                }
        }
        __syncthreads();
        if (c + 2 < NCH) {
            int k0 = (c + 2)*32;
            cp16(so + GA_HI + (ra*SROW + sa)*2, Ah + (size_t)ra*KCP + k0 + sa);
            cp16(so + GA_LO + (ra*SROW + sa)*2, Al + (size_t)ra*KCP + k0 + sa);
            #pragma unroll
            for (int q = 0; q < 2; q++) {
                int idx = q*256 + tid;
                int rb = idx >> 4, sg = (idx & 15) << 3;
                cp16(so + GB_HI + (rb*GBROW + sg)*2, Bhp + (size_t)(k0 + rb)*Nn + n0 + sg);
            }
        }
        CP_COMMIT();
    }

    // epilogue
    const int mr = lane >> 2, nc = (lane & 3) << 1;
    const float* bias = gate ? bu : br;
    #pragma unroll
    for (int mt = 0; mt < 2; mt++) {
        #pragma unroll
        for (int nb = 0; nb < 4; nb++) {
            int n = n0 + wn + nb*8 + nc;
            #pragma unroll
            for (int hv = 0; hv < 2; hv++) {
                int o = wm + mt*16 + mr + hv*8;
                float bb = bias[o];
                float s0 = 1.f/(1.f + expf(-(acc[mt][nb][hv*2]   + bb)));
                float s1 = 1.f/(1.f + expf(-(acc[mt][nb][hv*2+1] + bb)));
                size_t hidx = ((size_t)(b*Hh + o))*Nn + n;
                if (gate == 0) {
                    float2 hvv = *(const float2*)(g_h + hidx);
                    uint32_t rp = packh2(s0*hvv.x, s1*hvv.y);
                    size_t za = ((size_t)(b*C1 + 2 + o))*Nn + n;            // zA[1]
                    *(uint32_t*)((char*)&g_zAhi[1][0] + za*2) = rp;
                    size_t zb = (((size_t)(Bt + b))*ZBROW + 2 + o)*Nn + n;  // zb set 1
                    *(uint32_t*)((char*)g_zbh + zb*2) = rp;
                } else {
                    *(float2*)(g_u + hidx) = make_float2(s0, s1);
                }
            }
        }
    }
    if (gate == 0) {  // copy rows 0,1 (x_in, mask) set0 -> set1 + zA[1]
        int row = tid >> 7, nl = tid & 127, n = n0 + nl;
        __half vh = g_zbh[((size_t)b*ZBROW + row)*Nn + n];
        g_zbh[(((size_t)(Bt + b))*ZBROW + row)*Nn + n] = vh;
        g_zAhi[1][((size_t)(b*C1 + row))*Nn + n] = vh;
    }
}

// ---------------- update on HMMA + fused pre(t+1) ----------------
__global__ __launch_bounds__(256) void update_mma_kernel(
    const float* __restrict__ bc,
    const float* __restrict__ x, const void* __restrict__ mask,
    const float* __restrict__ Wout, const float* __restrict__ bout,
    float* __restrict__ out, int t)
{
    extern __shared__ char smem[];
    const uint32_t sb = smem_u32(smem);
    const int tid = threadIdx.x, wid = tid >> 5, lane = tid & 31;
    const int n0 = blockIdx.x*128, b = blockIdx.y;
    const int wm = (wid >> 2) << 5;
    const int wn = (wid & 3) << 5;
    __shared__ float ws[Hh];
    __shared__ float xpart[2*128];
    if (tid < Hh) ws[tid] = Wout[tid];

    const __half* __restrict__ Bhp = g_zbh + ((size_t)(Bt + b))*ZBROW*Nn;  // set 1

    const int ra = tid >> 2, sa = (tid & 3) << 3;
    float acc[2][4][4];
    #pragma unroll
    for (int mt = 0; mt < 2; mt++)
        #pragma unroll
        for (int nb = 0; nb < 4; nb++)
            #pragma unroll
            for (int q = 0; q < 4; q++) acc[mt][nb][q] = 0.f;

    #pragma unroll
    for (int st = 0; st < 2; st++) {
        int k0 = st*32;
        uint32_t so = sb + st*GSTG;
        cp16(so + GA_HI + (ra*SROW + sa)*2, g_Wch + (size_t)ra*KCP + k0 + sa);
        cp16(so + GA_LO + (ra*SROW + sa)*2, g_Wcl + (size_t)ra*KCP + k0 + sa);
        #pragma unroll
        for (int q = 0; q < 2; q++) {
            int idx = q*256 + tid;
            int rb = idx >> 4, sg = (idx & 15) << 3;
            cp16(so + GB_HI + (rb*GBROW + sg)*2, Bhp + (size_t)(k0 + rb)*Nn + n0 + sg);
        }
        CP_COMMIT();
    }

    const int ar = lane & 15;
    const int ac = (lane >> 4) << 3;

    for (int c = 0; c < NCH; c++) {
        const int st = c & 1;
        const uint32_t so = sb + st*GSTG;
        CP_WAIT1();
        __syncthreads();

        #pragma unroll
        for (int kk = 0; kk < 2; kk++) {
            const int k = kk << 4;
            uint32_t ah[2][4], al[2][4], bh[2][4];
            #pragma unroll
            for (int mt = 0; mt < 2; mt++) {
                uint32_t off = ((wm + mt*16 + ar)*SROW + k + ac)*2;
                ldsm4(ah[mt][0], ah[mt][1], ah[mt][2], ah[mt][3], so + GA_HI + off);
                ldsm4(al[mt][0], al[mt][1], al[mt][2], al[mt][3], so + GA_LO + off);
            }
            #pragma unroll
            for (int nt = 0; nt < 2; nt++) {
                uint32_t off = ((k + ar)*GBROW + wn + nt*16 + ac)*2;
                ldsm4t(bh[nt][0], bh[nt][1], bh[nt][2], bh[nt][3], so + GB_HI + off);
            }
            #pragma unroll
            for (int mt = 0; mt < 2; mt++)
                #pragma unroll
                for (int nb = 0; nb < 4; nb++) {
                    int nt = nb >> 1, p = (nb & 1) << 1;
                    mma_f16(acc[mt][nb], ah[mt], bh[nt][p], bh[nt][p+1]);
                    mma_f16(acc[mt][nb], al[mt], bh[nt][p], bh[nt][p+1]);
                }
        }
        __syncthreads();
        if (c + 2 < NCH) {
            int k0 = (c + 2)*32;
            cp16(so + GA_HI + (ra*SROW + sa)*2, g_Wch + (size_t)ra*KCP + k0 + sa);
            cp16(so + GA_LO + (ra*SROW + sa)*2, g_Wcl + (size_t)ra*KCP + k0 + sa);
            #pragma unroll
            for (int q = 0; q < 2; q++) {
                int idx = q*256 + tid;
                int rb = idx >> 4, sg = (idx & 15) << 3;
                cp16(so + GB_HI + (rb*GBROW + sg)*2, Bhp + (size_t)(k0 + rb)*Nn + n0 + sg);
            }
        }
        CP_COMMIT();
    }

    // epilogue: h update; stage hn into smem (aliased over GEMM buffers)
    float* hb = (float*)smem;    // [64][132]
    const int mr = lane >> 2, nc = (lane & 3) << 1;
    #pragma unroll
    for (int mt = 0; mt < 2; mt++) {
        #pragma unroll
        for (int nb = 0; nb < 4; nb++) {
            int nl = wn + nb*8 + nc;
            int n = n0 + nl;
            #pragma unroll
            for (int hv = 0; hv < 2; hv++) {
                int o = wm + mt*16 + mr + hv*8;
                float bb = bc[o];
                size_t hidx = ((size_t)(b*Hh + o))*Nn + n;
                float2 uu = *(const float2*)(g_u + hidx);
                float2 hh = *(const float2*)(g_h + hidx);
                float c0 = tanhf(acc[mt][nb][hv*2]   + bb);
                float c1 = tanhf(acc[mt][nb][hv*2+1] + bb);
                float h0 = uu.x*hh.x + (1.f - uu.x)*c0;
                float h1 = uu.y*hh.y + (1.f - uu.y)*c1;
                *(float2*)(g_h + hidx) = make_float2(h0, h1);
                hb[o*132 + nl]     = h0;
                hb[o*132 + nl + 1] = h1;
            }
        }
    }
    __syncthreads();

    // fused pre for step t+1
    if (t + 1 < Tt) {
        int tn = t + 1;
        int group = tid >> 7, nl = tid & 127, n = n0 + nl;
        float part = 0.f;
        #pragma unroll
        for (int oo = 0; oo < 32; oo++) {
            int o = group*32 + oo;
            float hv = hb[o*132 + nl];
            part += ws[o] * hv;
            out[PRED_SZ + (((size_t)(b*Hh + o))*Nn + n)*Tt + tn] = hv;
            __half hf = __float2half(hv);
            g_zAhi[0][((size_t)(b*C1 + 2 + o))*Nn + n] = hf;
            g_zbh[((size_t)b*ZBROW + 2 + o)*Nn + n] = hf;
        }
        xpart[group*128 + nl] = part;
        __syncthreads();
        if (group == 0) {
            float xhat = xpart[nl] + xpart[128 + nl] + bout[0];
            out[((size_t)(b*Nn) + n)*Tt + tn] = xhat;
            size_t xi = ((size_t)b*Nn + n)*Tt + tn;
            float xv = x[xi];
            bool m;
            if (g_masktype == 0)
                m = ((const unsigned char*)mask)[xi] != 0;
            else
                m = ((const unsigned int*)mask)[xi] != 0u;
            float xin = m ? xv : xhat;
            float mf  = m ? 1.f : 0.f;
            __half xh = __float2half(xin), mh = __float2half(mf);
            g_zAhi[0][((size_t)(b*C1) + 0)*Nn + n] = xh;
            g_zAhi[0][((size_t)(b*C1) + 1)*Nn + n] = mh;
            g_zbh[((size_t)b*ZBROW + 0)*Nn + n] = xh;
            g_zbh[((size_t)b*ZBROW + 1)*Nn + n] = mh;
        }
    }
}

// ---------------- pre (t=0 only) ----------------
__global__ __launch_bounds__(128) void pre_kernel(
    const float* __restrict__ x, const void* __restrict__ mask,
    const float* __restrict__ Wout, const float* __restrict__ bout,
    float* __restrict__ out)
{
    int n = blockIdx.x*128 + threadIdx.x;
    int b = blockIdx.y;
    __shared__ float ws[Hh];
    if (threadIdx.x < Hh) ws[threadIdx.x] = Wout[threadIdx.x];
    __syncthreads();
    float acc = 0.f;
    #pragma unroll 4
    for (int hh = 0; hh < Hh; hh++) {
        float hv = g_h[((size_t)(b*Hh + hh))*Nn + n];
        acc += hv * ws[hh];
        __half hf = __float2half(hv);
        g_zAhi[0][((size_t)(b*C1 + 2 + hh))*Nn + n] = hf;
        g_zbh[((size_t)b*ZBROW + 2 + hh)*Nn + n] = hf;
        out[PRED_SZ + (((size_t)(b*Hh + hh))*Nn + n)*Tt + 0] = hv;
    }
    float xhat = acc + bout[0];
    out[((size_t)(b*Nn) + n)*Tt + 0] = xhat;
    size_t xi = ((size_t)b*Nn + n)*Tt + 0;
    float xv = x[xi];
    bool m;
    if (g_masktype == 0)
        m = ((const unsigned char*)mask)[xi] != 0;
    else
        m = ((const unsigned int*)mask)[xi] != 0u;
    float xin = m ? xv : xhat;
    float mf  = m ? 1.f : 0.f;
    __half xh = __float2half(xin), mh = __float2half(mf);
    g_zAhi[0][((size_t)(b*C1) + 0)*Nn + n] = xh;
    g_zAhi[0][((size_t)(b*C1) + 1)*Nn + n] = mh;
    g_zbh[((size_t)b*ZBROW + 0)*Nn + n] = xh;
    g_zbh[((size_t)b*ZBROW + 1)*Nn + n] = mh;
}

// ---------------- launch ----------------
extern "C" void kernel_launch(void* const* d_in, const int* in_sizes, int n_in,
                              void* d_out, int out_size) {
    int ix, imask, iadj, iWr, ibr, iWu, ibu, iWc, ibc, iWout, ibout;
    if (in_sizes[0] == 21120) {
        iWc = 0; iWout = 1; iWr = 2; iWu = 3; iadj = 4; ibc = 5;
        ibout = 6; ibr = 7; ibu = 8; imask = 9; ix = 10;
    } else {
        ix = 0; imask = 1; iadj = 2; iWr = 3; ibr = 4; iWu = 5;
        ibu = 6; iWc = 7; ibc = 8; iWout = 9; ibout = 10;
    }
    const float* x    = (const float*)d_in[ix];
    const void*  mask = d_in[imask];
    const float* adj  = (const float*)d_in[iadj];
    const float* Wr   = (const float*)d_in[iWr];
    const float* br   = (const float*)d_in[ibr];
    const float* Wu   = (const float*)d_in[iWu];
    const float* bu   = (const float*)d_in[ibu];
    const float* Wc   = (const float*)d_in[iWc];
    const float* bc   = (const float*)d_in[ibc];
    const float* Wout = (const float*)d_in[iWout];
    const float* bout = (const float*)d_in[ibout];
    float* out = (float*)d_out;

    cudaFuncSetAttribute(diff_mma_kernel,
                         cudaFuncAttributeMaxDynamicSharedMemorySize, DIFF_SMEM);
    cudaFuncSetAttribute(gates_mma_kernel,
                         cudaFuncAttributeMaxDynamicSharedMemorySize, GATES_SMEM);
    cudaFuncSetAttribute(update_mma_kernel,
                         cudaFuncAttributeMaxDynamicSharedMemorySize, GATES_SMEM);

    detect_mask_kernel<<<1, 32>>>((const unsigned int*)mask);            // 0
    norm_kernel<<<Nn, 256>>>(adj);                                       // 1
    square_kernel<<<dim3(Nn/DBN, Nn/DBM, 2), 256>>>();                   // 2
    setup_convert_kernel<<<20488, 256>>>(Wr, Wu, Wc);                    // 3
    pre_kernel<<<dim3(Nn/128, Bt), 128>>>(x, mask, Wout, bout, out);     // 4

    for (int t = 0; t < Tt; t++) {
        diff_mma_kernel<<<dim3(8, 9, 4), 256, DIFF_SMEM>>>(0);           // 5 on t=0
        gates_mma_kernel<<<dim3(8, 2, Bt), 256, GATES_SMEM>>>(br, bu);
        diff_mma_kernel<<<dim3(8, 9, 4), 256, DIFF_SMEM>>>(1);
        update_mma_kernel<<<dim3(8, Bt), 256, GATES_SMEM>>>(bc, x, mask, Wout, bout, out, t);
    }
}

// round 17
// speedup vs baseline: 6.8720x; 1.0492x over previous
#include <cuda_runtime.h>
#include <cuda_fp16.h>
#include <math.h>
#include <stdint.h>

#define Bt 8
#define Nn 1024
#define Hh 64
#define Tt 128
#define C1 66              // channels in xh = 2 + H
#define KC 330             // 5 * C1
#define KCP 352            // padded K for gate GEMMs (22 * 16)
#define ZBROW 352
#define M_DIFF (Bt*C1)     // 528
#define M_PAD 576          // padded diff A rows (9 tiles of 64)
#define PRED_SZ (Bt*Nn*Tt) // 1048576

// f32x2 square-GEMM tile
#define DBM 64
#define DBN 128
#define DBK 16
#define APAD 68
#define BPAD 132

// HMMA diffusion layout: tile 64(M) x 128(N), fp16, 4-stage pipeline
#define SROW 40                        // 32 data + 8 pad halves (80B rows)
#define D_AHI 0
#define D_BHI (64*SROW*2)              // 5120
#define D_STG (D_BHI + 128*SROW*2)     // 15360
#define DIFF_SMEM (4*D_STG)            // 61440

// gates/update HMMA layout: tile 64 x 128, K chunks of 32, 4-stage pipeline
#define GBROW 136                      // 128 data + 8 pad
#define GA_HI 0
#define GB_HI (64*SROW*2)              // 5120
#define GSTG  (GB_HI + 32*GBROW*2)     // 13824
#define GATES_SMEM (4*GSTG)            // 55296
#define NCH 11                         // 352/32 K chunks

// ---------------- helpers ----------------
__device__ __forceinline__ uint32_t smem_u32(const void* p) {
    uint32_t a;
    asm("{ .reg .u64 t; cvta.to.shared.u64 t, %1; cvt.u32.u64 %0, t; }" : "=r"(a) : "l"(p));
    return a;
}
__device__ __forceinline__ void ldsm4(uint32_t& r0, uint32_t& r1, uint32_t& r2, uint32_t& r3,
                                      uint32_t addr) {
    asm volatile("ldmatrix.sync.aligned.m8n8.x4.shared.b16 {%0,%1,%2,%3}, [%4];"
                 : "=r"(r0), "=r"(r1), "=r"(r2), "=r"(r3) : "r"(addr));
}
__device__ __forceinline__ void ldsm4t(uint32_t& r0, uint32_t& r1, uint32_t& r2, uint32_t& r3,
                                       uint32_t addr) {
    asm volatile("ldmatrix.sync.aligned.m8n8.x4.trans.shared.b16 {%0,%1,%2,%3}, [%4];"
                 : "=r"(r0), "=r"(r1), "=r"(r2), "=r"(r3) : "r"(addr));
}
__device__ __forceinline__ void mma_f16(float* c, const uint32_t* a, uint32_t b0, uint32_t b1) {
    asm volatile(
        "mma.sync.aligned.m16n8k16.row.col.f32.f16.f16.f32 "
        "{%0,%1,%2,%3}, {%4,%5,%6,%7}, {%8,%9}, {%0,%1,%2,%3};"
        : "+f"(c[0]), "+f"(c[1]), "+f"(c[2]), "+f"(c[3])
        : "r"(a[0]), "r"(a[1]), "r"(a[2]), "r"(a[3]), "r"(b0), "r"(b1));
}
__device__ __forceinline__ void cp16(uint32_t saddr, const void* gaddr) {
    asm volatile("cp.async.cg.shared.global [%0], [%1], 16;" :: "r"(saddr), "l"(gaddr));
}
#define CP_COMMIT() asm volatile("cp.async.commit_group;" ::: "memory")
#define CP_WAIT2()  asm volatile("cp.async.wait_group 2;" ::: "memory")

// f32x2 (for the one-time S^2 GEMM)
__device__ __forceinline__ unsigned long long pack2(float v) {
    unsigned long long r;
    asm("mov.b64 %0, {%1, %1};" : "=l"(r) : "f"(v));
    return r;
}
__device__ __forceinline__ void ffma2(unsigned long long& d,
                                      unsigned long long a, unsigned long long b) {
    asm("fma.rn.f32x2 %0, %1, %2, %0;" : "+l"(d) : "l"(a), "l"(b));
}
__device__ __forceinline__ float2 unpack2(unsigned long long v) {
    float2 f;
    asm("mov.b64 {%0, %1}, %2;" : "=f"(f.x), "=f"(f.y) : "l"(v));
    return f;
}

// ---------------- device globals ----------------
__device__ float g_Sf [Nn*Nn];
__device__ float g_Sb [Nn*Nn];
__device__ float g_Sf2[Nn*Nn];
__device__ float g_Sb2[Nn*Nn];
__device__ float g_h  [Bt*Hh*Nn];
__device__ float g_u  [Bt*Hh*Nn];
__device__ int   g_masktype;
__device__ __half g_zAhi[2][M_PAD*Nn];     // diff A operand (fp16)
__device__ __half g_SBh[4][Nn*Nn];         // supports, fp16
__device__ __half g_zbh[2*Bt*ZBROW*Nn];    // gates B operand [set][b][352][1024], fp16
__device__ __half g_Wgh[2][Hh*KCP];        // Wr, Wu (fp16)
__device__ __half g_Wch[Hh*KCP];           // Wc (fp16)

__device__ __forceinline__ uint32_t packh2(float v0, float v1) {
    __half2 p = __floats2half2_rn(v0, v1);
    return *(uint32_t*)&p;
}

// ---------------- mask dtype sniffer ----------------
__global__ void detect_mask_kernel(const unsigned int* __restrict__ m) {
    if (threadIdx.x != 0 || blockIdx.x != 0) return;
    int byte_like = 0;
    for (int i = 0; i < 1024; i++) {
        unsigned int w = m[i];
        if (w == 0u || w == 1u || w == 0x3F800000u) continue;
        unsigned int b0 = w & 255u, b1 = (w >> 8) & 255u,
                     b2 = (w >> 16) & 255u, b3 = w >> 24;
        if (b0 <= 1u && b1 <= 1u && b2 <= 1u && b3 <= 1u) { byte_like = 1; break; }
    }
    g_masktype = byte_like ? 0 : 1;
}

// ---------------- support normalization ----------------
__global__ void norm_kernel(const float* __restrict__ adj) {
    int w = blockIdx.x;
    int tid = threadIdx.x;
    __shared__ float sred[256];
    float rs = 0.f, cs = 0.f;
    for (int v = tid; v < Nn; v += 256) {
        rs += adj[w*Nn + v];
        cs += adj[v*Nn + w];
    }
    sred[tid] = rs; __syncthreads();
    for (int s = 128; s > 0; s >>= 1) { if (tid < s) sred[tid] += sred[tid+s]; __syncthreads(); }
    float rsum = sred[0] + 1e-8f; __syncthreads();
    sred[tid] = cs; __syncthreads();
    for (int s = 128; s > 0; s >>= 1) { if (tid < s) sred[tid] += sred[tid+s]; __syncthreads(); }
    float csum = sred[0] + 1e-8f; __syncthreads();
    for (int v = tid; v < Nn; v += 256) {
        g_Sf[w*Nn + v] = adj[w*Nn + v] / rsum;
        g_Sb[w*Nn + v] = adj[v*Nn + w] / csum;
    }
}

// ---------------- f32x2 GEMM (once, for S^2) ----------------
__device__ __forceinline__ void gemm_nn_f32x2(const float* __restrict__ A,
                                              const float* __restrict__ B,
                                              float* __restrict__ C, int M)
{
    __shared__ float As[DBK][APAD];
    __shared__ float Bs[DBK][BPAD];
    const int tid  = threadIdx.x;
    const int row0 = blockIdx.y*DBM, col0 = blockIdx.x*DBN;
    const int am = tid >> 2, ak = (tid & 3) << 2;
    const int bk = tid >> 5, bn = (tid & 31) << 2;
    const int tx = tid & 15, ty = tid >> 4;

    unsigned long long acc[4][4];
    #pragma unroll
    for (int i = 0; i < 4; i++)
        #pragma unroll
        for (int p = 0; p < 4; p++) acc[i][p] = 0ULL;

    const bool arow_ok = (row0 + am) < M;
    const float* Aptr  = A + (size_t)(row0 + am)*Nn + ak;
    const float* Bptr0 = B + (size_t)bk*Nn + col0 + bn;
    const float* Bptr1 = B + (size_t)(bk + 8)*Nn + col0 + bn;

    float4 areg  = arow_ok ? *(const float4*)Aptr : make_float4(0.f,0.f,0.f,0.f);
    float4 breg0 = *(const float4*)Bptr0;
    float4 breg1 = *(const float4*)Bptr1;

    for (int k0 = 0; k0 < Nn; k0 += DBK) {
        As[ak+0][am] = areg.x; As[ak+1][am] = areg.y;
        As[ak+2][am] = areg.z; As[ak+3][am] = areg.w;
        *(float4*)&Bs[bk][bn]   = breg0;
        *(float4*)&Bs[bk+8][bn] = breg1;
        __syncthreads();
        if (k0 + DBK < Nn) {
            areg  = arow_ok ? *(const float4*)(Aptr + k0 + DBK) : make_float4(0.f,0.f,0.f,0.f);
            breg0 = *(const float4*)(Bptr0 + (size_t)(k0 + DBK)*Nn);
            breg1 = *(const float4*)(Bptr1 + (size_t)(k0 + DBK)*Nn);
        }
        #pragma unroll
        for (int kk = 0; kk < DBK; kk++) {
            float4 a4 = *(const float4*)&As[kk][ty << 2];
            ulonglong2 b01 = *(const ulonglong2*)&Bs[kk][tx << 2];
            ulonglong2 b23 = *(const ulonglong2*)&Bs[kk][64 + (tx << 2)];
            unsigned long long ap0 = pack2(a4.x), ap1 = pack2(a4.y),
                               ap2 = pack2(a4.z), ap3 = pack2(a4.w);
            ffma2(acc[0][0], ap0, b01.x); ffma2(acc[0][1], ap0, b01.y);
            ffma2(acc[0][2], ap0, b23.x); ffma2(acc[0][3], ap0, b23.y);
            ffma2(acc[1][0], ap1, b01.x); ffma2(acc[1][1], ap1, b01.y);
            ffma2(acc[1][2], ap1, b23.x); ffma2(acc[1][3], ap1, b23.y);
            ffma2(acc[2][0], ap2, b01.x); ffma2(acc[2][1], ap2, b01.y);
            ffma2(acc[2][2], ap2, b23.x); ffma2(acc[2][3], ap2, b23.y);
            ffma2(acc[3][0], ap3, b01.x); ffma2(acc[3][1], ap3, b01.y);
            ffma2(acc[3][2], ap3, b23.x); ffma2(acc[3][3], ap3, b23.y);
        }
        __syncthreads();
    }
    #pragma unroll
    for (int i = 0; i < 4; i++) {
        int m = row0 + (ty << 2) + i;
        if (m < M) {
            float2 p0 = unpack2(acc[i][0]), p1 = unpack2(acc[i][1]);
            float2 p2 = unpack2(acc[i][2]), p3 = unpack2(acc[i][3]);
            *(float4*)(C + (size_t)m*Nn + col0 + (tx << 2))
                = make_float4(p0.x, p0.y, p1.x, p1.y);
            *(float4*)(C + (size_t)m*Nn + col0 + 64 + (tx << 2))
                = make_float4(p2.x, p2.y, p3.x, p3.y);
        }
    }
}

__global__ __launch_bounds__(256) void square_kernel() {
    const float* S = blockIdx.z ? g_Sb : g_Sf;
    float*       D = blockIdx.z ? g_Sb2 : g_Sf2;
    gemm_nn_f32x2(S, S, D, Nn);
}

// ---------------- fused one-time conversions / zero-init ----------------
__global__ void setup_convert_kernel(const float* __restrict__ Wr,
                                     const float* __restrict__ Wu,
                                     const float* __restrict__ Wc) {
    int bid = blockIdx.x;
    int tid = threadIdx.x;
    if (bid < 16384) {                                  // supports -> fp16
        size_t idx = (size_t)bid*256 + tid;
        int s = (int)(idx >> 20);
        size_t i = idx & 1048575u;
        const float* src = (s == 0) ? g_Sf : (s == 1) ? g_Sf2 : (s == 2) ? g_Sb : g_Sb2;
        g_SBh[s][i] = __float2half(src[i]);
    } else if (bid < 16648) {                           // weights -> fp16
        int idx = (bid - 16384)*256 + tid;
        if (idx < 3*Hh*KCP) {
            int wsel = idx / (Hh*KCP), rem = idx % (Hh*KCP);
            int o = rem / KCP, kf = rem % KCP;
            const float* W = (wsel == 0) ? Wr : (wsel == 1) ? Wu : Wc;
            float v = (kf < KC) ? W[o*KC + kf] : 0.f;
            if (wsel < 2) g_Wgh[wsel][rem] = __float2half(v);
            else          g_Wch[rem] = __float2half(v);
        }
    } else if (bid < 17032) {                           // zA pad rows [528,576)
        size_t i = (size_t)(bid - 16648)*256 + tid;     // < 98304
        int w = (int)(i / 49152);
        size_t off = (size_t)M_DIFF*Nn + (i % 49152);
        __half z = __float2half(0.f);
        if (w == 0) g_zAhi[0][off] = z;
        else        g_zAhi[1][off] = z;
    } else if (bid < 18440) {                           // zb pad rows [330,352)
        int idx = (bid - 17032)*256 + tid;
        if (idx < 16*22*1024) {
            int sbi = idx / (22*1024);
            int rem = idx % (22*1024);
            int row = 330 + rem/1024, n = rem % 1024;
            g_zbh[((size_t)sbi*ZBROW + row)*Nn + n] = __float2half(0.f);
        }
    } else {                                            // zero h
        int i = (bid - 18440)*256 + tid;
        if (i < Bt*Hh*Nn) g_h[i] = 0.f;
    }
}

// ---------------- HMMA diffusion (fp16, single pass, 4-stage pipe) ----------------
__global__ __launch_bounds__(256) void diff_mma_kernel(int set) {
    extern __shared__ char smem[];
    const uint32_t sb = smem_u32(smem);
    const int tid = threadIdx.x, wid = tid >> 5, lane = tid & 31;
    const int n0 = blockIdx.x*128, m0 = blockIdx.y*64, s = blockIdx.z;
    const int wm = (wid >> 2) << 5;
    const int wn = (wid & 3) << 5;

    const __half* __restrict__ Ah = g_zAhi[set] + (size_t)m0*Nn;
    const __half* __restrict__ Bh = g_SBh[s]    + (size_t)n0*Nn;

    const int pr = tid >> 2, ps = (tid & 3) << 3;

    float acc[2][4][4];
    #pragma unroll
    for (int mt = 0; mt < 2; mt++)
        #pragma unroll
        for (int nb = 0; nb < 4; nb++)
            #pragma unroll
            for (int q = 0; q < 4; q++) acc[mt][nb][q] = 0.f;

    #pragma unroll
    for (int st = 0; st < 3; st++) {                    // prologue: chunks 0..2
        int k0 = st*32;
        uint32_t so = sb + st*D_STG;
        uint32_t rb = (pr*SROW + ps)*2;
        cp16(so + D_AHI + rb, Ah + (size_t)pr*Nn + k0 + ps);
        cp16(so + D_BHI + rb, Bh + (size_t)pr*Nn + k0 + ps);
        cp16(so + D_BHI + rb + 64*SROW*2, Bh + (size_t)(pr + 64)*Nn + k0 + ps);
        CP_COMMIT();
    }

    const int ar = lane & 15;
    const int ac = (lane >> 4) << 3;

    for (int c = 0; c < 32; c++) {
        const uint32_t so = sb + (c & 3)*D_STG;
        CP_WAIT2();
        __syncthreads();

        #pragma unroll
        for (int kk = 0; kk < 2; kk++) {
            const int k = kk << 4;
            uint32_t ah[2][4], bh[2][4];
            #pragma unroll
            for (int mt = 0; mt < 2; mt++) {
                uint32_t off = ((wm + mt*16 + ar)*SROW + k + ac)*2;
                ldsm4(ah[mt][0], ah[mt][1], ah[mt][2], ah[mt][3], so + D_AHI + off);
            }
            #pragma unroll
            for (int nt = 0; nt < 2; nt++) {
                uint32_t off = ((wn + nt*16 + ar)*SROW + k + ac)*2;
                ldsm4(bh[nt][0], bh[nt][1], bh[nt][2], bh[nt][3], so + D_BHI + off);
            }
            #pragma unroll
            for (int mt = 0; mt < 2; mt++)
                #pragma unroll
                for (int nb = 0; nb < 4; nb++) {
                    int nt = nb >> 1, hf = nb & 1;
                    mma_f16(acc[mt][nb], ah[mt], bh[nt][hf], bh[nt][2+hf]);
                }
        }
        __syncthreads();
        if (c + 3 < 32) {
            int k0 = (c + 3)*32;
            uint32_t sw = sb + ((c + 3) & 3)*D_STG;
            uint32_t rb = (pr*SROW + ps)*2;
            cp16(sw + D_AHI + rb, Ah + (size_t)pr*Nn + k0 + ps);
            cp16(sw + D_BHI + rb, Bh + (size_t)pr*Nn + k0 + ps);
            cp16(sw + D_BHI + rb + 64*SROW*2, Bh + (size_t)(pr + 64)*Nn + k0 + ps);
        }
        CP_COMMIT();
    }

    // epilogue: fp16 store into g_zb[set] rows 66..329
    const int mr = lane >> 2, nc = (lane & 3) << 1;
    #pragma unroll
    for (int mt = 0; mt < 2; mt++) {
        #pragma unroll
        for (int nb = 0; nb < 4; nb++) {
            int n = n0 + wn + nb*8 + nc;
            int m = m0 + wm + mt*16 + mr;
            #pragma unroll
            for (int hv = 0; hv < 2; hv++) {
                int mm = m + hv*8;
                if (mm < M_DIFF) {
                    int bb = mm / C1, cc = mm - bb*C1;
                    size_t a = (((size_t)(set*Bt + bb))*ZBROW + (s+1)*C1 + cc)*Nn + n;
                    *(uint32_t*)((char*)g_zbh + a*2)
                        = packh2(acc[mt][nb][hv*2], acc[mt][nb][hv*2+1]);
                }
            }
        }
    }
}

// ---------------- gates r+u on HMMA (single pass, 4-stage pipe) ----------------
__global__ __launch_bounds__(256) void gates_mma_kernel(
    const float* __restrict__ br, const float* __restrict__ bu)
{
    extern __shared__ char smem[];
    const uint32_t sb = smem_u32(smem);
    const int tid = threadIdx.x, wid = tid >> 5, lane = tid & 31;
    const int n0 = blockIdx.x*128, gate = blockIdx.y, b = blockIdx.z;
    const int wm = (wid >> 2) << 5;
    const int wn = (wid & 3) << 5;

    const __half* __restrict__ Ah = g_Wgh[gate];
    const __half* __restrict__ Bhp = g_zbh + (size_t)b*ZBROW*Nn;   // set 0

    const int ra = tid >> 2, sa = (tid & 3) << 3;
    float acc[2][4][4];
    #pragma unroll
    for (int mt = 0; mt < 2; mt++)
        #pragma unroll
        for (int nb = 0; nb < 4; nb++)
            #pragma unroll
            for (int q = 0; q < 4; q++) acc[mt][nb][q] = 0.f;

    #pragma unroll
    for (int st = 0; st < 3; st++) {
        int k0 = st*32;
        uint32_t so = sb + st*GSTG;
        cp16(so + GA_HI + (ra*SROW + sa)*2, Ah + (size_t)ra*KCP + k0 + sa);
        #pragma unroll
        for (int q = 0; q < 2; q++) {
            int idx = q*256 + tid;
            int rb = idx >> 4, sg = (idx & 15) << 3;
            cp16(so + GB_HI + (rb*GBROW + sg)*2, Bhp + (size_t)(k0 + rb)*Nn + n0 + sg);
        }
        CP_COMMIT();
    }

    const int ar = lane & 15;
    const int ac = (lane >> 4) << 3;

    for (int c = 0; c < NCH; c++) {
        const uint32_t so = sb + (c & 3)*GSTG;
        CP_WAIT2();
        __syncthreads();

        #pragma unroll
        for (int kk = 0; kk < 2; kk++) {
            const int k = kk << 4;
            uint32_t ah[2][4], bh[2][4];
            #pragma unroll
            for (int mt = 0; mt < 2; mt++) {
                uint32_t off = ((wm + mt*16 + ar)*SROW + k + ac)*2;
                ldsm4(ah[mt][0], ah[mt][1], ah[mt][2], ah[mt][3], so + GA_HI + off);
            }
            #pragma unroll
            for (int nt = 0; nt < 2; nt++) {
                uint32_t off = ((k + ar)*GBROW + wn + nt*16 + ac)*2;
                ldsm4t(bh[nt][0], bh[nt][1], bh[nt][2], bh[nt][3], so + GB_HI + off);
            }
            #pragma unroll
            for (int mt = 0; mt < 2; mt++)
                #pragma unroll
                for (int nb = 0; nb < 4; nb++) {
                    int nt = nb >> 1, p = (nb & 1) << 1;
                    mma_f16(acc[mt][nb], ah[mt], bh[nt][p], bh[nt][p+1]);
                }
        }
        __syncthreads();
        if (c + 3 < NCH) {
            int k0 = (c + 3)*32;
            uint32_t sw = sb + ((c + 3) & 3)*GSTG;
            cp16(sw + GA_HI + (ra*SROW + sa)*2, Ah + (size_t)ra*KCP + k0 + sa);
            #pragma unroll
            for (int q = 0; q < 2; q++) {
                int idx = q*256 + tid;
                int rb = idx >> 4, sg = (idx & 15) << 3;
                cp16(sw + GB_HI + (rb*GBROW + sg)*2, Bhp + (size_t)(k0 + rb)*Nn + n0 + sg);
            }
        }
        CP_COMMIT();
    }

    // epilogue
    const int mr = lane >> 2, nc = (lane & 3) << 1;
    const float* bias = gate ? bu : br;
    #pragma unroll
    for (int mt = 0; mt < 2; mt++) {
        #pragma unroll
        for (int nb = 0; nb < 4; nb++) {
            int n = n0 + wn + nb*8 + nc;
            #pragma unroll
            for (int hv = 0; hv < 2; hv++) {
                int o = wm + mt*16 + mr + hv*8;
                float bb = bias[o];
                float s0 = 1.f/(1.f + expf(-(acc[mt][nb][hv*2]   + bb)));
                float s1 = 1.f/(1.f + expf(-(acc[mt][nb][hv*2+1] + bb)));
                size_t hidx = ((size_t)(b*Hh + o))*Nn + n;
                if (gate == 0) {
                    float2 hvv = *(const float2*)(g_h + hidx);
                    uint32_t rp = packh2(s0*hvv.x, s1*hvv.y);
                    size_t za = ((size_t)(b*C1 + 2 + o))*Nn + n;            // zA[1]
                    *(uint32_t*)((char*)&g_zAhi[1][0] + za*2) = rp;
                    size_t zb = (((size_t)(Bt + b))*ZBROW + 2 + o)*Nn + n;  // zb set 1
                    *(uint32_t*)((char*)g_zbh + zb*2) = rp;
                } else {
                    *(float2*)(g_u + hidx) = make_float2(s0, s1);
                }
            }
        }
    }
    if (gate == 0) {  // copy rows 0,1 (x_in, mask) set0 -> set1 + zA[1]
        int row = tid >> 7, nl = tid & 127, n = n0 + nl;
        __half vh = g_zbh[((size_t)b*ZBROW + row)*Nn + n];
        g_zbh[(((size_t)(Bt + b))*ZBROW + row)*Nn + n] = vh;
        g_zAhi[1][((size_t)(b*C1 + row))*Nn + n] = vh;
    }
}

// ---------------- update on HMMA + fused pre(t+1), single pass, 4-stage ----------------
__global__ __launch_bounds__(256) void update_mma_kernel(
    const float* __restrict__ bc,
    const float* __restrict__ x, const void* __restrict__ mask,
    const float* __restrict__ Wout, const float* __restrict__ bout,
    float* __restrict__ out, int t)
{
    extern __shared__ char smem[];
    const uint32_t sb = smem_u32(smem);
    const int tid = threadIdx.x, wid = tid >> 5, lane = tid & 31;
    const int n0 = blockIdx.x*128, b = blockIdx.y;
    const int wm = (wid >> 2) << 5;
    const int wn = (wid & 3) << 5;
    __shared__ float ws[Hh];
    __shared__ float xpart[2*128];
    if (tid < Hh) ws[tid] = Wout[tid];

    const __half* __restrict__ Bhp = g_zbh + ((size_t)(Bt + b))*ZBROW*Nn;  // set 1

    const int ra = tid >> 2, sa = (tid & 3) << 3;
    float acc[2][4][4];
    #pragma unroll
    for (int mt = 0; mt < 2; mt++)
        #pragma unroll
        for (int nb = 0; nb < 4; nb++)
            #pragma unroll
            for (int q = 0; q < 4; q++) acc[mt][nb][q] = 0.f;

    #pragma unroll
    for (int st = 0; st < 3; st++) {
        int k0 = st*32;
        uint32_t so = sb + st*GSTG;
        cp16(so + GA_HI + (ra*SROW + sa)*2, g_Wch + (size_t)ra*KCP + k0 + sa);
        #pragma unroll
        for (int q = 0; q < 2; q++) {
            int idx = q*256 + tid;
            int rb = idx >> 4, sg = (idx & 15) << 3;
            cp16(so + GB_HI + (rb*GBROW + sg)*2, Bhp + (size_t)(k0 + rb)*Nn + n0 + sg);
        }
        CP_COMMIT();
    }

    const int ar = lane & 15;
    const int ac = (lane >> 4) << 3;

    for (int c = 0; c < NCH; c++) {
        const uint32_t so = sb + (c & 3)*GSTG;
        CP_WAIT2();
        __syncthreads();

        #pragma unroll
        for (int kk = 0; kk < 2; kk++) {
            const int k = kk << 4;
            uint32_t ah[2][4], bh[2][4];
            #pragma unroll
            for (int mt = 0; mt < 2; mt++) {
                uint32_t off = ((wm + mt*16 + ar)*SROW + k + ac)*2;
                ldsm4(ah[mt][0], ah[mt][1], ah[mt][2], ah[mt][3], so + GA_HI + off);
            }
            #pragma unroll
            for (int nt = 0; nt < 2; nt++) {
                uint32_t off = ((k + ar)*GBROW + wn + nt*16 + ac)*2;
                ldsm4t(bh[nt][0], bh[nt][1], bh[nt][2], bh[nt][3], so + GB_HI + off);
            }
            #pragma unroll
            for (int mt = 0; mt < 2; mt++)
                #pragma unroll
                for (int nb = 0; nb < 4; nb++) {
                    int nt = nb >> 1, p = (nb & 1) << 1;
                    mma_f16(acc[mt][nb], ah[mt], bh[nt][p], bh[nt][p+1]);
                }
        }
        __syncthreads();
        if (c + 3 < NCH) {
            int k0 = (c + 3)*32;
            uint32_t sw = sb + ((c + 3) & 3)*GSTG;
            cp16(sw + GA_HI + (ra*SROW + sa)*2, g_Wch + (size_t)ra*KCP + k0 + sa);
            #pragma unroll
            for (int q = 0; q < 2; q++) {
                int idx = q*256 + tid;
                int rb = idx >> 4, sg = (idx & 15) << 3;
                cp16(sw + GB_HI + (rb*GBROW + sg)*2, Bhp + (size_t)(k0 + rb)*Nn + n0 + sg);
            }
        }
        CP_COMMIT();
    }

    // epilogue: h update; stage hn into smem (aliased over GEMM buffers)
    float* hb = (float*)smem;    // [64][132]
    const int mr = lane >> 2, nc = (lane & 3) << 1;
    #pragma unroll
    for (int mt = 0; mt < 2; mt++) {
        #pragma unroll
        for (int nb = 0; nb < 4; nb++) {
            int nl = wn + nb*8 + nc;
            int n = n0 + nl;
            #pragma unroll
            for (int hv = 0; hv < 2; hv++) {
                int o = wm + mt*16 + mr + hv*8;
                float bb = bc[o];
                size_t hidx = ((size_t)(b*Hh + o))*Nn + n;
                float2 uu = *(const float2*)(g_u + hidx);
                float2 hh = *(const float2*)(g_h + hidx);
                float c0 = tanhf(acc[mt][nb][hv*2]   + bb);
                float c1 = tanhf(acc[mt][nb][hv*2+1] + bb);
                float h0 = uu.x*hh.x + (1.f - uu.x)*c0;
                float h1 = uu.y*hh.y + (1.f - uu.y)*c1;
                *(float2*)(g_h + hidx) = make_float2(h0, h1);
                hb[o*132 + nl]     = h0;
                hb[o*132 + nl + 1] = h1;
            }
        }
    }
    __syncthreads();

    // fused pre for step t+1
    if (t + 1 < Tt) {
        int tn = t + 1;
        int group = tid >> 7, nl = tid & 127, n = n0 + nl;
        float part = 0.f;
        #pragma unroll
        for (int oo = 0; oo < 32; oo++) {
            int o = group*32 + oo;
            float hv = hb[o*132 + nl];
            part += ws[o] * hv;
            out[PRED_SZ + (((size_t)(b*Hh + o))*Nn + n)*Tt + tn] = hv;
            __half hf = __float2half(hv);
            g_zAhi[0][((size_t)(b*C1 + 2 + o))*Nn + n] = hf;
            g_zbh[((size_t)b*ZBROW + 2 + o)*Nn + n] = hf;
        }
        xpart[group*128 + nl] = part;
        __syncthreads();
        if (group == 0) {
            float xhat = xpart[nl] + xpart[128 + nl] + bout[0];
            out[((size_t)(b*Nn) + n)*Tt + tn] = xhat;
            size_t xi = ((size_t)b*Nn + n)*Tt + tn;
            float xv = x[xi];
            bool m;
            if (g_masktype == 0)
                m = ((const unsigned char*)mask)[xi] != 0;
            else
                m = ((const unsigned int*)mask)[xi] != 0u;
            float xin = m ? xv : xhat;
            float mf  = m ? 1.f : 0.f;
            __half xh = __float2half(xin), mh = __float2half(mf);
            g_zAhi[0][((size_t)(b*C1) + 0)*Nn + n] = xh;
            g_zAhi[0][((size_t)(b*C1) + 1)*Nn + n] = mh;
            g_zbh[((size_t)b*ZBROW + 0)*Nn + n] = xh;
            g_zbh[((size_t)b*ZBROW + 1)*Nn + n] = mh;
        }
    }
}

// ---------------- pre (t=0 only) ----------------
__global__ __launch_bounds__(128) void pre_kernel(
    const float* __restrict__ x, const void* __restrict__ mask,
    const float* __restrict__ Wout, const float* __restrict__ bout,
    float* __restrict__ out)
{
    int n = blockIdx.x*128 + threadIdx.x;
    int b = blockIdx.y;
    __shared__ float ws[Hh];
    if (threadIdx.x < Hh) ws[threadIdx.x] = Wout[threadIdx.x];
    __syncthreads();
    float acc = 0.f;
    #pragma unroll 4
    for (int hh = 0; hh < Hh; hh++) {
        float hv = g_h[((size_t)(b*Hh + hh))*Nn + n];
        acc += hv * ws[hh];
        __half hf = __float2half(hv);
        g_zAhi[0][((size_t)(b*C1 + 2 + hh))*Nn + n] = hf;
        g_zbh[((size_t)b*ZBROW + 2 + hh)*Nn + n] = hf;
        out[PRED_SZ + (((size_t)(b*Hh + hh))*Nn + n)*Tt + 0] = hv;
    }
    float xhat = acc + bout[0];
    out[((size_t)(b*Nn) + n)*Tt + 0] = xhat;
    size_t xi = ((size_t)b*Nn + n)*Tt + 0;
    float xv = x[xi];
    bool m;
    if (g_masktype == 0)
        m = ((const unsigned char*)mask)[xi] != 0;
    else
        m = ((const unsigned int*)mask)[xi] != 0u;
    float xin = m ? xv : xhat;
    float mf  = m ? 1.f : 0.f;
    __half xh = __float2half(xin), mh = __float2half(mf);
    g_zAhi[0][((size_t)(b*C1) + 0)*Nn + n] = xh;
    g_zAhi[0][((size_t)(b*C1) + 1)*Nn + n] = mh;
    g_zbh[((size_t)b*ZBROW + 0)*Nn + n] = xh;
    g_zbh[((size_t)b*ZBROW + 1)*Nn + n] = mh;
}

// ---------------- launch ----------------
extern "C" void kernel_launch(void* const* d_in, const int* in_sizes, int n_in,
                              void* d_out, int out_size) {
    int ix, imask, iadj, iWr, ibr, iWu, ibu, iWc, ibc, iWout, ibout;
    if (in_sizes[0] == 21120) {
        iWc = 0; iWout = 1; iWr = 2; iWu = 3; iadj = 4; ibc = 5;
        ibout = 6; ibr = 7; ibu = 8; imask = 9; ix = 10;
    } else {
        ix = 0; imask = 1; iadj = 2; iWr = 3; ibr = 4; iWu = 5;
        ibu = 6; iWc = 7; ibc = 8; iWout = 9; ibout = 10;
    }
    const float* x    = (const float*)d_in[ix];
    const void*  mask = d_in[imask];
    const float* adj  = (const float*)d_in[iadj];
    const float* Wr   = (const float*)d_in[iWr];
    const float* br   = (const float*)d_in[ibr];
    const float* Wu   = (const float*)d_in[iWu];
    const float* bu   = (const float*)d_in[ibu];
    const float* Wc   = (const float*)d_in[iWc];
    const float* bc   = (const float*)d_in[ibc];
    const float* Wout = (const float*)d_in[iWout];
    const float* bout = (const float*)d_in[ibout];
    float* out = (float*)d_out;

    cudaFuncSetAttribute(diff_mma_kernel,
                         cudaFuncAttributeMaxDynamicSharedMemorySize, DIFF_SMEM);
    cudaFuncSetAttribute(gates_mma_kernel,
                         cudaFuncAttributeMaxDynamicSharedMemorySize, GATES_SMEM);
    cudaFuncSetAttribute(update_mma_kernel,
                         cudaFuncAttributeMaxDynamicSharedMemorySize, GATES_SMEM);

    detect_mask_kernel<<<1, 32>>>((const unsigned int*)mask);            // 0
    norm_kernel<<<Nn, 256>>>(adj);                                       // 1
    square_kernel<<<dim3(Nn/DBN, Nn/DBM, 2), 256>>>();                   // 2
    setup_convert_kernel<<<20488, 256>>>(Wr, Wu, Wc);                    // 3
    pre_kernel<<<dim3(Nn/128, Bt), 128>>>(x, mask, Wout, bout, out);     // 4

    for (int t = 0; t < Tt; t++) {
        diff_mma_kernel<<<dim3(8, 9, 4), 256, DIFF_SMEM>>>(0);           // 5 on t=0
        gates_mma_kernel<<<dim3(8, 2, Bt), 256, GATES_SMEM>>>(br, bu);
        diff_mma_kernel<<<dim3(8, 9, 4), 256, DIFF_SMEM>>>(1);
        update_mma_kernel<<<dim3(8, Bt), 256, GATES_SMEM>>>(bc, x, mask, Wout, bout, out, t);
    }
}